// round 6
// baseline (speedup 1.0000x reference)
#include <cuda_runtime.h>
#include <cuda_fp16.h>
#include <math.h>

#define NN   8192
#define EE   524288
#define FIN  256
#define FTOT 256      // H * F_OUT
#define FOUT 128
#define CAP  256      // per-node bucket capacity (mean deg = 65, Poisson)
#define LN_EPS   1e-5f
#define NEG_SLOPE 0.2f

// ---------------- scratch (__device__ globals; no allocation allowed) ----------------
__device__ __align__(16) __half g_hh[NN * FTOT];   // x @ W_gat, fp16 (agg-only consumer)
__device__ __align__(16) float g_as[NN * 2];       // per-node src attention logits
__device__ __align__(16) float g_ad[NN * 2];       // per-node dst attention logits
__device__ int   g_deg[NN];
__device__ int   g_srt[NN * CAP];    // bucketed src ids per dst
__device__ __align__(16) float g_gat[NN * 256];
__device__ __align__(16) float g_l1[NN * 128];
__device__ __align__(16) float g_l2[NN * 64];
__device__ __align__(16) float g_z[NN * 3];

// ---------------- packed fp32x2 FMA (Blackwell; ptxas never auto-fuses) ----------------
__device__ __forceinline__ void ffma2(float2& c, float a, const float2& b) {
    float2 av = make_float2(a, a);
    unsigned long long ua = *reinterpret_cast<unsigned long long*>(&av);
    unsigned long long ub = *reinterpret_cast<const unsigned long long*>(&b);
    unsigned long long uc = *reinterpret_cast<unsigned long long*>(&c);
    asm("fma.rn.f32x2 %0, %1, %2, %0;" : "+l"(uc) : "l"(ua), "l"(ub));
    c = *reinterpret_cast<float2*>(&uc);
}

// ---------------- gemm1: 128x128x16 fp32 SGEMM -> fp16 h, fused attention dots ----------------
// Each block's 128 columns == one full head, so the per-(row,head) dots with
// att_src/att_dst are computed from fp32 accumulators entirely in-block.
__global__ __launch_bounds__(256) void sgemm1_kernel(
    const float* __restrict__ A,      // x [NN, 256]
    const float* __restrict__ B,      // W_gat [256, 256]
    __half* __restrict__ C,           // h fp16 [NN, 256]
    const float* __restrict__ att_src,
    const float* __restrict__ att_dst) {
    __shared__ float As[16][132];
    __shared__ float Bs[16][128];
    const int tid  = threadIdx.x;
    const int brow = blockIdx.y * 128;
    const int bcol = blockIdx.x * 128;       // head = blockIdx.x
    const int tx   = tid % 16;
    const int ty   = tid / 16;
    const int K = FIN, N = FTOT;

    float2 acc2[8][4];
#pragma unroll
    for (int m = 0; m < 8; m++)
#pragma unroll
        for (int p = 0; p < 4; p++) acc2[m][p] = make_float2(0.f, 0.f);

    for (int k0 = 0; k0 < K; k0 += 16) {
#pragma unroll
        for (int l = 0; l < 2; l++) {
            int idx = tid + l * 256;
            int r = idx >> 2, c4 = (idx & 3) * 4;
            float4 v = *(const float4*)(A + (size_t)(brow + r) * K + k0 + c4);
            As[c4 + 0][r] = v.x; As[c4 + 1][r] = v.y;
            As[c4 + 2][r] = v.z; As[c4 + 3][r] = v.w;
        }
#pragma unroll
        for (int l = 0; l < 2; l++) {
            int idx = tid + l * 256;
            int r = idx >> 5, c4 = (idx & 31) * 4;
            *(float4*)&Bs[r][c4] = *(const float4*)(B + (size_t)(k0 + r) * N + bcol + c4);
        }
        __syncthreads();
#pragma unroll
        for (int k = 0; k < 16; k++) {
            float ar[8];
            *(float4*)&ar[0] = *(float4*)&As[k][ty * 8];
            *(float4*)&ar[4] = *(float4*)&As[k][ty * 8 + 4];
            float4 b0 = *(float4*)&Bs[k][tx * 8];
            float4 b1 = *(float4*)&Bs[k][tx * 8 + 4];
            float2 br[4] = {{b0.x, b0.y}, {b0.z, b0.w}, {b1.x, b1.y}, {b1.z, b1.w}};
#pragma unroll
            for (int m = 0; m < 8; m++) {
                ffma2(acc2[m][0], ar[m], br[0]);
                ffma2(acc2[m][1], ar[m], br[1]);
                ffma2(acc2[m][2], ar[m], br[2]);
                ffma2(acc2[m][3], ar[m], br[3]);
            }
        }
        __syncthreads();
    }

    // attention vector slices for this thread's 8 columns
    float4 s0 = *(const float4*)(att_src + bcol + tx * 8);
    float4 s1 = *(const float4*)(att_src + bcol + tx * 8 + 4);
    float4 d0 = *(const float4*)(att_dst + bcol + tx * 8);
    float4 d1 = *(const float4*)(att_dst + bcol + tx * 8 + 4);
    const int head = blockIdx.x;

#pragma unroll
    for (int m = 0; m < 8; m++) {
        int row = brow + ty * 8 + m;
        // store h row-slice as 8 halfs (one 16B store)
        __half2 hh[4];
        hh[0] = __floats2half2_rn(acc2[m][0].x, acc2[m][0].y);
        hh[1] = __floats2half2_rn(acc2[m][1].x, acc2[m][1].y);
        hh[2] = __floats2half2_rn(acc2[m][2].x, acc2[m][2].y);
        hh[3] = __floats2half2_rn(acc2[m][3].x, acc2[m][3].y);
        *(uint4*)(C + (size_t)row * N + bcol + tx * 8) = *(uint4*)hh;

        // partial dots over this thread's 8 columns
        float ds = acc2[m][0].x * s0.x + acc2[m][0].y * s0.y +
                   acc2[m][1].x * s0.z + acc2[m][1].y * s0.w +
                   acc2[m][2].x * s1.x + acc2[m][2].y * s1.y +
                   acc2[m][3].x * s1.z + acc2[m][3].y * s1.w;
        float dd = acc2[m][0].x * d0.x + acc2[m][0].y * d0.y +
                   acc2[m][1].x * d0.z + acc2[m][1].y * d0.w +
                   acc2[m][2].x * d1.x + acc2[m][2].y * d1.y +
                   acc2[m][3].x * d1.z + acc2[m][3].y * d1.w;
#pragma unroll
        for (int o = 8; o > 0; o >>= 1) {
            ds += __shfl_xor_sync(0xffffffffu, ds, o);
            dd += __shfl_xor_sync(0xffffffffu, dd, o);
        }
        if (tx == 0) {
            g_as[row * 2 + head] = ds;
            g_ad[row * 2 + head] = dd;
        }
    }
}

// ---------------- fused GEMM (full-row tiles) + bias + LayerNorm + ReLU [+ 32->3 proj] ----------------
template <int BM, int N, int K, int TM, bool PROJ>
__global__ void fused_gemm_ln_kernel(
    const float* __restrict__ A, const float* __restrict__ W,
    const float* __restrict__ bias, const float* __restrict__ gamma,
    const float* __restrict__ beta, float* __restrict__ C,
    const float* __restrict__ w3, const float* __restrict__ b3,
    float* __restrict__ Z) {
    constexpr int LX = N / 4;
    constexpr int THREADS = (BM / TM) * LX;
    __shared__ float As[16][BM + 4];
    __shared__ float Ws[16][N];
    __shared__ float w3s[96];
    __shared__ float b3s[3];
    const int tid = threadIdx.x;
    const int tx  = tid % LX;
    const int ty  = tid / LX;
    const int brow = blockIdx.x * BM;

    if (PROJ) {
        if (tid < 96) w3s[tid] = w3[tid];
        if (tid < 3)  b3s[tid] = b3[tid];
    }

    float2 acc2[TM][2];
#pragma unroll
    for (int m = 0; m < TM; m++) { acc2[m][0] = make_float2(0.f, 0.f); acc2[m][1] = make_float2(0.f, 0.f); }

    for (int k0 = 0; k0 < K; k0 += 16) {
#pragma unroll
        for (int i = tid; i < BM * 4; i += THREADS) {
            int r = i >> 2, c4 = (i & 3) * 4;
            float4 v = *(const float4*)(A + (size_t)(brow + r) * K + k0 + c4);
            As[c4 + 0][r] = v.x; As[c4 + 1][r] = v.y;
            As[c4 + 2][r] = v.z; As[c4 + 3][r] = v.w;
        }
#pragma unroll
        for (int i = tid; i < N * 4; i += THREADS) {
            int r = i / (N / 4), c4 = (i % (N / 4)) * 4;
            *(float4*)&Ws[r][c4] = *(const float4*)(W + (size_t)(k0 + r) * N + c4);
        }
        __syncthreads();
#pragma unroll
        for (int k = 0; k < 16; k++) {
            float ar[TM];
#pragma unroll
            for (int q = 0; q < TM / 4; q++)
                *(float4*)&ar[q * 4] = *(float4*)&As[k][ty * TM + q * 4];
            float4 b4 = *(float4*)&Ws[k][tx * 4];
            float2 br0 = make_float2(b4.x, b4.y);
            float2 br1 = make_float2(b4.z, b4.w);
#pragma unroll
            for (int m = 0; m < TM; m++) {
                ffma2(acc2[m][0], ar[m], br0);
                ffma2(acc2[m][1], ar[m], br1);
            }
        }
        __syncthreads();
    }

    const int c0 = tx * 4;
    float4 bi4 = *(const float4*)(bias + c0);
    float4 g4  = *(const float4*)(gamma + c0);
    float4 be4 = *(const float4*)(beta + c0);

#pragma unroll
    for (int m = 0; m < TM; m++) {
        float v0 = acc2[m][0].x + bi4.x;
        float v1 = acc2[m][0].y + bi4.y;
        float v2 = acc2[m][1].x + bi4.z;
        float v3 = acc2[m][1].y + bi4.w;
        float s = v0 + v1 + v2 + v3;
#pragma unroll
        for (int o = LX >> 1; o > 0; o >>= 1) s += __shfl_xor_sync(0xffffffffu, s, o);
        float mu = s * (1.f / N);
        float d0 = v0 - mu, d1 = v1 - mu, d2 = v2 - mu, d3 = v3 - mu;
        float sq = d0 * d0 + d1 * d1 + d2 * d2 + d3 * d3;
#pragma unroll
        for (int o = LX >> 1; o > 0; o >>= 1) sq += __shfl_xor_sync(0xffffffffu, sq, o);
        float inv = rsqrtf(sq * (1.f / N) + LN_EPS);
        float y0 = fmaxf(d0 * inv * g4.x + be4.x, 0.f);
        float y1 = fmaxf(d1 * inv * g4.y + be4.y, 0.f);
        float y2 = fmaxf(d2 * inv * g4.z + be4.z, 0.f);
        float y3 = fmaxf(d3 * inv * g4.w + be4.w, 0.f);
        int row = brow + ty * TM + m;
        if (!PROJ) {
            float4 v; v.x = y0; v.y = y1; v.z = y2; v.w = y3;
            *(float4*)(C + (size_t)row * N + c0) = v;
        } else {
            float p0 = y0 * w3s[(c0 + 0) * 3 + 0] + y1 * w3s[(c0 + 1) * 3 + 0] +
                       y2 * w3s[(c0 + 2) * 3 + 0] + y3 * w3s[(c0 + 3) * 3 + 0];
            float p1 = y0 * w3s[(c0 + 0) * 3 + 1] + y1 * w3s[(c0 + 1) * 3 + 1] +
                       y2 * w3s[(c0 + 2) * 3 + 1] + y3 * w3s[(c0 + 3) * 3 + 1];
            float p2 = y0 * w3s[(c0 + 0) * 3 + 2] + y1 * w3s[(c0 + 1) * 3 + 2] +
                       y2 * w3s[(c0 + 2) * 3 + 2] + y3 * w3s[(c0 + 3) * 3 + 2];
#pragma unroll
            for (int o = LX >> 1; o > 0; o >>= 1) {
                p0 += __shfl_xor_sync(0xffffffffu, p0, o);
                p1 += __shfl_xor_sync(0xffffffffu, p1, o);
                p2 += __shfl_xor_sync(0xffffffffu, p2, o);
            }
            if (tx == 0) {
                Z[row * 3 + 0] = p0 + b3s[0];
                Z[row * 3 + 1] = p1 + b3s[1];
                Z[row * 3 + 2] = p2 + b3s[2];
            }
        }
    }
}

// ---------------- bucket CSR: init (self-loop in slot 0) + single-pass scatter ----------------
__global__ void bucket_init_kernel() {
    int i = blockIdx.x * blockDim.x + threadIdx.x;
    if (i < NN) {
        g_deg[i] = 1;
        g_srt[i * CAP] = i;    // self loop
    }
}

__global__ void bucket_scatter_kernel(const int* __restrict__ ei) {
    int id = blockIdx.x * blockDim.x + threadIdx.x;   // [0, EE/4)
    if (id >= EE / 4) return;
    int4 s = *(const int4*)&ei[id * 4];
    int4 d = *(const int4*)&ei[EE + id * 4];
    int p;
    p = atomicAdd(&g_deg[d.x], 1); if (p < CAP) g_srt[d.x * CAP + p] = s.x;
    p = atomicAdd(&g_deg[d.y], 1); if (p < CAP) g_srt[d.y * CAP + p] = s.y;
    p = atomicAdd(&g_deg[d.z], 1); if (p < CAP) g_srt[d.z * CAP + p] = s.z;
    p = atomicAdd(&g_deg[d.w], 1); if (p < CAP) g_srt[d.w * CAP + p] = s.w;
}

// ---------------- GAT softmax + aggregation (fp16 h, LDG.64 per edge) ----------------
__global__ __launch_bounds__(64) void gat_agg_kernel(const float* __restrict__ bias) {
    const int dst = blockIdx.x;
    const int tid = threadIdx.x;
    const int start = dst * CAP;
    const int deg   = min(g_deg[dst], CAP);
    const float ad0 = g_ad[dst * 2], ad1 = g_ad[dst * 2 + 1];

    __shared__ int   sh_s[CAP];
    __shared__ float sh_w0[CAP];
    __shared__ float sh_w1[CAP];
    __shared__ float rsum[4];

    float s0 = 0.f, s1 = 0.f;
    for (int i = tid; i < deg; i += 64) {
        int s = g_srt[start + i];
        float2 av = ((const float2*)g_as)[s];
        float e0 = av.x + ad0; e0 = e0 > 0.f ? e0 : NEG_SLOPE * e0;
        float e1 = av.y + ad1; e1 = e1 > 0.f ? e1 : NEG_SLOPE * e1;
        float w0 = __expf(e0);
        float w1 = __expf(e1);
        sh_s[i]  = s;
        sh_w0[i] = w0;
        sh_w1[i] = w1;
        s0 += w0; s1 += w1;
    }
    __syncthreads();

    const int c0 = 4 * tid;                     // 4 channels per thread
    const float* shw = (tid >= 32) ? sh_w1 : sh_w0;
    float2 accA = make_float2(0.f, 0.f);
    float2 accB = make_float2(0.f, 0.f);
    const __half* hbase = &g_hh[c0];

#pragma unroll 8
    for (int i = 0; i < deg; i++) {
        float w = shw[i];
        uint2 v = *(const uint2*)(hbase + (size_t)sh_s[i] * FTOT);
        float2 f01 = __half22float2(*(__half2*)&v.x);
        float2 f23 = __half22float2(*(__half2*)&v.y);
        ffma2(accA, w, f01);
        ffma2(accB, w, f23);
    }

    // reduce s0,s1 across the 2 warps
#pragma unroll
    for (int o = 16; o > 0; o >>= 1) {
        s0 += __shfl_xor_sync(0xffffffffu, s0, o);
        s1 += __shfl_xor_sync(0xffffffffu, s1, o);
    }
    if ((tid & 31) == 0) { rsum[(tid >> 5) * 2] = s0; rsum[(tid >> 5) * 2 + 1] = s1; }
    __syncthreads();
    float t0 = rsum[0] + rsum[2];
    float t1 = rsum[1] + rsum[3];
    float inv = (tid >= 32) ? (1.f / (t1 + 1e-16f)) : (1.f / (t0 + 1e-16f));

    float4 bi = *(const float4*)(bias + c0);
    float4 o;
    o.x = fmaxf(accA.x * inv + bi.x, 0.f);
    o.y = fmaxf(accA.y * inv + bi.y, 0.f);
    o.z = fmaxf(accB.x * inv + bi.z, 0.f);
    o.w = fmaxf(accB.y * inv + bi.w, 0.f);
    *(float4*)&g_gat[(size_t)dst * 256 + c0] = o;
}

// ---------------- pairwise distances, 64 i-rows per block, streaming stores ----------------
#define CD_I 64
#define CD_J 1024
__global__ __launch_bounds__(256) void cdist_kernel(float* __restrict__ out) {
    __shared__ float zi[CD_I * 3];
    int ibase = blockIdx.y * CD_I;
    int jbase = blockIdx.x * CD_J;
    for (int t = threadIdx.x; t < CD_I * 3; t += 256) zi[t] = g_z[ibase * 3 + t];

    int j0 = jbase + threadIdx.x * 4;
    float4 p0 = *(const float4*)(g_z + (size_t)j0 * 3);
    float4 p1 = *(const float4*)(g_z + (size_t)j0 * 3 + 4);
    float4 p2 = *(const float4*)(g_z + (size_t)j0 * 3 + 8);
    float jx[4] = {p0.x, p0.w, p1.z, p2.y};
    float jy[4] = {p0.y, p1.x, p1.w, p2.z};
    float jz[4] = {p0.z, p1.y, p2.x, p2.w};
    __syncthreads();

#pragma unroll 4
    for (int ii = 0; ii < CD_I; ii++) {
        float zx = zi[ii * 3], zy = zi[ii * 3 + 1], zz = zi[ii * 3 + 2];
        float r[4];
#pragma unroll
        for (int t = 0; t < 4; t++) {
            float dx = zx - jx[t];
            float dy = zy - jy[t];
            float dz = zz - jz[t];
            float d2 = dx * dx + dy * dy + dz * dz;
            r[t] = d2 > 0.f ? sqrtf(d2) : 0.f;
        }
        float* ptr = out + (size_t)(ibase + ii) * NN + j0;
        asm volatile("st.global.cs.v4.f32 [%0], {%1, %2, %3, %4};"
                     :: "l"(ptr), "f"(r[0]), "f"(r[1]), "f"(r[2]), "f"(r[3])
                     : "memory");
    }
}

// ---------------- host launcher ----------------
extern "C" void kernel_launch(void* const* d_in, const int* in_sizes, int n_in,
                              void* d_out, int out_size) {
    const float* x        = (const float*)d_in[0];
    const int*   ei       = (const int*)  d_in[1];
    const float* W_gat    = (const float*)d_in[2];
    const float* att_src  = (const float*)d_in[3];
    const float* att_dst  = (const float*)d_in[4];
    const float* bias_gat = (const float*)d_in[5];
    const float* w_a  = (const float*)d_in[6];
    const float* b_a  = (const float*)d_in[7];
    const float* g_a  = (const float*)d_in[8];
    const float* be_a = (const float*)d_in[9];
    const float* w1   = (const float*)d_in[10];
    const float* b1   = (const float*)d_in[11];
    const float* g1   = (const float*)d_in[12];
    const float* be1  = (const float*)d_in[13];
    const float* w2   = (const float*)d_in[14];
    const float* b2   = (const float*)d_in[15];
    const float* g2   = (const float*)d_in[16];
    const float* be2  = (const float*)d_in[17];
    const float* w3   = (const float*)d_in[18];
    const float* b3   = (const float*)d_in[19];
    float* out = (float*)d_out;

    void* p;
    cudaGetSymbolAddress(&p, g_hh);  __half* phh = (__half*)p;
    cudaGetSymbolAddress(&p, g_gat); float* pgat = (float*)p;
    cudaGetSymbolAddress(&p, g_l1);  float* pl1  = (float*)p;
    cudaGetSymbolAddress(&p, g_l2);  float* pl2  = (float*)p;
    cudaGetSymbolAddress(&p, g_z);   float* pz   = (float*)p;

    // side stream + events for the CSR fork (host resources, created once;
    // identical GPU work is issued on every call)
    static cudaStream_t s2 = nullptr;
    static cudaEvent_t evFork = nullptr, evJoin = nullptr;
    static bool tried = false;
    if (!tried) {
        tried = true;
        if (cudaStreamCreateWithFlags(&s2, cudaStreamNonBlocking) != cudaSuccess) s2 = nullptr;
        if (s2) {
            if (cudaEventCreateWithFlags(&evFork, cudaEventDisableTiming) != cudaSuccess ||
                cudaEventCreateWithFlags(&evJoin, cudaEventDisableTiming) != cudaSuccess) {
                s2 = nullptr;
            }
        }
    }

    if (s2) {
        // fork: CSR bucket build depends only on edge_index
        cudaEventRecord(evFork, 0);
        cudaStreamWaitEvent(s2, evFork, 0);
        bucket_init_kernel<<<NN / 256, 256, 0, s2>>>();
        bucket_scatter_kernel<<<EE / 4 / 256, 256, 0, s2>>>(ei);
        cudaEventRecord(evJoin, s2);

        // main: h = x @ W_gat (fp16 out) with fused attention dots
        sgemm1_kernel<<<dim3(2, NN / 128), 256>>>(x, W_gat, phh, att_src, att_dst);

        // join before aggregation
        cudaStreamWaitEvent(0, evJoin, 0);
    } else {
        sgemm1_kernel<<<dim3(2, NN / 128), 256>>>(x, W_gat, phh, att_src, att_dst);
        bucket_init_kernel<<<NN / 256, 256>>>();
        bucket_scatter_kernel<<<EE / 4 / 256, 256>>>(ei);
    }

    // segment softmax + aggregation + bias + relu
    gat_agg_kernel<<<NN, 64>>>(bias_gat);

    // fused MLP: gemm + bias + LN + ReLU (+ final projection)
    fused_gemm_ln_kernel<64, 128, 256, 8, false><<<NN / 64, 256>>>(
        pgat, w_a, b_a, g_a, be_a, pl1, nullptr, nullptr, nullptr);
    fused_gemm_ln_kernel<128, 64, 128, 8, false><<<NN / 128, 256>>>(
        pl1, w1, b1, g1, be1, pl2, nullptr, nullptr, nullptr);
    fused_gemm_ln_kernel<128, 32, 64, 8, true><<<NN / 128, 128>>>(
        pl2, w2, b2, g2, be2, nullptr, w3, b3, pz);

    // pairwise distance matrix
    cdist_kernel<<<dim3(NN / CD_J, NN / CD_I), 256>>>(out);
}

// round 7
// speedup vs baseline: 1.0067x; 1.0067x over previous
#include <cuda_runtime.h>
#include <cuda_fp16.h>
#include <math.h>

#define NN   8192
#define EE   524288
#define FIN  256
#define FTOT 256      // H * F_OUT
#define FOUT 128
#define CAP  256      // per-node bucket capacity (mean deg = 65, Poisson)
#define LN_EPS   1e-5f
#define NEG_SLOPE 0.2f

// ---------------- scratch (__device__ globals; no allocation allowed) ----------------
__device__ __align__(16) __half g_hh[NN * FTOT];   // x @ W_gat, fp16
__device__ __align__(16) float g_as[NN * 2];       // per-node src attention logits
__device__ __align__(16) float g_ad[NN * 2];       // per-node dst attention logits
__device__ int   g_deg[NN];
__device__ int   g_srt[NN * CAP];    // bucketed src ids per dst
__device__ __align__(16) float g_gat[NN * 256];
__device__ __align__(16) float g_l1[NN * 128];
__device__ __align__(16) float g_l2[NN * 64];
__device__ __align__(16) float g_z[NN * 3];

// ---------------- packed fp32x2 FMA (Blackwell; ptxas never auto-fuses) ----------------
__device__ __forceinline__ void ffma2(float2& c, float a, const float2& b) {
    float2 av = make_float2(a, a);
    unsigned long long ua = *reinterpret_cast<unsigned long long*>(&av);
    unsigned long long ub = *reinterpret_cast<const unsigned long long*>(&b);
    unsigned long long uc = *reinterpret_cast<unsigned long long*>(&c);
    asm("fma.rn.f32x2 %0, %1, %2, %0;" : "+l"(uc) : "l"(ua), "l"(ub));
    c = *reinterpret_cast<float2*>(&uc);
}

// ---------------- gemm1: 128x128x16 fp32 SGEMM, fp16 output, plain epilogue ----------------
__global__ __launch_bounds__(256) void sgemm1_kernel(
    const float* __restrict__ A,      // x [NN, 256]
    const float* __restrict__ B,      // W_gat [256, 256]
    __half* __restrict__ C) {         // h fp16 [NN, 256]
    __shared__ float As[16][132];
    __shared__ float Bs[16][128];
    const int tid  = threadIdx.x;
    const int brow = blockIdx.y * 128;
    const int bcol = blockIdx.x * 128;
    const int tx   = tid % 16;
    const int ty   = tid / 16;
    const int K = FIN, N = FTOT;

    float2 acc2[8][4];
#pragma unroll
    for (int m = 0; m < 8; m++)
#pragma unroll
        for (int p = 0; p < 4; p++) acc2[m][p] = make_float2(0.f, 0.f);

    for (int k0 = 0; k0 < K; k0 += 16) {
#pragma unroll
        for (int l = 0; l < 2; l++) {
            int idx = tid + l * 256;
            int r = idx >> 2, c4 = (idx & 3) * 4;
            float4 v = *(const float4*)(A + (size_t)(brow + r) * K + k0 + c4);
            As[c4 + 0][r] = v.x; As[c4 + 1][r] = v.y;
            As[c4 + 2][r] = v.z; As[c4 + 3][r] = v.w;
        }
#pragma unroll
        for (int l = 0; l < 2; l++) {
            int idx = tid + l * 256;
            int r = idx >> 5, c4 = (idx & 31) * 4;
            *(float4*)&Bs[r][c4] = *(const float4*)(B + (size_t)(k0 + r) * N + bcol + c4);
        }
        __syncthreads();
#pragma unroll
        for (int k = 0; k < 16; k++) {
            float ar[8];
            *(float4*)&ar[0] = *(float4*)&As[k][ty * 8];
            *(float4*)&ar[4] = *(float4*)&As[k][ty * 8 + 4];
            float4 b0 = *(float4*)&Bs[k][tx * 8];
            float4 b1 = *(float4*)&Bs[k][tx * 8 + 4];
            float2 br[4] = {{b0.x, b0.y}, {b0.z, b0.w}, {b1.x, b1.y}, {b1.z, b1.w}};
#pragma unroll
            for (int m = 0; m < 8; m++) {
                ffma2(acc2[m][0], ar[m], br[0]);
                ffma2(acc2[m][1], ar[m], br[1]);
                ffma2(acc2[m][2], ar[m], br[2]);
                ffma2(acc2[m][3], ar[m], br[3]);
            }
        }
        __syncthreads();
    }
#pragma unroll
    for (int m = 0; m < 8; m++) {
        int row = brow + ty * 8 + m;
        __half2 hh[4];
        hh[0] = __floats2half2_rn(acc2[m][0].x, acc2[m][0].y);
        hh[1] = __floats2half2_rn(acc2[m][1].x, acc2[m][1].y);
        hh[2] = __floats2half2_rn(acc2[m][2].x, acc2[m][2].y);
        hh[3] = __floats2half2_rn(acc2[m][3].x, acc2[m][3].y);
        *(uint4*)(C + (size_t)row * N + bcol + tx * 8) = *(uint4*)hh;
    }
}

// ---------------- attention logits from fp16 h: both dots in one pass ----------------
__global__ void attn_dots_kernel(const float* __restrict__ att_src,
                                 const float* __restrict__ att_dst) {
    int warp = threadIdx.x >> 5;
    int lane = threadIdx.x & 31;
    int n    = blockIdx.x * 2 + (warp >> 1);
    int head = warp & 1;
    uint2 hv = ((const uint2*)&g_hh[(size_t)n * FTOT + head * FOUT])[lane];
    float2 h01 = __half22float2(*(__half2*)&hv.x);
    float2 h23 = __half22float2(*(__half2*)&hv.y);
    float4 s4 = ((const float4*)att_src)[head * 32 + lane];
    float4 d4 = ((const float4*)att_dst)[head * 32 + lane];
    float ds = h01.x * s4.x + h01.y * s4.y + h23.x * s4.z + h23.y * s4.w;
    float dd = h01.x * d4.x + h01.y * d4.y + h23.x * d4.z + h23.y * d4.w;
#pragma unroll
    for (int o = 16; o > 0; o >>= 1) {
        ds += __shfl_xor_sync(0xffffffff, ds, o);
        dd += __shfl_xor_sync(0xffffffff, dd, o);
    }
    if (lane == 0) {
        g_as[n * 2 + head] = ds;
        g_ad[n * 2 + head] = dd;
    }
}

// ---------------- fused GEMM (full-row tiles) + bias + LayerNorm + ReLU [+ 32->3 proj] ----------------
template <int BM, int N, int K, int TM, bool PROJ>
__global__ void fused_gemm_ln_kernel(
    const float* __restrict__ A, const float* __restrict__ W,
    const float* __restrict__ bias, const float* __restrict__ gamma,
    const float* __restrict__ beta, float* __restrict__ C,
    const float* __restrict__ w3, const float* __restrict__ b3,
    float* __restrict__ Z) {
    constexpr int LX = N / 4;
    constexpr int THREADS = (BM / TM) * LX;
    __shared__ float As[16][BM + 4];
    __shared__ float Ws[16][N];
    __shared__ float w3s[96];
    __shared__ float b3s[3];
    const int tid = threadIdx.x;
    const int tx  = tid % LX;
    const int ty  = tid / LX;
    const int brow = blockIdx.x * BM;

    if (PROJ) {
        for (int i = tid; i < 96; i += THREADS) w3s[i] = w3[i];
        if (tid < 3) b3s[tid] = b3[tid];
    }

    float2 acc2[TM][2];
#pragma unroll
    for (int m = 0; m < TM; m++) { acc2[m][0] = make_float2(0.f, 0.f); acc2[m][1] = make_float2(0.f, 0.f); }

    for (int k0 = 0; k0 < K; k0 += 16) {
#pragma unroll
        for (int i = tid; i < BM * 4; i += THREADS) {
            int r = i >> 2, c4 = (i & 3) * 4;
            float4 v = *(const float4*)(A + (size_t)(brow + r) * K + k0 + c4);
            As[c4 + 0][r] = v.x; As[c4 + 1][r] = v.y;
            As[c4 + 2][r] = v.z; As[c4 + 3][r] = v.w;
        }
#pragma unroll
        for (int i = tid; i < N * 4; i += THREADS) {
            int r = i / (N / 4), c4 = (i % (N / 4)) * 4;
            *(float4*)&Ws[r][c4] = *(const float4*)(W + (size_t)(k0 + r) * N + c4);
        }
        __syncthreads();
#pragma unroll
        for (int k = 0; k < 16; k++) {
            float ar[TM];
#pragma unroll
            for (int q = 0; q < TM / 4; q++)
                *(float4*)&ar[q * 4] = *(float4*)&As[k][ty * TM + q * 4];
            float4 b4 = *(float4*)&Ws[k][tx * 4];
            float2 br0 = make_float2(b4.x, b4.y);
            float2 br1 = make_float2(b4.z, b4.w);
#pragma unroll
            for (int m = 0; m < TM; m++) {
                ffma2(acc2[m][0], ar[m], br0);
                ffma2(acc2[m][1], ar[m], br1);
            }
        }
        __syncthreads();
    }

    const int c0 = tx * 4;
    float4 bi4 = *(const float4*)(bias + c0);
    float4 g4  = *(const float4*)(gamma + c0);
    float4 be4 = *(const float4*)(beta + c0);

#pragma unroll
    for (int m = 0; m < TM; m++) {
        float v0 = acc2[m][0].x + bi4.x;
        float v1 = acc2[m][0].y + bi4.y;
        float v2 = acc2[m][1].x + bi4.z;
        float v3 = acc2[m][1].y + bi4.w;
        float s = v0 + v1 + v2 + v3;
#pragma unroll
        for (int o = LX >> 1; o > 0; o >>= 1) s += __shfl_xor_sync(0xffffffffu, s, o);
        float mu = s * (1.f / N);
        float d0 = v0 - mu, d1 = v1 - mu, d2 = v2 - mu, d3 = v3 - mu;
        float sq = d0 * d0 + d1 * d1 + d2 * d2 + d3 * d3;
#pragma unroll
        for (int o = LX >> 1; o > 0; o >>= 1) sq += __shfl_xor_sync(0xffffffffu, sq, o);
        float inv = rsqrtf(sq * (1.f / N) + LN_EPS);
        float y0 = fmaxf(d0 * inv * g4.x + be4.x, 0.f);
        float y1 = fmaxf(d1 * inv * g4.y + be4.y, 0.f);
        float y2 = fmaxf(d2 * inv * g4.z + be4.z, 0.f);
        float y3 = fmaxf(d3 * inv * g4.w + be4.w, 0.f);
        int row = brow + ty * TM + m;
        if (!PROJ) {
            float4 v; v.x = y0; v.y = y1; v.z = y2; v.w = y3;
            *(float4*)(C + (size_t)row * N + c0) = v;
        } else {
            float p0 = y0 * w3s[(c0 + 0) * 3 + 0] + y1 * w3s[(c0 + 1) * 3 + 0] +
                       y2 * w3s[(c0 + 2) * 3 + 0] + y3 * w3s[(c0 + 3) * 3 + 0];
            float p1 = y0 * w3s[(c0 + 0) * 3 + 1] + y1 * w3s[(c0 + 1) * 3 + 1] +
                       y2 * w3s[(c0 + 2) * 3 + 1] + y3 * w3s[(c0 + 3) * 3 + 1];
            float p2 = y0 * w3s[(c0 + 0) * 3 + 2] + y1 * w3s[(c0 + 1) * 3 + 2] +
                       y2 * w3s[(c0 + 2) * 3 + 2] + y3 * w3s[(c0 + 3) * 3 + 2];
#pragma unroll
            for (int o = LX >> 1; o > 0; o >>= 1) {
                p0 += __shfl_xor_sync(0xffffffffu, p0, o);
                p1 += __shfl_xor_sync(0xffffffffu, p1, o);
                p2 += __shfl_xor_sync(0xffffffffu, p2, o);
            }
            if (tx == 0) {
                Z[row * 3 + 0] = p0 + b3s[0];
                Z[row * 3 + 1] = p1 + b3s[1];
                Z[row * 3 + 2] = p2 + b3s[2];
            }
        }
    }
}

// ---------------- bucket CSR: init (self-loop in slot 0) + single-pass scatter ----------------
__global__ void bucket_init_kernel() {
    int i = blockIdx.x * blockDim.x + threadIdx.x;
    if (i < NN) {
        g_deg[i] = 1;
        g_srt[i * CAP] = i;    // self loop
    }
}

__global__ void bucket_scatter_kernel(const int* __restrict__ ei) {
    int id = blockIdx.x * blockDim.x + threadIdx.x;   // [0, EE/4)
    if (id >= EE / 4) return;
    int4 s = *(const int4*)&ei[id * 4];
    int4 d = *(const int4*)&ei[EE + id * 4];
    int p;
    p = atomicAdd(&g_deg[d.x], 1); if (p < CAP) g_srt[d.x * CAP + p] = s.x;
    p = atomicAdd(&g_deg[d.y], 1); if (p < CAP) g_srt[d.y * CAP + p] = s.y;
    p = atomicAdd(&g_deg[d.z], 1); if (p < CAP) g_srt[d.z * CAP + p] = s.z;
    p = atomicAdd(&g_deg[d.w], 1); if (p < CAP) g_srt[d.w * CAP + p] = s.w;
}

// ---------------- GAT softmax + aggregation (fp16 h) -- verified 28.4us in R6 ----------------
__global__ __launch_bounds__(64) void gat_agg_kernel(const float* __restrict__ bias) {
    const int dst = blockIdx.x;
    const int tid = threadIdx.x;
    const int start = dst * CAP;
    const int deg   = min(g_deg[dst], CAP);
    const float ad0 = g_ad[dst * 2], ad1 = g_ad[dst * 2 + 1];

    __shared__ int   sh_s[CAP];
    __shared__ float sh_w0[CAP];
    __shared__ float sh_w1[CAP];
    __shared__ float rsum[4];

    float s0 = 0.f, s1 = 0.f;
    for (int i = tid; i < deg; i += 64) {
        int s = g_srt[start + i];
        float2 av = ((const float2*)g_as)[s];
        float e0 = av.x + ad0; e0 = e0 > 0.f ? e0 : NEG_SLOPE * e0;
        float e1 = av.y + ad1; e1 = e1 > 0.f ? e1 : NEG_SLOPE * e1;
        float w0 = __expf(e0);
        float w1 = __expf(e1);
        sh_s[i]  = s;
        sh_w0[i] = w0;
        sh_w1[i] = w1;
        s0 += w0; s1 += w1;
    }
    __syncthreads();

    const int c0 = 4 * tid;                     // 4 channels per thread
    const float* shw = (tid >= 32) ? sh_w1 : sh_w0;
    float2 accA = make_float2(0.f, 0.f);
    float2 accB = make_float2(0.f, 0.f);
    const __half* hbase = &g_hh[c0];

#pragma unroll 8
    for (int i = 0; i < deg; i++) {
        float w = shw[i];
        uint2 v = *(const uint2*)(hbase + (size_t)sh_s[i] * FTOT);
        float2 f01 = __half22float2(*(__half2*)&v.x);
        float2 f23 = __half22float2(*(__half2*)&v.y);
        ffma2(accA, w, f01);
        ffma2(accB, w, f23);
    }

    // reduce s0,s1 across the 2 warps
#pragma unroll
    for (int o = 16; o > 0; o >>= 1) {
        s0 += __shfl_xor_sync(0xffffffffu, s0, o);
        s1 += __shfl_xor_sync(0xffffffffu, s1, o);
    }
    if ((tid & 31) == 0) { rsum[(tid >> 5) * 2] = s0; rsum[(tid >> 5) * 2 + 1] = s1; }
    __syncthreads();
    float t0 = rsum[0] + rsum[2];
    float t1 = rsum[1] + rsum[3];
    float inv = (tid >= 32) ? (1.f / (t1 + 1e-16f)) : (1.f / (t0 + 1e-16f));

    float4 bi = *(const float4*)(bias + c0);
    float4 o;
    o.x = fmaxf(accA.x * inv + bi.x, 0.f);
    o.y = fmaxf(accA.y * inv + bi.y, 0.f);
    o.z = fmaxf(accB.x * inv + bi.z, 0.f);
    o.w = fmaxf(accB.y * inv + bi.w, 0.f);
    *(float4*)&g_gat[(size_t)dst * 256 + c0] = o;
}

// ---------------- pairwise distances, 64 i-rows per block, streaming stores ----------------
#define CD_I 64
#define CD_J 1024
__global__ __launch_bounds__(256) void cdist_kernel(float* __restrict__ out) {
    __shared__ float zi[CD_I * 3];
    int ibase = blockIdx.y * CD_I;
    int jbase = blockIdx.x * CD_J;
    for (int t = threadIdx.x; t < CD_I * 3; t += 256) zi[t] = g_z[ibase * 3 + t];

    int j0 = jbase + threadIdx.x * 4;
    float4 p0 = *(const float4*)(g_z + (size_t)j0 * 3);
    float4 p1 = *(const float4*)(g_z + (size_t)j0 * 3 + 4);
    float4 p2 = *(const float4*)(g_z + (size_t)j0 * 3 + 8);
    float jx[4] = {p0.x, p0.w, p1.z, p2.y};
    float jy[4] = {p0.y, p1.x, p1.w, p2.z};
    float jz[4] = {p0.z, p1.y, p2.x, p2.w};
    __syncthreads();

#pragma unroll 4
    for (int ii = 0; ii < CD_I; ii++) {
        float zx = zi[ii * 3], zy = zi[ii * 3 + 1], zz = zi[ii * 3 + 2];
        float r[4];
#pragma unroll
        for (int t = 0; t < 4; t++) {
            float dx = zx - jx[t];
            float dy = zy - jy[t];
            float dz = zz - jz[t];
            float d2 = dx * dx + dy * dy + dz * dz;
            r[t] = d2 > 0.f ? sqrtf(d2) : 0.f;
        }
        float* ptr = out + (size_t)(ibase + ii) * NN + j0;
        asm volatile("st.global.cs.v4.f32 [%0], {%1, %2, %3, %4};"
                     :: "l"(ptr), "f"(r[0]), "f"(r[1]), "f"(r[2]), "f"(r[3])
                     : "memory");
    }
}

// ---------------- host launcher ----------------
extern "C" void kernel_launch(void* const* d_in, const int* in_sizes, int n_in,
                              void* d_out, int out_size) {
    const float* x        = (const float*)d_in[0];
    const int*   ei       = (const int*)  d_in[1];
    const float* W_gat    = (const float*)d_in[2];
    const float* att_src  = (const float*)d_in[3];
    const float* att_dst  = (const float*)d_in[4];
    const float* bias_gat = (const float*)d_in[5];
    const float* w_a  = (const float*)d_in[6];
    const float* b_a  = (const float*)d_in[7];
    const float* g_a  = (const float*)d_in[8];
    const float* be_a = (const float*)d_in[9];
    const float* w1   = (const float*)d_in[10];
    const float* b1   = (const float*)d_in[11];
    const float* g1   = (const float*)d_in[12];
    const float* be1  = (const float*)d_in[13];
    const float* w2   = (const float*)d_in[14];
    const float* b2   = (const float*)d_in[15];
    const float* g2   = (const float*)d_in[16];
    const float* be2  = (const float*)d_in[17];
    const float* w3   = (const float*)d_in[18];
    const float* b3   = (const float*)d_in[19];
    float* out = (float*)d_out;

    void* p;
    cudaGetSymbolAddress(&p, g_hh);  __half* phh = (__half*)p;
    cudaGetSymbolAddress(&p, g_gat); float* pgat = (float*)p;
    cudaGetSymbolAddress(&p, g_l1);  float* pl1  = (float*)p;
    cudaGetSymbolAddress(&p, g_l2);  float* pl2  = (float*)p;
    cudaGetSymbolAddress(&p, g_z);   float* pz   = (float*)p;

    // side stream + events for the CSR fork (host resources, created once;
    // identical GPU work is issued on every call)
    static cudaStream_t s2 = nullptr;
    static cudaEvent_t evFork = nullptr, evJoin = nullptr;
    static bool tried = false;
    if (!tried) {
        tried = true;
        if (cudaStreamCreateWithFlags(&s2, cudaStreamNonBlocking) != cudaSuccess) s2 = nullptr;
        if (s2) {
            if (cudaEventCreateWithFlags(&evFork, cudaEventDisableTiming) != cudaSuccess ||
                cudaEventCreateWithFlags(&evJoin, cudaEventDisableTiming) != cudaSuccess) {
                s2 = nullptr;
            }
        }
    }

    if (s2) {
        // fork: CSR bucket build depends only on edge_index
        cudaEventRecord(evFork, 0);
        cudaStreamWaitEvent(s2, evFork, 0);
        bucket_init_kernel<<<NN / 256, 256, 0, s2>>>();
        bucket_scatter_kernel<<<EE / 4 / 256, 256, 0, s2>>>(ei);
        cudaEventRecord(evJoin, s2);

        // main: h = x @ W_gat (fp16 out), then attention dots
        sgemm1_kernel<<<dim3(2, NN / 128), 256>>>(x, W_gat, phh);
        attn_dots_kernel<<<NN / 2, 128>>>(att_src, att_dst);

        // join before aggregation
        cudaStreamWaitEvent(0, evJoin, 0);
    } else {
        sgemm1_kernel<<<dim3(2, NN / 128), 256>>>(x, W_gat, phh);
        attn_dots_kernel<<<NN / 2, 128>>>(att_src, att_dst);
        bucket_init_kernel<<<NN / 256, 256>>>();
        bucket_scatter_kernel<<<EE / 4 / 256, 256>>>(ei);
    }

    // segment softmax + aggregation + bias + relu
    gat_agg_kernel<<<NN, 64>>>(bias_gat);

    // fused MLP: gemm + bias + LN + ReLU (+ final projection); full-wave grids
    fused_gemm_ln_kernel<64, 128, 256, 8, false><<<NN / 64, 256>>>(
        pgat, w_a, b_a, g_a, be_a, pl1, nullptr, nullptr, nullptr);
    fused_gemm_ln_kernel<64, 64, 128, 8, false><<<NN / 64, 128>>>(
        pl1, w1, b1, g1, be1, pl2, nullptr, nullptr, nullptr);
    fused_gemm_ln_kernel<64, 32, 64, 8, true><<<NN / 64, 64>>>(
        pl2, w2, b2, g2, be2, nullptr, w3, b3, pz);

    // pairwise distance matrix
    cdist_kernel<<<dim3(NN / CD_J, NN / CD_I), 256>>>(out);
}

// round 8
// speedup vs baseline: 1.2736x; 1.2651x over previous
#include <cuda_runtime.h>
#include <cuda_fp16.h>
#include <math.h>

#define NN   8192
#define EE   524288
#define FIN  256
#define FTOT 256      // H * F_OUT
#define FOUT 128
#define CAP  256      // per-node bucket capacity (mean deg = 65, Poisson)
#define LN_EPS   1e-5f
#define NEG_SLOPE 0.2f

// ---------------- scratch (__device__ globals; no allocation allowed) ----------------
__device__ __align__(16) __half g_xh[NN * FIN];    // x in fp16
__device__ __align__(16) __half g_wh[FIN * FTOT];  // W_gat in fp16
__device__ __align__(16) __half g_hh[NN * FTOT];   // x @ W_gat, fp16
__device__ __align__(16) float g_as[NN * 2];       // per-node src attention logits
__device__ __align__(16) float g_ad[NN * 2];       // per-node dst attention logits
__device__ int   g_deg[NN];
__device__ int   g_srt[NN * CAP];    // bucketed src ids per dst
__device__ __align__(16) float g_gat[NN * 256];
__device__ __align__(16) float g_l1[NN * 128];
__device__ __align__(16) float g_l2[NN * 64];
__device__ __align__(16) float g_z[NN * 3];

// ---------------- packed fp32x2 FMA (Blackwell; ptxas never auto-fuses) ----------------
__device__ __forceinline__ void ffma2(float2& c, float a, const float2& b) {
    float2 av = make_float2(a, a);
    unsigned long long ua = *reinterpret_cast<unsigned long long*>(&av);
    unsigned long long ub = *reinterpret_cast<const unsigned long long*>(&b);
    unsigned long long uc = *reinterpret_cast<unsigned long long*>(&c);
    asm("fma.rn.f32x2 %0, %1, %2, %0;" : "+l"(uc) : "l"(ua), "l"(ub));
    c = *reinterpret_cast<float2*>(&uc);
}

// ---------------- fp32 -> fp16 conversion (float4 granularity) ----------------
__global__ void cvt_fp16_kernel(const float* __restrict__ src, __half* __restrict__ dst, int n4) {
    int i = blockIdx.x * blockDim.x + threadIdx.x;
    if (i < n4) {
        float4 v = ((const float4*)src)[i];
        __half2 h0 = __floats2half2_rn(v.x, v.y);
        __half2 h1 = __floats2half2_rn(v.z, v.w);
        uint2 u;
        u.x = *(unsigned*)&h0;
        u.y = *(unsigned*)&h1;
        ((uint2*)dst)[i] = u;
    }
}

// ---------------- gemm1: fp16 HMMA (mma.sync m16n8k16), 128x128 tile, 8 warps ----------------
__global__ __launch_bounds__(256) void hgemm1_kernel(
    const __half* __restrict__ Ah,   // x fp16 [NN][256]
    const __half* __restrict__ Bh,   // W fp16 [256][256]
    __half* __restrict__ C) {        // h fp16 [NN][256]
    __shared__ __half As[128][24];    // 16 halfs + 8 pad (48B rows, ldmatrix conflict-free)
    __shared__ __half Bs[16][136];    // 128 halfs + 8 pad (272B rows)
    __shared__ __half Cs[128][136];   // output staging
    const int tid  = threadIdx.x;
    const int warp = tid >> 5;
    const int lane = tid & 31;
    const int brow = blockIdx.y * 128;
    const int bcol = blockIdx.x * 128;
    const int mw = (warp & 3) * 32;   // warp m offset
    const int nw = (warp >> 2) * 64;  // warp n offset

    float c[2][8][4];
#pragma unroll
    for (int mi = 0; mi < 2; mi++)
#pragma unroll
        for (int nj = 0; nj < 8; nj++)
#pragma unroll
            for (int q = 0; q < 4; q++) c[mi][nj][q] = 0.f;

    // ldmatrix source addresses (fixed per lane)
    unsigned aAddr[2], bAddr[4];
#pragma unroll
    for (int mi = 0; mi < 2; mi++)
        aAddr[mi] = (unsigned)__cvta_generic_to_shared(
            &As[mw + mi * 16 + (lane & 15)][(lane >> 4) * 8]);
#pragma unroll
    for (int j = 0; j < 4; j++)
        bAddr[j] = (unsigned)__cvta_generic_to_shared(
            &Bs[lane & 15][nw + j * 16 + (lane >> 4) * 8]);

    const int ar = tid >> 1, ac = (tid & 1) * 8;       // A staging: 2 threads/row
    const int br = tid >> 4, bc = (tid & 15) * 8;      // B staging: 16 threads/row

    for (int k0 = 0; k0 < FIN; k0 += 16) {
        *(uint4*)&As[ar][ac] = *(const uint4*)(Ah + (size_t)(brow + ar) * FIN + k0 + ac);
        *(uint4*)&Bs[br][bc] = *(const uint4*)(Bh + (size_t)(k0 + br) * FTOT + bcol + bc);
        __syncthreads();

        unsigned a[2][4], b[4][4];
#pragma unroll
        for (int mi = 0; mi < 2; mi++)
            asm volatile("ldmatrix.sync.aligned.m8n8.x4.shared.b16 {%0,%1,%2,%3}, [%4];"
                         : "=r"(a[mi][0]), "=r"(a[mi][1]), "=r"(a[mi][2]), "=r"(a[mi][3])
                         : "r"(aAddr[mi]));
#pragma unroll
        for (int j = 0; j < 4; j++)
            asm volatile("ldmatrix.sync.aligned.m8n8.x4.trans.shared.b16 {%0,%1,%2,%3}, [%4];"
                         : "=r"(b[j][0]), "=r"(b[j][1]), "=r"(b[j][2]), "=r"(b[j][3])
                         : "r"(bAddr[j]));
#pragma unroll
        for (int mi = 0; mi < 2; mi++)
#pragma unroll
            for (int nj = 0; nj < 8; nj++) {
                const unsigned b0 = b[nj >> 1][(nj & 1) * 2];
                const unsigned b1 = b[nj >> 1][(nj & 1) * 2 + 1];
                asm volatile(
                    "mma.sync.aligned.m16n8k16.row.col.f32.f16.f16.f32 "
                    "{%0,%1,%2,%3}, {%4,%5,%6,%7}, {%8,%9}, {%0,%1,%2,%3};"
                    : "+f"(c[mi][nj][0]), "+f"(c[mi][nj][1]),
                      "+f"(c[mi][nj][2]), "+f"(c[mi][nj][3])
                    : "r"(a[mi][0]), "r"(a[mi][1]), "r"(a[mi][2]), "r"(a[mi][3]),
                      "r"(b0), "r"(b1));
            }
        __syncthreads();
    }

    // epilogue: stage fp16 into Cs, then cooperative uint4 stores
    const int g  = lane >> 2;
    const int tg = lane & 3;
#pragma unroll
    for (int mi = 0; mi < 2; mi++)
#pragma unroll
        for (int nj = 0; nj < 8; nj++) {
            int r0 = mw + mi * 16 + g;
            int cc = nw + nj * 8 + tg * 2;
            *(__half2*)&Cs[r0][cc]     = __floats2half2_rn(c[mi][nj][0], c[mi][nj][1]);
            *(__half2*)&Cs[r0 + 8][cc] = __floats2half2_rn(c[mi][nj][2], c[mi][nj][3]);
        }
    __syncthreads();
#pragma unroll
    for (int l = 0; l < 8; l++) {
        int idx = tid + l * 256;
        int r = idx >> 4, c8 = (idx & 15) * 8;
        *(uint4*)(C + (size_t)(brow + r) * FTOT + bcol + c8) = *(uint4*)&Cs[r][c8];
    }
}

// ---------------- attention logits from fp16 h: both dots in one pass ----------------
__global__ void attn_dots_kernel(const float* __restrict__ att_src,
                                 const float* __restrict__ att_dst) {
    int warp = threadIdx.x >> 5;
    int lane = threadIdx.x & 31;
    int n    = blockIdx.x * 2 + (warp >> 1);
    int head = warp & 1;
    uint2 hv = ((const uint2*)&g_hh[(size_t)n * FTOT + head * FOUT])[lane];
    float2 h01 = __half22float2(*(__half2*)&hv.x);
    float2 h23 = __half22float2(*(__half2*)&hv.y);
    float4 s4 = ((const float4*)att_src)[head * 32 + lane];
    float4 d4 = ((const float4*)att_dst)[head * 32 + lane];
    float ds = h01.x * s4.x + h01.y * s4.y + h23.x * s4.z + h23.y * s4.w;
    float dd = h01.x * d4.x + h01.y * d4.y + h23.x * d4.z + h23.y * d4.w;
#pragma unroll
    for (int o = 16; o > 0; o >>= 1) {
        ds += __shfl_xor_sync(0xffffffff, ds, o);
        dd += __shfl_xor_sync(0xffffffff, dd, o);
    }
    if (lane == 0) {
        g_as[n * 2 + head] = ds;
        g_ad[n * 2 + head] = dd;
    }
}

// ---------------- fused GEMM (full-row tiles) + bias + LayerNorm + ReLU [+ 32->3 proj] ----------------
template <int BM, int N, int K, int TM, bool PROJ>
__global__ void fused_gemm_ln_kernel(
    const float* __restrict__ A, const float* __restrict__ W,
    const float* __restrict__ bias, const float* __restrict__ gamma,
    const float* __restrict__ beta, float* __restrict__ C,
    const float* __restrict__ w3, const float* __restrict__ b3,
    float* __restrict__ Z) {
    constexpr int LX = N / 4;
    constexpr int THREADS = (BM / TM) * LX;
    __shared__ float As[16][BM + 4];
    __shared__ float Ws[16][N];
    __shared__ float w3s[96];
    __shared__ float b3s[3];
    const int tid = threadIdx.x;
    const int tx  = tid % LX;
    const int ty  = tid / LX;
    const int brow = blockIdx.x * BM;

    if (PROJ) {
        for (int i = tid; i < 96; i += THREADS) w3s[i] = w3[i];
        if (tid < 3) b3s[tid] = b3[tid];
    }

    float2 acc2[TM][2];
#pragma unroll
    for (int m = 0; m < TM; m++) { acc2[m][0] = make_float2(0.f, 0.f); acc2[m][1] = make_float2(0.f, 0.f); }

    for (int k0 = 0; k0 < K; k0 += 16) {
#pragma unroll
        for (int i = tid; i < BM * 4; i += THREADS) {
            int r = i >> 2, c4 = (i & 3) * 4;
            float4 v = *(const float4*)(A + (size_t)(brow + r) * K + k0 + c4);
            As[c4 + 0][r] = v.x; As[c4 + 1][r] = v.y;
            As[c4 + 2][r] = v.z; As[c4 + 3][r] = v.w;
        }
#pragma unroll
        for (int i = tid; i < N * 4; i += THREADS) {
            int r = i / (N / 4), c4 = (i % (N / 4)) * 4;
            *(float4*)&Ws[r][c4] = *(const float4*)(W + (size_t)(k0 + r) * N + c4);
        }
        __syncthreads();
#pragma unroll
        for (int k = 0; k < 16; k++) {
            float ar[TM];
#pragma unroll
            for (int q = 0; q < TM / 4; q++)
                *(float4*)&ar[q * 4] = *(float4*)&As[k][ty * TM + q * 4];
            float4 b4 = *(float4*)&Ws[k][tx * 4];
            float2 br0 = make_float2(b4.x, b4.y);
            float2 br1 = make_float2(b4.z, b4.w);
#pragma unroll
            for (int m = 0; m < TM; m++) {
                ffma2(acc2[m][0], ar[m], br0);
                ffma2(acc2[m][1], ar[m], br1);
            }
        }
        __syncthreads();
    }

    const int c0 = tx * 4;
    float4 bi4 = *(const float4*)(bias + c0);
    float4 g4  = *(const float4*)(gamma + c0);
    float4 be4 = *(const float4*)(beta + c0);

#pragma unroll
    for (int m = 0; m < TM; m++) {
        float v0 = acc2[m][0].x + bi4.x;
        float v1 = acc2[m][0].y + bi4.y;
        float v2 = acc2[m][1].x + bi4.z;
        float v3 = acc2[m][1].y + bi4.w;
        float s = v0 + v1 + v2 + v3;
#pragma unroll
        for (int o = LX >> 1; o > 0; o >>= 1) s += __shfl_xor_sync(0xffffffffu, s, o);
        float mu = s * (1.f / N);
        float d0 = v0 - mu, d1 = v1 - mu, d2 = v2 - mu, d3 = v3 - mu;
        float sq = d0 * d0 + d1 * d1 + d2 * d2 + d3 * d3;
#pragma unroll
        for (int o = LX >> 1; o > 0; o >>= 1) sq += __shfl_xor_sync(0xffffffffu, sq, o);
        float inv = rsqrtf(sq * (1.f / N) + LN_EPS);
        float y0 = fmaxf(d0 * inv * g4.x + be4.x, 0.f);
        float y1 = fmaxf(d1 * inv * g4.y + be4.y, 0.f);
        float y2 = fmaxf(d2 * inv * g4.z + be4.z, 0.f);
        float y3 = fmaxf(d3 * inv * g4.w + be4.w, 0.f);
        int row = brow + ty * TM + m;
        if (!PROJ) {
            float4 v; v.x = y0; v.y = y1; v.z = y2; v.w = y3;
            *(float4*)(C + (size_t)row * N + c0) = v;
        } else {
            float p0 = y0 * w3s[(c0 + 0) * 3 + 0] + y1 * w3s[(c0 + 1) * 3 + 0] +
                       y2 * w3s[(c0 + 2) * 3 + 0] + y3 * w3s[(c0 + 3) * 3 + 0];
            float p1 = y0 * w3s[(c0 + 0) * 3 + 1] + y1 * w3s[(c0 + 1) * 3 + 1] +
                       y2 * w3s[(c0 + 2) * 3 + 1] + y3 * w3s[(c0 + 3) * 3 + 1];
            float p2 = y0 * w3s[(c0 + 0) * 3 + 2] + y1 * w3s[(c0 + 1) * 3 + 2] +
                       y2 * w3s[(c0 + 2) * 3 + 2] + y3 * w3s[(c0 + 3) * 3 + 2];
#pragma unroll
            for (int o = LX >> 1; o > 0; o >>= 1) {
                p0 += __shfl_xor_sync(0xffffffffu, p0, o);
                p1 += __shfl_xor_sync(0xffffffffu, p1, o);
                p2 += __shfl_xor_sync(0xffffffffu, p2, o);
            }
            if (tx == 0) {
                Z[row * 3 + 0] = p0 + b3s[0];
                Z[row * 3 + 1] = p1 + b3s[1];
                Z[row * 3 + 2] = p2 + b3s[2];
            }
        }
    }
}

// ---------------- bucket CSR: init (self-loop in slot 0) + single-pass scatter ----------------
__global__ void bucket_init_kernel() {
    int i = blockIdx.x * blockDim.x + threadIdx.x;
    if (i < NN) {
        g_deg[i] = 1;
        g_srt[i * CAP] = i;    // self loop
    }
}

__global__ void bucket_scatter_kernel(const int* __restrict__ ei) {
    int id = blockIdx.x * blockDim.x + threadIdx.x;   // [0, EE/4)
    if (id >= EE / 4) return;
    int4 s = *(const int4*)&ei[id * 4];
    int4 d = *(const int4*)&ei[EE + id * 4];
    int p;
    p = atomicAdd(&g_deg[d.x], 1); if (p < CAP) g_srt[d.x * CAP + p] = s.x;
    p = atomicAdd(&g_deg[d.y], 1); if (p < CAP) g_srt[d.y * CAP + p] = s.y;
    p = atomicAdd(&g_deg[d.z], 1); if (p < CAP) g_srt[d.z * CAP + p] = s.z;
    p = atomicAdd(&g_deg[d.w], 1); if (p < CAP) g_srt[d.w * CAP + p] = s.w;
}

// ---------------- GAT softmax + aggregation (fp16 h) -- verified 28.4us in R6 ----------------
__global__ __launch_bounds__(64) void gat_agg_kernel(const float* __restrict__ bias) {
    const int dst = blockIdx.x;
    const int tid = threadIdx.x;
    const int start = dst * CAP;
    const int deg   = min(g_deg[dst], CAP);
    const float ad0 = g_ad[dst * 2], ad1 = g_ad[dst * 2 + 1];

    __shared__ int   sh_s[CAP];
    __shared__ float sh_w0[CAP];
    __shared__ float sh_w1[CAP];
    __shared__ float rsum[4];

    float s0 = 0.f, s1 = 0.f;
    for (int i = tid; i < deg; i += 64) {
        int s = g_srt[start + i];
        float2 av = ((const float2*)g_as)[s];
        float e0 = av.x + ad0; e0 = e0 > 0.f ? e0 : NEG_SLOPE * e0;
        float e1 = av.y + ad1; e1 = e1 > 0.f ? e1 : NEG_SLOPE * e1;
        float w0 = __expf(e0);
        float w1 = __expf(e1);
        sh_s[i]  = s;
        sh_w0[i] = w0;
        sh_w1[i] = w1;
        s0 += w0; s1 += w1;
    }
    __syncthreads();

    const int c0 = 4 * tid;                     // 4 channels per thread
    const float* shw = (tid >= 32) ? sh_w1 : sh_w0;
    float2 accA = make_float2(0.f, 0.f);
    float2 accB = make_float2(0.f, 0.f);
    const __half* hbase = &g_hh[c0];

#pragma unroll 8
    for (int i = 0; i < deg; i++) {
        float w = shw[i];
        uint2 v = *(const uint2*)(hbase + (size_t)sh_s[i] * FTOT);
        float2 f01 = __half22float2(*(__half2*)&v.x);
        float2 f23 = __half22float2(*(__half2*)&v.y);
        ffma2(accA, w, f01);
        ffma2(accB, w, f23);
    }

    // reduce s0,s1 across the 2 warps
#pragma unroll
    for (int o = 16; o > 0; o >>= 1) {
        s0 += __shfl_xor_sync(0xffffffffu, s0, o);
        s1 += __shfl_xor_sync(0xffffffffu, s1, o);
    }
    if ((tid & 31) == 0) { rsum[(tid >> 5) * 2] = s0; rsum[(tid >> 5) * 2 + 1] = s1; }
    __syncthreads();
    float t0 = rsum[0] + rsum[2];
    float t1 = rsum[1] + rsum[3];
    float inv = (tid >= 32) ? (1.f / (t1 + 1e-16f)) : (1.f / (t0 + 1e-16f));

    float4 bi = *(const float4*)(bias + c0);
    float4 o;
    o.x = fmaxf(accA.x * inv + bi.x, 0.f);
    o.y = fmaxf(accA.y * inv + bi.y, 0.f);
    o.z = fmaxf(accB.x * inv + bi.z, 0.f);
    o.w = fmaxf(accB.y * inv + bi.w, 0.f);
    *(float4*)&g_gat[(size_t)dst * 256 + c0] = o;
}

// ---------------- pairwise distances, 64 i-rows per block, streaming stores ----------------
#define CD_I 64
#define CD_J 1024
__global__ __launch_bounds__(256) void cdist_kernel(float* __restrict__ out) {
    __shared__ float zi[CD_I * 3];
    int ibase = blockIdx.y * CD_I;
    int jbase = blockIdx.x * CD_J;
    for (int t = threadIdx.x; t < CD_I * 3; t += 256) zi[t] = g_z[ibase * 3 + t];

    int j0 = jbase + threadIdx.x * 4;
    float4 p0 = *(const float4*)(g_z + (size_t)j0 * 3);
    float4 p1 = *(const float4*)(g_z + (size_t)j0 * 3 + 4);
    float4 p2 = *(const float4*)(g_z + (size_t)j0 * 3 + 8);
    float jx[4] = {p0.x, p0.w, p1.z, p2.y};
    float jy[4] = {p0.y, p1.x, p1.w, p2.z};
    float jz[4] = {p0.z, p1.y, p2.x, p2.w};
    __syncthreads();

#pragma unroll 4
    for (int ii = 0; ii < CD_I; ii++) {
        float zx = zi[ii * 3], zy = zi[ii * 3 + 1], zz = zi[ii * 3 + 2];
        float r[4];
#pragma unroll
        for (int t = 0; t < 4; t++) {
            float dx = zx - jx[t];
            float dy = zy - jy[t];
            float dz = zz - jz[t];
            float d2 = dx * dx + dy * dy + dz * dz;
            r[t] = d2 > 0.f ? sqrtf(d2) : 0.f;
        }
        float* ptr = out + (size_t)(ibase + ii) * NN + j0;
        asm volatile("st.global.cs.v4.f32 [%0], {%1, %2, %3, %4};"
                     :: "l"(ptr), "f"(r[0]), "f"(r[1]), "f"(r[2]), "f"(r[3])
                     : "memory");
    }
}

// ---------------- host launcher ----------------
extern "C" void kernel_launch(void* const* d_in, const int* in_sizes, int n_in,
                              void* d_out, int out_size) {
    const float* x        = (const float*)d_in[0];
    const int*   ei       = (const int*)  d_in[1];
    const float* W_gat    = (const float*)d_in[2];
    const float* att_src  = (const float*)d_in[3];
    const float* att_dst  = (const float*)d_in[4];
    const float* bias_gat = (const float*)d_in[5];
    const float* w_a  = (const float*)d_in[6];
    const float* b_a  = (const float*)d_in[7];
    const float* g_a  = (const float*)d_in[8];
    const float* be_a = (const float*)d_in[9];
    const float* w1   = (const float*)d_in[10];
    const float* b1   = (const float*)d_in[11];
    const float* g1   = (const float*)d_in[12];
    const float* be1  = (const float*)d_in[13];
    const float* w2   = (const float*)d_in[14];
    const float* b2   = (const float*)d_in[15];
    const float* g2   = (const float*)d_in[16];
    const float* be2  = (const float*)d_in[17];
    const float* w3   = (const float*)d_in[18];
    const float* b3   = (const float*)d_in[19];
    float* out = (float*)d_out;

    void* p;
    cudaGetSymbolAddress(&p, g_xh);  __half* pxh = (__half*)p;
    cudaGetSymbolAddress(&p, g_wh);  __half* pwh = (__half*)p;
    cudaGetSymbolAddress(&p, g_hh);  __half* phh = (__half*)p;
    cudaGetSymbolAddress(&p, g_gat); float* pgat = (float*)p;
    cudaGetSymbolAddress(&p, g_l1);  float* pl1  = (float*)p;
    cudaGetSymbolAddress(&p, g_l2);  float* pl2  = (float*)p;
    cudaGetSymbolAddress(&p, g_z);   float* pz   = (float*)p;

    // side stream + events for the CSR fork (host resources, created once;
    // identical GPU work is issued on every call)
    static cudaStream_t s2 = nullptr;
    static cudaEvent_t evFork = nullptr, evJoin = nullptr;
    static bool tried = false;
    if (!tried) {
        tried = true;
        if (cudaStreamCreateWithFlags(&s2, cudaStreamNonBlocking) != cudaSuccess) s2 = nullptr;
        if (s2) {
            if (cudaEventCreateWithFlags(&evFork, cudaEventDisableTiming) != cudaSuccess ||
                cudaEventCreateWithFlags(&evJoin, cudaEventDisableTiming) != cudaSuccess) {
                s2 = nullptr;
            }
        }
    }

    if (s2) {
        // fork: CSR bucket build depends only on edge_index
        cudaEventRecord(evFork, 0);
        cudaStreamWaitEvent(s2, evFork, 0);
        bucket_init_kernel<<<NN / 256, 256, 0, s2>>>();
        bucket_scatter_kernel<<<EE / 4 / 256, 256, 0, s2>>>(ei);
        cudaEventRecord(evJoin, s2);

        // main: convert inputs, tensor-core gemm1, attention dots
        cvt_fp16_kernel<<<(NN * FIN / 4 + 255) / 256, 256>>>(x, pxh, NN * FIN / 4);
        cvt_fp16_kernel<<<(FIN * FTOT / 4 + 255) / 256, 256>>>(W_gat, pwh, FIN * FTOT / 4);
        hgemm1_kernel<<<dim3(FTOT / 128, NN / 128), 256>>>(pxh, pwh, phh);
        attn_dots_kernel<<<NN / 2, 128>>>(att_src, att_dst);

        // join before aggregation
        cudaStreamWaitEvent(0, evJoin, 0);
    } else {
        cvt_fp16_kernel<<<(NN * FIN / 4 + 255) / 256, 256>>>(x, pxh, NN * FIN / 4);
        cvt_fp16_kernel<<<(FIN * FTOT / 4 + 255) / 256, 256>>>(W_gat, pwh, FIN * FTOT / 4);
        hgemm1_kernel<<<dim3(FTOT / 128, NN / 128), 256>>>(pxh, pwh, phh);
        attn_dots_kernel<<<NN / 2, 128>>>(att_src, att_dst);
        bucket_init_kernel<<<NN / 256, 256>>>();
        bucket_scatter_kernel<<<EE / 4 / 256, 256>>>(ei);
    }

    // segment softmax + aggregation + bias + relu
    gat_agg_kernel<<<NN, 64>>>(bias_gat);

    // fused MLP: gemm + bias + LN + ReLU (+ final projection) -- R5-measured tiling
    fused_gemm_ln_kernel<64, 128, 256, 8, false><<<NN / 64, 256>>>(
        pgat, w_a, b_a, g_a, be_a, pl1, nullptr, nullptr, nullptr);
    fused_gemm_ln_kernel<128, 64, 128, 8, false><<<NN / 128, 256>>>(
        pl1, w1, b1, g1, be1, pl2, nullptr, nullptr, nullptr);
    fused_gemm_ln_kernel<128, 32, 64, 8, true><<<NN / 128, 128>>>(
        pl2, w2, b2, g2, be2, nullptr, w3, b3, pz);

    // pairwise distance matrix
    cdist_kernel<<<dim3(NN / CD_J, NN / CD_I), 256>>>(out);
}

// round 9
// speedup vs baseline: 1.4560x; 1.1432x over previous
#include <cuda_runtime.h>
#include <cuda_fp16.h>
#include <math.h>

#define NN   8192
#define EE   524288
#define FIN  256
#define FTOT 256      // H * F_OUT
#define FOUT 128
#define CAP  256      // per-node bucket capacity (mean deg = 65, Poisson)
#define LN_EPS   1e-5f
#define NEG_SLOPE 0.2f

// ---------------- scratch (__device__ globals; no allocation allowed) ----------------
__device__ __align__(16) __half g_xh[NN * FIN];     // x in fp16
__device__ __align__(16) __half g_wh[FIN * FTOT];   // W_gat in fp16
__device__ __align__(16) __half g_w1h[256 * 128];   // w_a in fp16
__device__ __align__(16) __half g_hh[NN * FTOT];    // x @ W_gat, fp16
__device__ __align__(16) __half g_gath[NN * 256];   // GAT output (relu), fp16
__device__ __align__(16) float g_as[NN * 2];
__device__ __align__(16) float g_ad[NN * 2];
__device__ int   g_deg[NN];
__device__ int   g_srt[NN * CAP];
__device__ __align__(16) float g_l1[NN * 128];
__device__ __align__(16) float g_l2[NN * 64];
__device__ __align__(16) float g_z[NN * 3];

// ---------------- packed fp32x2 FMA ----------------
__device__ __forceinline__ void ffma2(float2& c, float a, const float2& b) {
    float2 av = make_float2(a, a);
    unsigned long long ua = *reinterpret_cast<unsigned long long*>(&av);
    unsigned long long ub = *reinterpret_cast<const unsigned long long*>(&b);
    unsigned long long uc = *reinterpret_cast<unsigned long long*>(&c);
    asm("fma.rn.f32x2 %0, %1, %2, %0;" : "+l"(uc) : "l"(ua), "l"(ub));
    c = *reinterpret_cast<float2*>(&uc);
}

// ---------------- fused fp32 -> fp16 conversion of x, W_gat, w_a ----------------
#define X4  (NN * FIN / 4)          // 131072
#define W4  (FIN * FTOT / 4)        // 16384
#define WA4 (256 * 128 / 4)         // 8192
__global__ void cvt_all_kernel(const float* __restrict__ x,
                               const float* __restrict__ W,
                               const float* __restrict__ wa) {
    int i = blockIdx.x * blockDim.x + threadIdx.x;
    const float* src; __half* dst; int j;
    if (i < X4)            { src = x;  dst = g_xh;  j = i; }
    else if (i < X4 + W4)  { src = W;  dst = g_wh;  j = i - X4; }
    else if (i < X4 + W4 + WA4) { src = wa; dst = g_w1h; j = i - X4 - W4; }
    else return;
    float4 v = ((const float4*)src)[j];
    __half2 h0 = __floats2half2_rn(v.x, v.y);
    __half2 h1 = __floats2half2_rn(v.z, v.w);
    uint2 u;
    u.x = *(unsigned*)&h0;
    u.y = *(unsigned*)&h1;
    ((uint2*)dst)[j] = u;
}

// ---------------- gemm1: fp16 HMMA, 128x128 tile, 8 warps (R8-validated) ----------------
__global__ __launch_bounds__(256) void hgemm1_kernel(
    const __half* __restrict__ Ah,
    const __half* __restrict__ Bh,
    __half* __restrict__ C) {
    __shared__ __half As[128][24];
    __shared__ __half Bs[16][136];
    __shared__ __half Cs[128][136];
    const int tid  = threadIdx.x;
    const int warp = tid >> 5;
    const int lane = tid & 31;
    const int brow = blockIdx.y * 128;
    const int bcol = blockIdx.x * 128;
    const int mw = (warp & 3) * 32;
    const int nw = (warp >> 2) * 64;

    float c[2][8][4];
#pragma unroll
    for (int mi = 0; mi < 2; mi++)
#pragma unroll
        for (int nj = 0; nj < 8; nj++)
#pragma unroll
            for (int q = 0; q < 4; q++) c[mi][nj][q] = 0.f;

    unsigned aAddr[2], bAddr[4];
#pragma unroll
    for (int mi = 0; mi < 2; mi++)
        aAddr[mi] = (unsigned)__cvta_generic_to_shared(
            &As[mw + mi * 16 + (lane & 15)][(lane >> 4) * 8]);
#pragma unroll
    for (int j = 0; j < 4; j++)
        bAddr[j] = (unsigned)__cvta_generic_to_shared(
            &Bs[lane & 15][nw + j * 16 + (lane >> 4) * 8]);

    const int ar = tid >> 1, ac = (tid & 1) * 8;
    const int br = tid >> 4, bc = (tid & 15) * 8;

    for (int k0 = 0; k0 < FIN; k0 += 16) {
        *(uint4*)&As[ar][ac] = *(const uint4*)(Ah + (size_t)(brow + ar) * FIN + k0 + ac);
        *(uint4*)&Bs[br][bc] = *(const uint4*)(Bh + (size_t)(k0 + br) * FTOT + bcol + bc);
        __syncthreads();

        unsigned a[2][4], b[4][4];
#pragma unroll
        for (int mi = 0; mi < 2; mi++)
            asm volatile("ldmatrix.sync.aligned.m8n8.x4.shared.b16 {%0,%1,%2,%3}, [%4];"
                         : "=r"(a[mi][0]), "=r"(a[mi][1]), "=r"(a[mi][2]), "=r"(a[mi][3])
                         : "r"(aAddr[mi]));
#pragma unroll
        for (int j = 0; j < 4; j++)
            asm volatile("ldmatrix.sync.aligned.m8n8.x4.trans.shared.b16 {%0,%1,%2,%3}, [%4];"
                         : "=r"(b[j][0]), "=r"(b[j][1]), "=r"(b[j][2]), "=r"(b[j][3])
                         : "r"(bAddr[j]));
#pragma unroll
        for (int mi = 0; mi < 2; mi++)
#pragma unroll
            for (int nj = 0; nj < 8; nj++) {
                const unsigned b0 = b[nj >> 1][(nj & 1) * 2];
                const unsigned b1 = b[nj >> 1][(nj & 1) * 2 + 1];
                asm volatile(
                    "mma.sync.aligned.m16n8k16.row.col.f32.f16.f16.f32 "
                    "{%0,%1,%2,%3}, {%4,%5,%6,%7}, {%8,%9}, {%0,%1,%2,%3};"
                    : "+f"(c[mi][nj][0]), "+f"(c[mi][nj][1]),
                      "+f"(c[mi][nj][2]), "+f"(c[mi][nj][3])
                    : "r"(a[mi][0]), "r"(a[mi][1]), "r"(a[mi][2]), "r"(a[mi][3]),
                      "r"(b0), "r"(b1));
            }
        __syncthreads();
    }

    const int g  = lane >> 2;
    const int tg = lane & 3;
#pragma unroll
    for (int mi = 0; mi < 2; mi++)
#pragma unroll
        for (int nj = 0; nj < 8; nj++) {
            int r0 = mw + mi * 16 + g;
            int cc = nw + nj * 8 + tg * 2;
            *(__half2*)&Cs[r0][cc]     = __floats2half2_rn(c[mi][nj][0], c[mi][nj][1]);
            *(__half2*)&Cs[r0 + 8][cc] = __floats2half2_rn(c[mi][nj][2], c[mi][nj][3]);
        }
    __syncthreads();
#pragma unroll
    for (int l = 0; l < 8; l++) {
        int idx = tid + l * 256;
        int r = idx >> 4, c8 = (idx & 15) * 8;
        *(uint4*)(C + (size_t)(brow + r) * FTOT + bcol + c8) = *(uint4*)&Cs[r][c8];
    }
}

// ---------------- layer_a: fp16 HMMA GEMM (64x128 tile) + bias + LN + ReLU -> fp32 ----------------
__global__ __launch_bounds__(256) void hgemm_ln_kernel(
    const __half* __restrict__ Ah,   // g_gath [NN][256]
    const __half* __restrict__ Bh,   // w_a fp16 [256][128]
    const float* __restrict__ bias, const float* __restrict__ gamma,
    const float* __restrict__ beta, float* __restrict__ C) {  // g_l1 [NN][128]
    __shared__ __half As[64][24];
    __shared__ __half Bs[16][136];
    __shared__ float  Cs[64][132];
    const int tid  = threadIdx.x;
    const int warp = tid >> 5;
    const int lane = tid & 31;
    const int brow = blockIdx.x * 64;
    const int mw = (warp & 3) * 16;
    const int nw = (warp >> 2) * 64;

    float c[8][4];
#pragma unroll
    for (int nj = 0; nj < 8; nj++)
#pragma unroll
        for (int q = 0; q < 4; q++) c[nj][q] = 0.f;

    unsigned aAddr = (unsigned)__cvta_generic_to_shared(
        &As[mw + (lane & 15)][(lane >> 4) * 8]);
    unsigned bAddr[4];
#pragma unroll
    for (int j = 0; j < 4; j++)
        bAddr[j] = (unsigned)__cvta_generic_to_shared(
            &Bs[lane & 15][nw + j * 16 + (lane >> 4) * 8]);

    const int ar = tid >> 1, ac = (tid & 1) * 8;   // threads 0..127 stage A
    const int br = tid >> 4, bc = (tid & 15) * 8;  // all 256 stage B

    for (int k0 = 0; k0 < 256; k0 += 16) {
        if (tid < 128)
            *(uint4*)&As[ar][ac] = *(const uint4*)(Ah + (size_t)(brow + ar) * 256 + k0 + ac);
        *(uint4*)&Bs[br][bc] = *(const uint4*)(Bh + (size_t)(k0 + br) * 128 + bc);
        __syncthreads();

        unsigned a[4], b[4][4];
        asm volatile("ldmatrix.sync.aligned.m8n8.x4.shared.b16 {%0,%1,%2,%3}, [%4];"
                     : "=r"(a[0]), "=r"(a[1]), "=r"(a[2]), "=r"(a[3]) : "r"(aAddr));
#pragma unroll
        for (int j = 0; j < 4; j++)
            asm volatile("ldmatrix.sync.aligned.m8n8.x4.trans.shared.b16 {%0,%1,%2,%3}, [%4];"
                         : "=r"(b[j][0]), "=r"(b[j][1]), "=r"(b[j][2]), "=r"(b[j][3])
                         : "r"(bAddr[j]));
#pragma unroll
        for (int nj = 0; nj < 8; nj++) {
            const unsigned b0 = b[nj >> 1][(nj & 1) * 2];
            const unsigned b1 = b[nj >> 1][(nj & 1) * 2 + 1];
            asm volatile(
                "mma.sync.aligned.m16n8k16.row.col.f32.f16.f16.f32 "
                "{%0,%1,%2,%3}, {%4,%5,%6,%7}, {%8,%9}, {%0,%1,%2,%3};"
                : "+f"(c[nj][0]), "+f"(c[nj][1]), "+f"(c[nj][2]), "+f"(c[nj][3])
                : "r"(a[0]), "r"(a[1]), "r"(a[2]), "r"(a[3]), "r"(b0), "r"(b1));
        }
        __syncthreads();
    }

    // stage fp32 accumulators
    const int g  = lane >> 2;
    const int tg = lane & 3;
#pragma unroll
    for (int nj = 0; nj < 8; nj++) {
        int r0 = mw + g;
        int cc = nw + nj * 8 + tg * 2;
        Cs[r0][cc]     = c[nj][0]; Cs[r0][cc + 1]     = c[nj][1];
        Cs[r0 + 8][cc] = c[nj][2]; Cs[r0 + 8][cc + 1] = c[nj][3];
    }
    __syncthreads();

    // LN + ReLU: warp per row, 8 rows per warp-iteration
    const int c0 = lane * 4;
    float4 bi4 = *(const float4*)(bias + c0);
    float4 g4  = *(const float4*)(gamma + c0);
    float4 be4 = *(const float4*)(beta + c0);
    for (int rr = warp; rr < 64; rr += 8) {
        float v0 = Cs[rr][c0]     + bi4.x;
        float v1 = Cs[rr][c0 + 1] + bi4.y;
        float v2 = Cs[rr][c0 + 2] + bi4.z;
        float v3 = Cs[rr][c0 + 3] + bi4.w;
        float s = v0 + v1 + v2 + v3;
#pragma unroll
        for (int o = 16; o > 0; o >>= 1) s += __shfl_xor_sync(0xffffffffu, s, o);
        float mu = s * (1.f / 128.f);
        float d0 = v0 - mu, d1 = v1 - mu, d2 = v2 - mu, d3 = v3 - mu;
        float sq = d0 * d0 + d1 * d1 + d2 * d2 + d3 * d3;
#pragma unroll
        for (int o = 16; o > 0; o >>= 1) sq += __shfl_xor_sync(0xffffffffu, sq, o);
        float inv = rsqrtf(sq * (1.f / 128.f) + LN_EPS);
        float4 y;
        y.x = fmaxf(d0 * inv * g4.x + be4.x, 0.f);
        y.y = fmaxf(d1 * inv * g4.y + be4.y, 0.f);
        y.z = fmaxf(d2 * inv * g4.z + be4.z, 0.f);
        y.w = fmaxf(d3 * inv * g4.w + be4.w, 0.f);
        *(float4*)(C + (size_t)(brow + rr) * 128 + c0) = y;
    }
}

// ---------------- attention logits from fp16 h ----------------
__global__ void attn_dots_kernel(const float* __restrict__ att_src,
                                 const float* __restrict__ att_dst) {
    int warp = threadIdx.x >> 5;
    int lane = threadIdx.x & 31;
    int n    = blockIdx.x * 2 + (warp >> 1);
    int head = warp & 1;
    uint2 hv = ((const uint2*)&g_hh[(size_t)n * FTOT + head * FOUT])[lane];
    float2 h01 = __half22float2(*(__half2*)&hv.x);
    float2 h23 = __half22float2(*(__half2*)&hv.y);
    float4 s4 = ((const float4*)att_src)[head * 32 + lane];
    float4 d4 = ((const float4*)att_dst)[head * 32 + lane];
    float ds = h01.x * s4.x + h01.y * s4.y + h23.x * s4.z + h23.y * s4.w;
    float dd = h01.x * d4.x + h01.y * d4.y + h23.x * d4.z + h23.y * d4.w;
#pragma unroll
    for (int o = 16; o > 0; o >>= 1) {
        ds += __shfl_xor_sync(0xffffffff, ds, o);
        dd += __shfl_xor_sync(0xffffffff, dd, o);
    }
    if (lane == 0) {
        g_as[n * 2 + head] = ds;
        g_ad[n * 2 + head] = dd;
    }
}

// ---------------- fused fp32 GEMM + bias + LN + ReLU [+ 32->3 proj] (small layers) ----------------
template <int BM, int N, int K, int TM, bool PROJ>
__global__ void fused_gemm_ln_kernel(
    const float* __restrict__ A, const float* __restrict__ W,
    const float* __restrict__ bias, const float* __restrict__ gamma,
    const float* __restrict__ beta, float* __restrict__ C,
    const float* __restrict__ w3, const float* __restrict__ b3,
    float* __restrict__ Z) {
    constexpr int LX = N / 4;
    constexpr int THREADS = (BM / TM) * LX;
    __shared__ float As[16][BM + 4];
    __shared__ float Ws[16][N];
    __shared__ float w3s[96];
    __shared__ float b3s[3];
    const int tid = threadIdx.x;
    const int tx  = tid % LX;
    const int ty  = tid / LX;
    const int brow = blockIdx.x * BM;

    if (PROJ) {
        for (int i = tid; i < 96; i += THREADS) w3s[i] = w3[i];
        if (tid < 3) b3s[tid] = b3[tid];
    }

    float2 acc2[TM][2];
#pragma unroll
    for (int m = 0; m < TM; m++) { acc2[m][0] = make_float2(0.f, 0.f); acc2[m][1] = make_float2(0.f, 0.f); }

    for (int k0 = 0; k0 < K; k0 += 16) {
#pragma unroll
        for (int i = tid; i < BM * 4; i += THREADS) {
            int r = i >> 2, c4 = (i & 3) * 4;
            float4 v = *(const float4*)(A + (size_t)(brow + r) * K + k0 + c4);
            As[c4 + 0][r] = v.x; As[c4 + 1][r] = v.y;
            As[c4 + 2][r] = v.z; As[c4 + 3][r] = v.w;
        }
#pragma unroll
        for (int i = tid; i < N * 4; i += THREADS) {
            int r = i / (N / 4), c4 = (i % (N / 4)) * 4;
            *(float4*)&Ws[r][c4] = *(const float4*)(W + (size_t)(k0 + r) * N + c4);
        }
        __syncthreads();
#pragma unroll
        for (int k = 0; k < 16; k++) {
            float ar[TM];
#pragma unroll
            for (int q = 0; q < TM / 4; q++)
                *(float4*)&ar[q * 4] = *(float4*)&As[k][ty * TM + q * 4];
            float4 b4 = *(float4*)&Ws[k][tx * 4];
            float2 br0 = make_float2(b4.x, b4.y);
            float2 br1 = make_float2(b4.z, b4.w);
#pragma unroll
            for (int m = 0; m < TM; m++) {
                ffma2(acc2[m][0], ar[m], br0);
                ffma2(acc2[m][1], ar[m], br1);
            }
        }
        __syncthreads();
    }

    const int c0 = tx * 4;
    float4 bi4 = *(const float4*)(bias + c0);
    float4 g4  = *(const float4*)(gamma + c0);
    float4 be4 = *(const float4*)(beta + c0);

#pragma unroll
    for (int m = 0; m < TM; m++) {
        float v0 = acc2[m][0].x + bi4.x;
        float v1 = acc2[m][0].y + bi4.y;
        float v2 = acc2[m][1].x + bi4.z;
        float v3 = acc2[m][1].y + bi4.w;
        float s = v0 + v1 + v2 + v3;
#pragma unroll
        for (int o = LX >> 1; o > 0; o >>= 1) s += __shfl_xor_sync(0xffffffffu, s, o);
        float mu = s * (1.f / N);
        float d0 = v0 - mu, d1 = v1 - mu, d2 = v2 - mu, d3 = v3 - mu;
        float sq = d0 * d0 + d1 * d1 + d2 * d2 + d3 * d3;
#pragma unroll
        for (int o = LX >> 1; o > 0; o >>= 1) sq += __shfl_xor_sync(0xffffffffu, sq, o);
        float inv = rsqrtf(sq * (1.f / N) + LN_EPS);
        float y0 = fmaxf(d0 * inv * g4.x + be4.x, 0.f);
        float y1 = fmaxf(d1 * inv * g4.y + be4.y, 0.f);
        float y2 = fmaxf(d2 * inv * g4.z + be4.z, 0.f);
        float y3 = fmaxf(d3 * inv * g4.w + be4.w, 0.f);
        int row = brow + ty * TM + m;
        if (!PROJ) {
            float4 v; v.x = y0; v.y = y1; v.z = y2; v.w = y3;
            *(float4*)(C + (size_t)row * N + c0) = v;
        } else {
            float p0 = y0 * w3s[(c0 + 0) * 3 + 0] + y1 * w3s[(c0 + 1) * 3 + 0] +
                       y2 * w3s[(c0 + 2) * 3 + 0] + y3 * w3s[(c0 + 3) * 3 + 0];
            float p1 = y0 * w3s[(c0 + 0) * 3 + 1] + y1 * w3s[(c0 + 1) * 3 + 1] +
                       y2 * w3s[(c0 + 2) * 3 + 1] + y3 * w3s[(c0 + 3) * 3 + 1];
            float p2 = y0 * w3s[(c0 + 0) * 3 + 2] + y1 * w3s[(c0 + 1) * 3 + 2] +
                       y2 * w3s[(c0 + 2) * 3 + 2] + y3 * w3s[(c0 + 3) * 3 + 2];
#pragma unroll
            for (int o = LX >> 1; o > 0; o >>= 1) {
                p0 += __shfl_xor_sync(0xffffffffu, p0, o);
                p1 += __shfl_xor_sync(0xffffffffu, p1, o);
                p2 += __shfl_xor_sync(0xffffffffu, p2, o);
            }
            if (tx == 0) {
                Z[row * 3 + 0] = p0 + b3s[0];
                Z[row * 3 + 1] = p1 + b3s[1];
                Z[row * 3 + 2] = p2 + b3s[2];
            }
        }
    }
}

// ---------------- bucket CSR ----------------
__global__ void bucket_init_kernel() {
    int i = blockIdx.x * blockDim.x + threadIdx.x;
    if (i < NN) {
        g_deg[i] = 1;
        g_srt[i * CAP] = i;
    }
}

__global__ void bucket_scatter_kernel(const int* __restrict__ ei) {
    int id = blockIdx.x * blockDim.x + threadIdx.x;
    if (id >= EE / 4) return;
    int4 s = *(const int4*)&ei[id * 4];
    int4 d = *(const int4*)&ei[EE + id * 4];
    int p;
    p = atomicAdd(&g_deg[d.x], 1); if (p < CAP) g_srt[d.x * CAP + p] = s.x;
    p = atomicAdd(&g_deg[d.y], 1); if (p < CAP) g_srt[d.y * CAP + p] = s.y;
    p = atomicAdd(&g_deg[d.z], 1); if (p < CAP) g_srt[d.z * CAP + p] = s.z;
    p = atomicAdd(&g_deg[d.w], 1); if (p < CAP) g_srt[d.w * CAP + p] = s.w;
}

// ---------------- GAT softmax + aggregation (fp16 h in, fp16 out) ----------------
__global__ __launch_bounds__(64) void gat_agg_kernel(const float* __restrict__ bias) {
    const int dst = blockIdx.x;
    const int tid = threadIdx.x;
    const int start = dst * CAP;
    const int deg   = min(g_deg[dst], CAP);
    const float ad0 = g_ad[dst * 2], ad1 = g_ad[dst * 2 + 1];

    __shared__ int   sh_s[CAP];
    __shared__ float sh_w0[CAP];
    __shared__ float sh_w1[CAP];
    __shared__ float rsum[4];

    float s0 = 0.f, s1 = 0.f;
    for (int i = tid; i < deg; i += 64) {
        int s = g_srt[start + i];
        float2 av = ((const float2*)g_as)[s];
        float e0 = av.x + ad0; e0 = e0 > 0.f ? e0 : NEG_SLOPE * e0;
        float e1 = av.y + ad1; e1 = e1 > 0.f ? e1 : NEG_SLOPE * e1;
        float w0 = __expf(e0);
        float w1 = __expf(e1);
        sh_s[i]  = s;
        sh_w0[i] = w0;
        sh_w1[i] = w1;
        s0 += w0; s1 += w1;
    }
    __syncthreads();

    const int c0 = 4 * tid;
    const float* shw = (tid >= 32) ? sh_w1 : sh_w0;
    float2 accA = make_float2(0.f, 0.f);
    float2 accB = make_float2(0.f, 0.f);
    const __half* hbase = &g_hh[c0];

#pragma unroll 8
    for (int i = 0; i < deg; i++) {
        float w = shw[i];
        uint2 v = *(const uint2*)(hbase + (size_t)sh_s[i] * FTOT);
        float2 f01 = __half22float2(*(__half2*)&v.x);
        float2 f23 = __half22float2(*(__half2*)&v.y);
        ffma2(accA, w, f01);
        ffma2(accB, w, f23);
    }

#pragma unroll
    for (int o = 16; o > 0; o >>= 1) {
        s0 += __shfl_xor_sync(0xffffffffu, s0, o);
        s1 += __shfl_xor_sync(0xffffffffu, s1, o);
    }
    if ((tid & 31) == 0) { rsum[(tid >> 5) * 2] = s0; rsum[(tid >> 5) * 2 + 1] = s1; }
    __syncthreads();
    float t0 = rsum[0] + rsum[2];
    float t1 = rsum[1] + rsum[3];
    float inv = (tid >= 32) ? (1.f / (t1 + 1e-16f)) : (1.f / (t0 + 1e-16f));

    float4 bi = *(const float4*)(bias + c0);
    float o0 = fmaxf(accA.x * inv + bi.x, 0.f);
    float o1 = fmaxf(accA.y * inv + bi.y, 0.f);
    float o2 = fmaxf(accB.x * inv + bi.z, 0.f);
    float o3 = fmaxf(accB.y * inv + bi.w, 0.f);
    __half2 h0 = __floats2half2_rn(o0, o1);
    __half2 h1 = __floats2half2_rn(o2, o3);
    uint2 u;
    u.x = *(unsigned*)&h0;
    u.y = *(unsigned*)&h1;
    *(uint2*)&g_gath[(size_t)dst * 256 + c0] = u;
}

// ---------------- pairwise distances, streaming stores, MUFU sqrt ----------------
#define CD_I 64
#define CD_J 1024
__global__ __launch_bounds__(256) void cdist_kernel(float* __restrict__ out) {
    __shared__ float zi[CD_I * 3];
    int ibase = blockIdx.y * CD_I;
    int jbase = blockIdx.x * CD_J;
    for (int t = threadIdx.x; t < CD_I * 3; t += 256) zi[t] = g_z[ibase * 3 + t];

    int j0 = jbase + threadIdx.x * 4;
    float4 p0 = *(const float4*)(g_z + (size_t)j0 * 3);
    float4 p1 = *(const float4*)(g_z + (size_t)j0 * 3 + 4);
    float4 p2 = *(const float4*)(g_z + (size_t)j0 * 3 + 8);
    float jx[4] = {p0.x, p0.w, p1.z, p2.y};
    float jy[4] = {p0.y, p1.x, p1.w, p2.z};
    float jz[4] = {p0.z, p1.y, p2.x, p2.w};
    __syncthreads();

#pragma unroll 4
    for (int ii = 0; ii < CD_I; ii++) {
        float zx = zi[ii * 3], zy = zi[ii * 3 + 1], zz = zi[ii * 3 + 2];
        float r[4];
#pragma unroll
        for (int t = 0; t < 4; t++) {
            float dx = zx - jx[t];
            float dy = zy - jy[t];
            float dz = zz - jz[t];
            float d2 = dx * dx + dy * dy + dz * dz;
            r[t] = d2 > 0.f ? d2 * rsqrtf(d2) : 0.f;   // single MUFU.RSQ
        }
        float* ptr = out + (size_t)(ibase + ii) * NN + j0;
        asm volatile("st.global.cs.v4.f32 [%0], {%1, %2, %3, %4};"
                     :: "l"(ptr), "f"(r[0]), "f"(r[1]), "f"(r[2]), "f"(r[3])
                     : "memory");
    }
}

// ---------------- host launcher ----------------
extern "C" void kernel_launch(void* const* d_in, const int* in_sizes, int n_in,
                              void* d_out, int out_size) {
    const float* x        = (const float*)d_in[0];
    const int*   ei       = (const int*)  d_in[1];
    const float* W_gat    = (const float*)d_in[2];
    const float* att_src  = (const float*)d_in[3];
    const float* att_dst  = (const float*)d_in[4];
    const float* bias_gat = (const float*)d_in[5];
    const float* w_a  = (const float*)d_in[6];
    const float* b_a  = (const float*)d_in[7];
    const float* g_a  = (const float*)d_in[8];
    const float* be_a = (const float*)d_in[9];
    const float* w1   = (const float*)d_in[10];
    const float* b1   = (const float*)d_in[11];
    const float* g1   = (const float*)d_in[12];
    const float* be1  = (const float*)d_in[13];
    const float* w2   = (const float*)d_in[14];
    const float* b2   = (const float*)d_in[15];
    const float* g2   = (const float*)d_in[16];
    const float* be2  = (const float*)d_in[17];
    const float* w3   = (const float*)d_in[18];
    const float* b3   = (const float*)d_in[19];
    float* out = (float*)d_out;

    void* p;
    cudaGetSymbolAddress(&p, g_xh);   __half* pxh  = (__half*)p;
    cudaGetSymbolAddress(&p, g_wh);   __half* pwh  = (__half*)p;
    cudaGetSymbolAddress(&p, g_w1h);  __half* pw1h = (__half*)p;
    cudaGetSymbolAddress(&p, g_hh);   __half* phh  = (__half*)p;
    cudaGetSymbolAddress(&p, g_gath); __half* pgath= (__half*)p;
    cudaGetSymbolAddress(&p, g_l1);   float* pl1   = (float*)p;
    cudaGetSymbolAddress(&p, g_l2);   float* pl2   = (float*)p;
    cudaGetSymbolAddress(&p, g_z);    float* pz    = (float*)p;

    static cudaStream_t s2 = nullptr;
    static cudaEvent_t evFork = nullptr, evJoin = nullptr;
    static bool tried = false;
    if (!tried) {
        tried = true;
        if (cudaStreamCreateWithFlags(&s2, cudaStreamNonBlocking) != cudaSuccess) s2 = nullptr;
        if (s2) {
            if (cudaEventCreateWithFlags(&evFork, cudaEventDisableTiming) != cudaSuccess ||
                cudaEventCreateWithFlags(&evJoin, cudaEventDisableTiming) != cudaSuccess) {
                s2 = nullptr;
            }
        }
    }

    const int CVT_TOT = X4 + W4 + WA4;
    if (s2) {
        cudaEventRecord(evFork, 0);
        cudaStreamWaitEvent(s2, evFork, 0);
        bucket_init_kernel<<<NN / 256, 256, 0, s2>>>();
        bucket_scatter_kernel<<<EE / 4 / 256, 256, 0, s2>>>(ei);
        cudaEventRecord(evJoin, s2);

        cvt_all_kernel<<<(CVT_TOT + 255) / 256, 256>>>(x, W_gat, w_a);
        hgemm1_kernel<<<dim3(FTOT / 128, NN / 128), 256>>>(pxh, pwh, phh);
        attn_dots_kernel<<<NN / 2, 128>>>(att_src, att_dst);

        cudaStreamWaitEvent(0, evJoin, 0);
    } else {
        cvt_all_kernel<<<(CVT_TOT + 255) / 256, 256>>>(x, W_gat, w_a);
        hgemm1_kernel<<<dim3(FTOT / 128, NN / 128), 256>>>(pxh, pwh, phh);
        attn_dots_kernel<<<NN / 2, 128>>>(att_src, att_dst);
        bucket_init_kernel<<<NN / 256, 256>>>();
        bucket_scatter_kernel<<<EE / 4 / 256, 256>>>(ei);
    }

    // segment softmax + aggregation + bias + relu -> fp16
    gat_agg_kernel<<<NN, 64>>>(bias_gat);

    // layer_a: HMMA gemm + bias + LN + ReLU
    hgemm_ln_kernel<<<NN / 64, 256>>>(pgath, pw1h, b_a, g_a, be_a, pl1);

    // remaining MLP (fp32 FFMA2) + final projection
    fused_gemm_ln_kernel<128, 64, 128, 8, false><<<NN / 128, 256>>>(
        pl1, w1, b1, g1, be1, pl2, nullptr, nullptr, nullptr);
    fused_gemm_ln_kernel<128, 32, 64, 8, true><<<NN / 128, 128>>>(
        pl2, w2, b2, g2, be2, nullptr, w3, b3, pz);

    // pairwise distance matrix
    cdist_kernel<<<dim3(NN / CD_J, NN / CD_I), 256>>>(out);
}

// round 10
// speedup vs baseline: 1.4644x; 1.0057x over previous
#include <cuda_runtime.h>
#include <cuda_fp16.h>
#include <math.h>

#define NN   8192
#define EE   524288
#define FIN  256
#define FTOT 256      // H * F_OUT
#define FOUT 128
#define CAP  256      // per-node bucket capacity (mean deg = 65, Poisson)
#define LN_EPS   1e-5f
#define NEG_SLOPE 0.2f

// ---------------- scratch (__device__ globals; no allocation allowed) ----------------
__device__ __align__(16) __half g_xh[NN * FIN];     // x in fp16
__device__ __align__(16) __half g_wh[FIN * FTOT];   // W_gat in fp16
__device__ __align__(16) __half g_w1h[256 * 128];   // w_a in fp16
__device__ __align__(16) __half g_hh[NN * FTOT];    // x @ W_gat, fp16
__device__ __align__(16) __half g_gath[NN * 256];   // GAT output (relu), fp16
__device__ __align__(16) float g_as[NN * 2];
__device__ __align__(16) float g_ad[NN * 2];
__device__ int   g_deg[NN];
__device__ int   g_srt[NN * CAP];
__device__ __align__(16) float g_l1[NN * 128];
__device__ __align__(16) float g_l2[NN * 64];
__device__ __align__(16) float g_z[NN * 3];

// ---------------- packed fp32x2 FMA ----------------
__device__ __forceinline__ void ffma2(float2& c, float a, const float2& b) {
    float2 av = make_float2(a, a);
    unsigned long long ua = *reinterpret_cast<unsigned long long*>(&av);
    unsigned long long ub = *reinterpret_cast<const unsigned long long*>(&b);
    unsigned long long uc = *reinterpret_cast<unsigned long long*>(&c);
    asm("fma.rn.f32x2 %0, %1, %2, %0;" : "+l"(uc) : "l"(ua), "l"(ub));
    c = *reinterpret_cast<float2*>(&uc);
}

__device__ __forceinline__ void cp_async16(unsigned smem_dst, const void* gmem_src) {
    asm volatile("cp.async.cg.shared.global [%0], [%1], 16;" :: "r"(smem_dst), "l"(gmem_src));
}

// ---------------- fused fp32 -> fp16 conversion of x, W_gat, w_a ----------------
#define X4  (NN * FIN / 4)          // 131072
#define W4  (FIN * FTOT / 4)        // 16384
#define WA4 (256 * 128 / 4)         // 8192
__global__ void cvt_all_kernel(const float* __restrict__ x,
                               const float* __restrict__ W,
                               const float* __restrict__ wa) {
    int i = blockIdx.x * blockDim.x + threadIdx.x;
    const float* src; __half* dst; int j;
    if (i < X4)            { src = x;  dst = g_xh;  j = i; }
    else if (i < X4 + W4)  { src = W;  dst = g_wh;  j = i - X4; }
    else if (i < X4 + W4 + WA4) { src = wa; dst = g_w1h; j = i - X4 - W4; }
    else return;
    float4 v = ((const float4*)src)[j];
    __half2 h0 = __floats2half2_rn(v.x, v.y);
    __half2 h1 = __floats2half2_rn(v.z, v.w);
    uint2 u;
    u.x = *(unsigned*)&h0;
    u.y = *(unsigned*)&h1;
    ((uint2*)dst)[j] = u;
}

// ---------------- gemm1: fp16 HMMA, 128x128 tile, BK=32, cp.async double-buffered ----------------
#define A_LDS 40   // 32 + 8 pad halfs (80B rows, 16B-aligned)
#define B_LDS 136  // 128 + 8 pad halfs (272B rows)
__global__ __launch_bounds__(256) void hgemm1_kernel(
    const __half* __restrict__ Ah,
    const __half* __restrict__ Bh,
    __half* __restrict__ C) {
    // overlay: [As(2 stages) | Bs(2 stages)] reused as Cs in the epilogue
    __shared__ __align__(16) char smem_raw[2 * 128 * A_LDS * 2 + 2 * 32 * B_LDS * 2];
    __half* As_base = (__half*)smem_raw;                   // stage s: As_base + s*128*A_LDS
    __half* Bs_base = As_base + 2 * 128 * A_LDS;           // stage s: Bs_base + s*32*B_LDS
    __half (*Cs)[B_LDS] = (__half(*)[B_LDS])smem_raw;      // epilogue overlay [128][136]

    const int tid  = threadIdx.x;
    const int warp = tid >> 5;
    const int lane = tid & 31;
    const int brow = blockIdx.y * 128;
    const int bcol = blockIdx.x * 128;
    const int mw = (warp & 3) * 32;
    const int nw = (warp >> 2) * 64;

    float c[2][8][4];
#pragma unroll
    for (int mi = 0; mi < 2; mi++)
#pragma unroll
        for (int nj = 0; nj < 8; nj++)
#pragma unroll
            for (int q = 0; q < 4; q++) c[mi][nj][q] = 0.f;

    // ldmatrix base addresses per stage (ksub adds 32B on A, 16 rows = 16*B_LDS*2 B on B)
    unsigned aAddr[2][2], bAddr[2][4];
#pragma unroll
    for (int st = 0; st < 2; st++) {
#pragma unroll
        for (int mi = 0; mi < 2; mi++)
            aAddr[st][mi] = (unsigned)__cvta_generic_to_shared(
                As_base + st * 128 * A_LDS + (mw + mi * 16 + (lane & 15)) * A_LDS + (lane >> 4) * 8);
#pragma unroll
        for (int j = 0; j < 4; j++)
            bAddr[st][j] = (unsigned)__cvta_generic_to_shared(
                Bs_base + st * 32 * B_LDS + (lane & 15) * B_LDS + nw + j * 16 + (lane >> 4) * 8);
    }

    // staging indices: A tile 128x32 (4 chunks/row), B tile 32x128 (16 chunks/row); 2 chunks/thread each
    const int arA = tid >> 2, acA = (tid & 3) * 8;
    const int brB = tid >> 4, bcB = (tid & 15) * 8;

    auto stage = [&](int kt, int st) {
        __half* Ad = As_base + st * 128 * A_LDS;
        __half* Bd = Bs_base + st * 32 * B_LDS;
        int k0 = kt * 32;
#pragma unroll
        for (int l = 0; l < 2; l++) {
            int r = arA + l * 64;
            cp_async16((unsigned)__cvta_generic_to_shared(Ad + r * A_LDS + acA),
                       Ah + (size_t)(brow + r) * FIN + k0 + acA);
        }
#pragma unroll
        for (int l = 0; l < 2; l++) {
            int r = brB + l * 16;
            cp_async16((unsigned)__cvta_generic_to_shared(Bd + r * B_LDS + bcB),
                       Bh + (size_t)(k0 + r) * FTOT + bcol + bcB);
        }
    };

    stage(0, 0);
    asm volatile("cp.async.commit_group;");

#pragma unroll
    for (int it = 0; it < 8; it++) {
        const int cur = it & 1;
        if (it < 7) {
            stage(it + 1, cur ^ 1);
            asm volatile("cp.async.commit_group;");
            asm volatile("cp.async.wait_group 1;");
        } else {
            asm volatile("cp.async.wait_group 0;");
        }
        __syncthreads();
#pragma unroll
        for (int ks = 0; ks < 2; ks++) {
            unsigned a[2][4], b[4][4];
#pragma unroll
            for (int mi = 0; mi < 2; mi++)
                asm volatile("ldmatrix.sync.aligned.m8n8.x4.shared.b16 {%0,%1,%2,%3}, [%4];"
                             : "=r"(a[mi][0]), "=r"(a[mi][1]), "=r"(a[mi][2]), "=r"(a[mi][3])
                             : "r"(aAddr[cur][mi] + ks * 32));
#pragma unroll
            for (int j = 0; j < 4; j++)
                asm volatile("ldmatrix.sync.aligned.m8n8.x4.trans.shared.b16 {%0,%1,%2,%3}, [%4];"
                             : "=r"(b[j][0]), "=r"(b[j][1]), "=r"(b[j][2]), "=r"(b[j][3])
                             : "r"(bAddr[cur][j] + ks * 16 * B_LDS * 2));
#pragma unroll
            for (int mi = 0; mi < 2; mi++)
#pragma unroll
                for (int nj = 0; nj < 8; nj++) {
                    const unsigned b0 = b[nj >> 1][(nj & 1) * 2];
                    const unsigned b1 = b[nj >> 1][(nj & 1) * 2 + 1];
                    asm volatile(
                        "mma.sync.aligned.m16n8k16.row.col.f32.f16.f16.f32 "
                        "{%0,%1,%2,%3}, {%4,%5,%6,%7}, {%8,%9}, {%0,%1,%2,%3};"
                        : "+f"(c[mi][nj][0]), "+f"(c[mi][nj][1]),
                          "+f"(c[mi][nj][2]), "+f"(c[mi][nj][3])
                        : "r"(a[mi][0]), "r"(a[mi][1]), "r"(a[mi][2]), "r"(a[mi][3]),
                          "r"(b0), "r"(b1));
                }
        }
        __syncthreads();
    }

    // epilogue: overlay Cs on As/Bs (loop's trailing barrier protects the reuse)
    const int g  = lane >> 2;
    const int tg = lane & 3;
#pragma unroll
    for (int mi = 0; mi < 2; mi++)
#pragma unroll
        for (int nj = 0; nj < 8; nj++) {
            int r0 = mw + mi * 16 + g;
            int cc = nw + nj * 8 + tg * 2;
            *(__half2*)&Cs[r0][cc]     = __floats2half2_rn(c[mi][nj][0], c[mi][nj][1]);
            *(__half2*)&Cs[r0 + 8][cc] = __floats2half2_rn(c[mi][nj][2], c[mi][nj][3]);
        }
    __syncthreads();
#pragma unroll
    for (int l = 0; l < 8; l++) {
        int idx = tid + l * 256;
        int r = idx >> 4, c8 = (idx & 15) * 8;
        *(uint4*)(C + (size_t)(brow + r) * FTOT + bcol + c8) = *(uint4*)&Cs[r][c8];
    }
}

// ---------------- layer_a: fp16 HMMA GEMM (64x128 tile) + bias + LN + ReLU -> fp32 ----------------
__global__ __launch_bounds__(256) void hgemm_ln_kernel(
    const __half* __restrict__ Ah,   // g_gath [NN][256]
    const __half* __restrict__ Bh,   // w_a fp16 [256][128]
    const float* __restrict__ bias, const float* __restrict__ gamma,
    const float* __restrict__ beta, float* __restrict__ C) {  // g_l1 [NN][128]
    __shared__ __half As[64][24];
    __shared__ __half Bs[16][136];
    __shared__ float  Cs[64][132];
    const int tid  = threadIdx.x;
    const int warp = tid >> 5;
    const int lane = tid & 31;
    const int brow = blockIdx.x * 64;
    const int mw = (warp & 3) * 16;
    const int nw = (warp >> 2) * 64;

    float c[8][4];
#pragma unroll
    for (int nj = 0; nj < 8; nj++)
#pragma unroll
        for (int q = 0; q < 4; q++) c[nj][q] = 0.f;

    unsigned aAddr = (unsigned)__cvta_generic_to_shared(
        &As[mw + (lane & 15)][(lane >> 4) * 8]);
    unsigned bAddr[4];
#pragma unroll
    for (int j = 0; j < 4; j++)
        bAddr[j] = (unsigned)__cvta_generic_to_shared(
            &Bs[lane & 15][nw + j * 16 + (lane >> 4) * 8]);

    const int ar = tid >> 1, ac = (tid & 1) * 8;
    const int br = tid >> 4, bc = (tid & 15) * 8;

    for (int k0 = 0; k0 < 256; k0 += 16) {
        if (tid < 128)
            *(uint4*)&As[ar][ac] = *(const uint4*)(Ah + (size_t)(brow + ar) * 256 + k0 + ac);
        *(uint4*)&Bs[br][bc] = *(const uint4*)(Bh + (size_t)(k0 + br) * 128 + bc);
        __syncthreads();

        unsigned a[4], b[4][4];
        asm volatile("ldmatrix.sync.aligned.m8n8.x4.shared.b16 {%0,%1,%2,%3}, [%4];"
                     : "=r"(a[0]), "=r"(a[1]), "=r"(a[2]), "=r"(a[3]) : "r"(aAddr));
#pragma unroll
        for (int j = 0; j < 4; j++)
            asm volatile("ldmatrix.sync.aligned.m8n8.x4.trans.shared.b16 {%0,%1,%2,%3}, [%4];"
                         : "=r"(b[j][0]), "=r"(b[j][1]), "=r"(b[j][2]), "=r"(b[j][3])
                         : "r"(bAddr[j]));
#pragma unroll
        for (int nj = 0; nj < 8; nj++) {
            const unsigned b0 = b[nj >> 1][(nj & 1) * 2];
            const unsigned b1 = b[nj >> 1][(nj & 1) * 2 + 1];
            asm volatile(
                "mma.sync.aligned.m16n8k16.row.col.f32.f16.f16.f32 "
                "{%0,%1,%2,%3}, {%4,%5,%6,%7}, {%8,%9}, {%0,%1,%2,%3};"
                : "+f"(c[nj][0]), "+f"(c[nj][1]), "+f"(c[nj][2]), "+f"(c[nj][3])
                : "r"(a[0]), "r"(a[1]), "r"(a[2]), "r"(a[3]), "r"(b0), "r"(b1));
        }
        __syncthreads();
    }

    const int g  = lane >> 2;
    const int tg = lane & 3;
#pragma unroll
    for (int nj = 0; nj < 8; nj++) {
        int r0 = mw + g;
        int cc = nw + nj * 8 + tg * 2;
        Cs[r0][cc]     = c[nj][0]; Cs[r0][cc + 1]     = c[nj][1];
        Cs[r0 + 8][cc] = c[nj][2]; Cs[r0 + 8][cc + 1] = c[nj][3];
    }
    __syncthreads();

    const int c0 = lane * 4;
    float4 bi4 = *(const float4*)(bias + c0);
    float4 g4  = *(const float4*)(gamma + c0);
    float4 be4 = *(const float4*)(beta + c0);
    for (int rr = warp; rr < 64; rr += 8) {
        float v0 = Cs[rr][c0]     + bi4.x;
        float v1 = Cs[rr][c0 + 1] + bi4.y;
        float v2 = Cs[rr][c0 + 2] + bi4.z;
        float v3 = Cs[rr][c0 + 3] + bi4.w;
        float s = v0 + v1 + v2 + v3;
#pragma unroll
        for (int o = 16; o > 0; o >>= 1) s += __shfl_xor_sync(0xffffffffu, s, o);
        float mu = s * (1.f / 128.f);
        float d0 = v0 - mu, d1 = v1 - mu, d2 = v2 - mu, d3 = v3 - mu;
        float sq = d0 * d0 + d1 * d1 + d2 * d2 + d3 * d3;
#pragma unroll
        for (int o = 16; o > 0; o >>= 1) sq += __shfl_xor_sync(0xffffffffu, sq, o);
        float inv = rsqrtf(sq * (1.f / 128.f) + LN_EPS);
        float4 y;
        y.x = fmaxf(d0 * inv * g4.x + be4.x, 0.f);
        y.y = fmaxf(d1 * inv * g4.y + be4.y, 0.f);
        y.z = fmaxf(d2 * inv * g4.z + be4.z, 0.f);
        y.w = fmaxf(d3 * inv * g4.w + be4.w, 0.f);
        *(float4*)(C + (size_t)(brow + rr) * 128 + c0) = y;
    }
}

// ---------------- attention logits from fp16 h ----------------
__global__ void attn_dots_kernel(const float* __restrict__ att_src,
                                 const float* __restrict__ att_dst) {
    int warp = threadIdx.x >> 5;
    int lane = threadIdx.x & 31;
    int n    = blockIdx.x * 2 + (warp >> 1);
    int head = warp & 1;
    uint2 hv = ((const uint2*)&g_hh[(size_t)n * FTOT + head * FOUT])[lane];
    float2 h01 = __half22float2(*(__half2*)&hv.x);
    float2 h23 = __half22float2(*(__half2*)&hv.y);
    float4 s4 = ((const float4*)att_src)[head * 32 + lane];
    float4 d4 = ((const float4*)att_dst)[head * 32 + lane];
    float ds = h01.x * s4.x + h01.y * s4.y + h23.x * s4.z + h23.y * s4.w;
    float dd = h01.x * d4.x + h01.y * d4.y + h23.x * d4.z + h23.y * d4.w;
#pragma unroll
    for (int o = 16; o > 0; o >>= 1) {
        ds += __shfl_xor_sync(0xffffffff, ds, o);
        dd += __shfl_xor_sync(0xffffffff, dd, o);
    }
    if (lane == 0) {
        g_as[n * 2 + head] = ds;
        g_ad[n * 2 + head] = dd;
    }
}

// ---------------- fused fp32 GEMM + bias + LN + ReLU [+ 32->3 proj] (small layers) ----------------
template <int BM, int N, int K, int TM, bool PROJ>
__global__ void fused_gemm_ln_kernel(
    const float* __restrict__ A, const float* __restrict__ W,
    const float* __restrict__ bias, const float* __restrict__ gamma,
    const float* __restrict__ beta, float* __restrict__ C,
    const float* __restrict__ w3, const float* __restrict__ b3,
    float* __restrict__ Z) {
    constexpr int LX = N / 4;
    constexpr int THREADS = (BM / TM) * LX;
    __shared__ float As[16][BM + 4];
    __shared__ float Ws[16][N];
    __shared__ float w3s[96];
    __shared__ float b3s[3];
    const int tid = threadIdx.x;
    const int tx  = tid % LX;
    const int ty  = tid / LX;
    const int brow = blockIdx.x * BM;

    if (PROJ) {
        for (int i = tid; i < 96; i += THREADS) w3s[i] = w3[i];
        if (tid < 3) b3s[tid] = b3[tid];
    }

    float2 acc2[TM][2];
#pragma unroll
    for (int m = 0; m < TM; m++) { acc2[m][0] = make_float2(0.f, 0.f); acc2[m][1] = make_float2(0.f, 0.f); }

    for (int k0 = 0; k0 < K; k0 += 16) {
#pragma unroll
        for (int i = tid; i < BM * 4; i += THREADS) {
            int r = i >> 2, c4 = (i & 3) * 4;
            float4 v = *(const float4*)(A + (size_t)(brow + r) * K + k0 + c4);
            As[c4 + 0][r] = v.x; As[c4 + 1][r] = v.y;
            As[c4 + 2][r] = v.z; As[c4 + 3][r] = v.w;
        }
#pragma unroll
        for (int i = tid; i < N * 4; i += THREADS) {
            int r = i / (N / 4), c4 = (i % (N / 4)) * 4;
            *(float4*)&Ws[r][c4] = *(const float4*)(W + (size_t)(k0 + r) * N + c4);
        }
        __syncthreads();
#pragma unroll
        for (int k = 0; k < 16; k++) {
            float ar[TM];
#pragma unroll
            for (int q = 0; q < TM / 4; q++)
                *(float4*)&ar[q * 4] = *(float4*)&As[k][ty * TM + q * 4];
            float4 b4 = *(float4*)&Ws[k][tx * 4];
            float2 br0 = make_float2(b4.x, b4.y);
            float2 br1 = make_float2(b4.z, b4.w);
#pragma unroll
            for (int m = 0; m < TM; m++) {
                ffma2(acc2[m][0], ar[m], br0);
                ffma2(acc2[m][1], ar[m], br1);
            }
        }
        __syncthreads();
    }

    const int c0 = tx * 4;
    float4 bi4 = *(const float4*)(bias + c0);
    float4 g4  = *(const float4*)(gamma + c0);
    float4 be4 = *(const float4*)(beta + c0);

#pragma unroll
    for (int m = 0; m < TM; m++) {
        float v0 = acc2[m][0].x + bi4.x;
        float v1 = acc2[m][0].y + bi4.y;
        float v2 = acc2[m][1].x + bi4.z;
        float v3 = acc2[m][1].y + bi4.w;
        float s = v0 + v1 + v2 + v3;
#pragma unroll
        for (int o = LX >> 1; o > 0; o >>= 1) s += __shfl_xor_sync(0xffffffffu, s, o);
        float mu = s * (1.f / N);
        float d0 = v0 - mu, d1 = v1 - mu, d2 = v2 - mu, d3 = v3 - mu;
        float sq = d0 * d0 + d1 * d1 + d2 * d2 + d3 * d3;
#pragma unroll
        for (int o = LX >> 1; o > 0; o >>= 1) sq += __shfl_xor_sync(0xffffffffu, sq, o);
        float inv = rsqrtf(sq * (1.f / N) + LN_EPS);
        float y0 = fmaxf(d0 * inv * g4.x + be4.x, 0.f);
        float y1 = fmaxf(d1 * inv * g4.y + be4.y, 0.f);
        float y2 = fmaxf(d2 * inv * g4.z + be4.z, 0.f);
        float y3 = fmaxf(d3 * inv * g4.w + be4.w, 0.f);
        int row = brow + ty * TM + m;
        if (!PROJ) {
            float4 v; v.x = y0; v.y = y1; v.z = y2; v.w = y3;
            *(float4*)(C + (size_t)row * N + c0) = v;
        } else {
            float p0 = y0 * w3s[(c0 + 0) * 3 + 0] + y1 * w3s[(c0 + 1) * 3 + 0] +
                       y2 * w3s[(c0 + 2) * 3 + 0] + y3 * w3s[(c0 + 3) * 3 + 0];
            float p1 = y0 * w3s[(c0 + 0) * 3 + 1] + y1 * w3s[(c0 + 1) * 3 + 1] +
                       y2 * w3s[(c0 + 2) * 3 + 1] + y3 * w3s[(c0 + 3) * 3 + 1];
            float p2 = y0 * w3s[(c0 + 0) * 3 + 2] + y1 * w3s[(c0 + 1) * 3 + 2] +
                       y2 * w3s[(c0 + 2) * 3 + 2] + y3 * w3s[(c0 + 3) * 3 + 2];
#pragma unroll
            for (int o = LX >> 1; o > 0; o >>= 1) {
                p0 += __shfl_xor_sync(0xffffffffu, p0, o);
                p1 += __shfl_xor_sync(0xffffffffu, p1, o);
                p2 += __shfl_xor_sync(0xffffffffu, p2, o);
            }
            if (tx == 0) {
                Z[row * 3 + 0] = p0 + b3s[0];
                Z[row * 3 + 1] = p1 + b3s[1];
                Z[row * 3 + 2] = p2 + b3s[2];
            }
        }
    }
}

// ---------------- bucket CSR ----------------
__global__ void bucket_init_kernel() {
    int i = blockIdx.x * blockDim.x + threadIdx.x;
    if (i < NN) {
        g_deg[i] = 1;
        g_srt[i * CAP] = i;
    }
}

__global__ void bucket_scatter_kernel(const int* __restrict__ ei) {
    int id = blockIdx.x * blockDim.x + threadIdx.x;
    if (id >= EE / 4) return;
    int4 s = *(const int4*)&ei[id * 4];
    int4 d = *(const int4*)&ei[EE + id * 4];
    int p;
    p = atomicAdd(&g_deg[d.x], 1); if (p < CAP) g_srt[d.x * CAP + p] = s.x;
    p = atomicAdd(&g_deg[d.y], 1); if (p < CAP) g_srt[d.y * CAP + p] = s.y;
    p = atomicAdd(&g_deg[d.z], 1); if (p < CAP) g_srt[d.z * CAP + p] = s.z;
    p = atomicAdd(&g_deg[d.w], 1); if (p < CAP) g_srt[d.w * CAP + p] = s.w;
}

// ---------------- GAT softmax + aggregation (fp16 h in, fp16 out) ----------------
__global__ __launch_bounds__(64) void gat_agg_kernel(const float* __restrict__ bias) {
    const int dst = blockIdx.x;
    const int tid = threadIdx.x;
    const int start = dst * CAP;
    const int deg   = min(g_deg[dst], CAP);
    const float ad0 = g_ad[dst * 2], ad1 = g_ad[dst * 2 + 1];

    __shared__ int   sh_s[CAP];
    __shared__ float sh_w0[CAP];
    __shared__ float sh_w1[CAP];
    __shared__ float rsum[4];

    float s0 = 0.f, s1 = 0.f;
    for (int i = tid; i < deg; i += 64) {
        int s = g_srt[start + i];
        float2 av = ((const float2*)g_as)[s];
        float e0 = av.x + ad0; e0 = e0 > 0.f ? e0 : NEG_SLOPE * e0;
        float e1 = av.y + ad1; e1 = e1 > 0.f ? e1 : NEG_SLOPE * e1;
        float w0 = __expf(e0);
        float w1 = __expf(e1);
        sh_s[i]  = s;
        sh_w0[i] = w0;
        sh_w1[i] = w1;
        s0 += w0; s1 += w1;
    }
    __syncthreads();

    const int c0 = 4 * tid;
    const float* shw = (tid >= 32) ? sh_w1 : sh_w0;
    float2 accA = make_float2(0.f, 0.f);
    float2 accB = make_float2(0.f, 0.f);
    const __half* hbase = &g_hh[c0];

#pragma unroll 8
    for (int i = 0; i < deg; i++) {
        float w = shw[i];
        uint2 v = *(const uint2*)(hbase + (size_t)sh_s[i] * FTOT);
        float2 f01 = __half22float2(*(__half2*)&v.x);
        float2 f23 = __half22float2(*(__half2*)&v.y);
        ffma2(accA, w, f01);
        ffma2(accB, w, f23);
    }

#pragma unroll
    for (int o = 16; o > 0; o >>= 1) {
        s0 += __shfl_xor_sync(0xffffffffu, s0, o);
        s1 += __shfl_xor_sync(0xffffffffu, s1, o);
    }
    if ((tid & 31) == 0) { rsum[(tid >> 5) * 2] = s0; rsum[(tid >> 5) * 2 + 1] = s1; }
    __syncthreads();
    float t0 = rsum[0] + rsum[2];
    float t1 = rsum[1] + rsum[3];
    float inv = (tid >= 32) ? (1.f / (t1 + 1e-16f)) : (1.f / (t0 + 1e-16f));

    float4 bi = *(const float4*)(bias + c0);
    float o0 = fmaxf(accA.x * inv + bi.x, 0.f);
    float o1 = fmaxf(accA.y * inv + bi.y, 0.f);
    float o2 = fmaxf(accB.x * inv + bi.z, 0.f);
    float o3 = fmaxf(accB.y * inv + bi.w, 0.f);
    __half2 h0 = __floats2half2_rn(o0, o1);
    __half2 h1 = __floats2half2_rn(o2, o3);
    uint2 u;
    u.x = *(unsigned*)&h0;
    u.y = *(unsigned*)&h1;
    *(uint2*)&g_gath[(size_t)dst * 256 + c0] = u;
}

// ---------------- pairwise distances, streaming stores, MUFU sqrt ----------------
#define CD_I 64
#define CD_J 1024
__global__ __launch_bounds__(256) void cdist_kernel(float* __restrict__ out) {
    __shared__ float zi[CD_I * 3];
    int ibase = blockIdx.y * CD_I;
    int jbase = blockIdx.x * CD_J;
    for (int t = threadIdx.x; t < CD_I * 3; t += 256) zi[t] = g_z[ibase * 3 + t];

    int j0 = jbase + threadIdx.x * 4;
    float4 p0 = *(const float4*)(g_z + (size_t)j0 * 3);
    float4 p1 = *(const float4*)(g_z + (size_t)j0 * 3 + 4);
    float4 p2 = *(const float4*)(g_z + (size_t)j0 * 3 + 8);
    float jx[4] = {p0.x, p0.w, p1.z, p2.y};
    float jy[4] = {p0.y, p1.x, p1.w, p2.z};
    float jz[4] = {p0.z, p1.y, p2.x, p2.w};
    __syncthreads();

#pragma unroll 4
    for (int ii = 0; ii < CD_I; ii++) {
        float zx = zi[ii * 3], zy = zi[ii * 3 + 1], zz = zi[ii * 3 + 2];
        float r[4];
#pragma unroll
        for (int t = 0; t < 4; t++) {
            float dx = zx - jx[t];
            float dy = zy - jy[t];
            float dz = zz - jz[t];
            float d2 = dx * dx + dy * dy + dz * dz;
            r[t] = d2 > 0.f ? d2 * rsqrtf(d2) : 0.f;
        }
        float* ptr = out + (size_t)(ibase + ii) * NN + j0;
        asm volatile("st.global.cs.v4.f32 [%0], {%1, %2, %3, %4};"
                     :: "l"(ptr), "f"(r[0]), "f"(r[1]), "f"(r[2]), "f"(r[3])
                     : "memory");
    }
}

// ---------------- host launcher ----------------
extern "C" void kernel_launch(void* const* d_in, const int* in_sizes, int n_in,
                              void* d_out, int out_size) {
    const float* x        = (const float*)d_in[0];
    const int*   ei       = (const int*)  d_in[1];
    const float* W_gat    = (const float*)d_in[2];
    const float* att_src  = (const float*)d_in[3];
    const float* att_dst  = (const float*)d_in[4];
    const float* bias_gat = (const float*)d_in[5];
    const float* w_a  = (const float*)d_in[6];
    const float* b_a  = (const float*)d_in[7];
    const float* g_a  = (const float*)d_in[8];
    const float* be_a = (const float*)d_in[9];
    const float* w1   = (const float*)d_in[10];
    const float* b1   = (const float*)d_in[11];
    const float* g1   = (const float*)d_in[12];
    const float* be1  = (const float*)d_in[13];
    const float* w2   = (const float*)d_in[14];
    const float* b2   = (const float*)d_in[15];
    const float* g2   = (const float*)d_in[16];
    const float* be2  = (const float*)d_in[17];
    const float* w3   = (const float*)d_in[18];
    const float* b3   = (const float*)d_in[19];
    float* out = (float*)d_out;

    void* p;
    cudaGetSymbolAddress(&p, g_xh);   __half* pxh  = (__half*)p;
    cudaGetSymbolAddress(&p, g_wh);   __half* pwh  = (__half*)p;
    cudaGetSymbolAddress(&p, g_w1h);  __half* pw1h = (__half*)p;
    cudaGetSymbolAddress(&p, g_hh);   __half* phh  = (__half*)p;
    cudaGetSymbolAddress(&p, g_gath); __half* pgath= (__half*)p;
    cudaGetSymbolAddress(&p, g_l1);   float* pl1   = (float*)p;
    cudaGetSymbolAddress(&p, g_l2);   float* pl2   = (float*)p;
    cudaGetSymbolAddress(&p, g_z);    float* pz    = (float*)p;

    static cudaStream_t s2 = nullptr;
    static cudaEvent_t evFork = nullptr, evJoin = nullptr;
    static bool tried = false;
    if (!tried) {
        tried = true;
        if (cudaStreamCreateWithFlags(&s2, cudaStreamNonBlocking) != cudaSuccess) s2 = nullptr;
        if (s2) {
            if (cudaEventCreateWithFlags(&evFork, cudaEventDisableTiming) != cudaSuccess ||
                cudaEventCreateWithFlags(&evJoin, cudaEventDisableTiming) != cudaSuccess) {
                s2 = nullptr;
            }
        }
    }

    const int CVT_TOT = X4 + W4 + WA4;
    if (s2) {
        cudaEventRecord(evFork, 0);
        cudaStreamWaitEvent(s2, evFork, 0);
        bucket_init_kernel<<<NN / 256, 256, 0, s2>>>();
        bucket_scatter_kernel<<<EE / 4 / 256, 256, 0, s2>>>(ei);
        cudaEventRecord(evJoin, s2);

        cvt_all_kernel<<<(CVT_TOT + 255) / 256, 256>>>(x, W_gat, w_a);
        hgemm1_kernel<<<dim3(FTOT / 128, NN / 128), 256>>>(pxh, pwh, phh);
        attn_dots_kernel<<<NN / 2, 128>>>(att_src, att_dst);

        cudaStreamWaitEvent(0, evJoin, 0);
    } else {
        cvt_all_kernel<<<(CVT_TOT + 255) / 256, 256>>>(x, W_gat, w_a);
        hgemm1_kernel<<<dim3(FTOT / 128, NN / 128), 256>>>(pxh, pwh, phh);
        attn_dots_kernel<<<NN / 2, 128>>>(att_src, att_dst);
        bucket_init_kernel<<<NN / 256, 256>>>();
        bucket_scatter_kernel<<<EE / 4 / 256, 256>>>(ei);
    }

    // segment softmax + aggregation + bias + relu -> fp16
    gat_agg_kernel<<<NN, 64>>>(bias_gat);

    // layer_a: HMMA gemm + bias + LN + ReLU
    hgemm_ln_kernel<<<NN / 64, 256>>>(pgath, pw1h, b_a, g_a, be_a, pl1);

    // remaining MLP (fp32 FFMA2) + final projection
    fused_gemm_ln_kernel<128, 64, 128, 8, false><<<NN / 128, 256>>>(
        pl1, w1, b1, g1, be1, pl2, nullptr, nullptr, nullptr);
    fused_gemm_ln_kernel<128, 32, 64, 8, true><<<NN / 128, 128>>>(
        pl2, w2, b2, g2, be2, nullptr, w3, b3, pz);

    // pairwise distance matrix
    cdist_kernel<<<dim3(NN / CD_J, NN / CD_I), 256>>>(out);
}

// round 11
// speedup vs baseline: 1.4647x; 1.0002x over previous
#include <cuda_runtime.h>
#include <cuda_fp16.h>
#include <math.h>

#define NN   8192
#define EE   524288
#define FIN  256
#define FTOT 256      // H * F_OUT
#define FOUT 128
#define CAP  256      // per-node bucket capacity (mean deg = 65, Poisson)
#define LN_EPS   1e-5f
#define NEG_SLOPE 0.2f

// ---------------- scratch (__device__ globals; no allocation allowed) ----------------
__device__ __align__(16) __half g_xh[NN * FIN];     // x in fp16
__device__ __align__(16) __half g_wh[FIN * FTOT];   // W_gat in fp16
__device__ __align__(16) __half g_w1h[256 * 128];   // w_a in fp16
__device__ __align__(16) __half g_hh[NN * FTOT];    // x @ W_gat, fp16
__device__ __align__(16) __half g_gath[NN * 256];   // GAT output (relu), fp16
__device__ __align__(16) float g_as[NN * 2];
__device__ __align__(16) float g_ad[NN * 2];
__device__ int   g_deg[NN];
__device__ int   g_srt[NN * CAP];
__device__ __align__(16) float g_l1[NN * 128];
__device__ __align__(16) float g_l2[NN * 64];
__device__ __align__(16) float g_z[NN * 3];

// ---------------- packed fp32x2 FMA ----------------
__device__ __forceinline__ void ffma2(float2& c, float a, const float2& b) {
    float2 av = make_float2(a, a);
    unsigned long long ua = *reinterpret_cast<unsigned long long*>(&av);
    unsigned long long ub = *reinterpret_cast<const unsigned long long*>(&b);
    unsigned long long uc = *reinterpret_cast<unsigned long long*>(&c);
    asm("fma.rn.f32x2 %0, %1, %2, %0;" : "+l"(uc) : "l"(ua), "l"(ub));
    c = *reinterpret_cast<float2*>(&uc);
}

__device__ __forceinline__ void cp_async16(unsigned smem_dst, const void* gmem_src) {
    asm volatile("cp.async.cg.shared.global [%0], [%1], 16;" :: "r"(smem_dst), "l"(gmem_src));
}

// ---------------- fused fp32 -> fp16 conversion of x, W_gat, w_a ----------------
#define X4  (NN * FIN / 4)          // 131072
#define W4  (FIN * FTOT / 4)        // 16384
#define WA4 (256 * 128 / 4)         // 8192
__global__ void cvt_all_kernel(const float* __restrict__ x,
                               const float* __restrict__ W,
                               const float* __restrict__ wa) {
    int i = blockIdx.x * blockDim.x + threadIdx.x;
    const float* src; __half* dst; int j;
    if (i < X4)            { src = x;  dst = g_xh;  j = i; }
    else if (i < X4 + W4)  { src = W;  dst = g_wh;  j = i - X4; }
    else if (i < X4 + W4 + WA4) { src = wa; dst = g_w1h; j = i - X4 - W4; }
    else return;
    float4 v = ((const float4*)src)[j];
    __half2 h0 = __floats2half2_rn(v.x, v.y);
    __half2 h1 = __floats2half2_rn(v.z, v.w);
    uint2 u;
    u.x = *(unsigned*)&h0;
    u.y = *(unsigned*)&h1;
    ((uint2*)dst)[j] = u;
}

// ---------------- gemm1: fp16 HMMA, 128x128 tile, BK=32, cp.async double-buffered ----------------
#define A_LDS 40   // 32 + 8 pad halfs (80B rows, 16B-aligned)
#define B_LDS 136  // 128 + 8 pad halfs (272B rows)
__global__ __launch_bounds__(256) void hgemm1_kernel(
    const __half* __restrict__ Ah,
    const __half* __restrict__ Bh,
    __half* __restrict__ C) {
    // overlay: [As(2 stages) | Bs(2 stages)] reused as Cs in the epilogue
    __shared__ __align__(16) char smem_raw[2 * 128 * A_LDS * 2 + 2 * 32 * B_LDS * 2];
    __half* As_base = (__half*)smem_raw;                   // stage s: As_base + s*128*A_LDS
    __half* Bs_base = As_base + 2 * 128 * A_LDS;           // stage s: Bs_base + s*32*B_LDS
    __half (*Cs)[B_LDS] = (__half(*)[B_LDS])smem_raw;      // epilogue overlay [128][136]

    const int tid  = threadIdx.x;
    const int warp = tid >> 5;
    const int lane = tid & 31;
    const int brow = blockIdx.y * 128;
    const int bcol = blockIdx.x * 128;
    const int mw = (warp & 3) * 32;
    const int nw = (warp >> 2) * 64;

    float c[2][8][4];
#pragma unroll
    for (int mi = 0; mi < 2; mi++)
#pragma unroll
        for (int nj = 0; nj < 8; nj++)
#pragma unroll
            for (int q = 0; q < 4; q++) c[mi][nj][q] = 0.f;

    // ldmatrix base addresses per stage (ksub adds 32B on A, 16 rows = 16*B_LDS*2 B on B)
    unsigned aAddr[2][2], bAddr[2][4];
#pragma unroll
    for (int st = 0; st < 2; st++) {
#pragma unroll
        for (int mi = 0; mi < 2; mi++)
            aAddr[st][mi] = (unsigned)__cvta_generic_to_shared(
                As_base + st * 128 * A_LDS + (mw + mi * 16 + (lane & 15)) * A_LDS + (lane >> 4) * 8);
#pragma unroll
        for (int j = 0; j < 4; j++)
            bAddr[st][j] = (unsigned)__cvta_generic_to_shared(
                Bs_base + st * 32 * B_LDS + (lane & 15) * B_LDS + nw + j * 16 + (lane >> 4) * 8);
    }

    // staging indices: A tile 128x32 (4 chunks/row), B tile 32x128 (16 chunks/row); 2 chunks/thread each
    const int arA = tid >> 2, acA = (tid & 3) * 8;
    const int brB = tid >> 4, bcB = (tid & 15) * 8;

    auto stage = [&](int kt, int st) {
        __half* Ad = As_base + st * 128 * A_LDS;
        __half* Bd = Bs_base + st * 32 * B_LDS;
        int k0 = kt * 32;
#pragma unroll
        for (int l = 0; l < 2; l++) {
            int r = arA + l * 64;
            cp_async16((unsigned)__cvta_generic_to_shared(Ad + r * A_LDS + acA),
                       Ah + (size_t)(brow + r) * FIN + k0 + acA);
        }
#pragma unroll
        for (int l = 0; l < 2; l++) {
            int r = brB + l * 16;
            cp_async16((unsigned)__cvta_generic_to_shared(Bd + r * B_LDS + bcB),
                       Bh + (size_t)(k0 + r) * FTOT + bcol + bcB);
        }
    };

    stage(0, 0);
    asm volatile("cp.async.commit_group;");

#pragma unroll
    for (int it = 0; it < 8; it++) {
        const int cur = it & 1;
        if (it < 7) {
            stage(it + 1, cur ^ 1);
            asm volatile("cp.async.commit_group;");
            asm volatile("cp.async.wait_group 1;");
        } else {
            asm volatile("cp.async.wait_group 0;");
        }
        __syncthreads();
#pragma unroll
        for (int ks = 0; ks < 2; ks++) {
            unsigned a[2][4], b[4][4];
#pragma unroll
            for (int mi = 0; mi < 2; mi++)
                asm volatile("ldmatrix.sync.aligned.m8n8.x4.shared.b16 {%0,%1,%2,%3}, [%4];"
                             : "=r"(a[mi][0]), "=r"(a[mi][1]), "=r"(a[mi][2]), "=r"(a[mi][3])
                             : "r"(aAddr[cur][mi] + ks * 32));
#pragma unroll
            for (int j = 0; j < 4; j++)
                asm volatile("ldmatrix.sync.aligned.m8n8.x4.trans.shared.b16 {%0,%1,%2,%3}, [%4];"
                             : "=r"(b[j][0]), "=r"(b[j][1]), "=r"(b[j][2]), "=r"(b[j][3])
                             : "r"(bAddr[cur][j] + ks * 16 * B_LDS * 2));
#pragma unroll
            for (int mi = 0; mi < 2; mi++)
#pragma unroll
                for (int nj = 0; nj < 8; nj++) {
                    const unsigned b0 = b[nj >> 1][(nj & 1) * 2];
                    const unsigned b1 = b[nj >> 1][(nj & 1) * 2 + 1];
                    asm volatile(
                        "mma.sync.aligned.m16n8k16.row.col.f32.f16.f16.f32 "
                        "{%0,%1,%2,%3}, {%4,%5,%6,%7}, {%8,%9}, {%0,%1,%2,%3};"
                        : "+f"(c[mi][nj][0]), "+f"(c[mi][nj][1]),
                          "+f"(c[mi][nj][2]), "+f"(c[mi][nj][3])
                        : "r"(a[mi][0]), "r"(a[mi][1]), "r"(a[mi][2]), "r"(a[mi][3]),
                          "r"(b0), "r"(b1));
                }
        }
        __syncthreads();
    }

    // epilogue: overlay Cs on As/Bs (loop's trailing barrier protects the reuse)
    const int g  = lane >> 2;
    const int tg = lane & 3;
#pragma unroll
    for (int mi = 0; mi < 2; mi++)
#pragma unroll
        for (int nj = 0; nj < 8; nj++) {
            int r0 = mw + mi * 16 + g;
            int cc = nw + nj * 8 + tg * 2;
            *(__half2*)&Cs[r0][cc]     = __floats2half2_rn(c[mi][nj][0], c[mi][nj][1]);
            *(__half2*)&Cs[r0 + 8][cc] = __floats2half2_rn(c[mi][nj][2], c[mi][nj][3]);
        }
    __syncthreads();
#pragma unroll
    for (int l = 0; l < 8; l++) {
        int idx = tid + l * 256;
        int r = idx >> 4, c8 = (idx & 15) * 8;
        *(uint4*)(C + (size_t)(brow + r) * FTOT + bcol + c8) = *(uint4*)&Cs[r][c8];
    }
}

// ---------------- layer_a: fp16 HMMA GEMM (64x128 tile) + bias + LN + ReLU -> fp32 ----------------
__global__ __launch_bounds__(256) void hgemm_ln_kernel(
    const __half* __restrict__ Ah,   // g_gath [NN][256]
    const __half* __restrict__ Bh,   // w_a fp16 [256][128]
    const float* __restrict__ bias, const float* __restrict__ gamma,
    const float* __restrict__ beta, float* __restrict__ C) {  // g_l1 [NN][128]
    __shared__ __half As[64][24];
    __shared__ __half Bs[16][136];
    __shared__ float  Cs[64][132];
    const int tid  = threadIdx.x;
    const int warp = tid >> 5;
    const int lane = tid & 31;
    const int brow = blockIdx.x * 64;
    const int mw = (warp & 3) * 16;
    const int nw = (warp >> 2) * 64;

    float c[8][4];
#pragma unroll
    for (int nj = 0; nj < 8; nj++)
#pragma unroll
        for (int q = 0; q < 4; q++) c[nj][q] = 0.f;

    unsigned aAddr = (unsigned)__cvta_generic_to_shared(
        &As[mw + (lane & 15)][(lane >> 4) * 8]);
    unsigned bAddr[4];
#pragma unroll
    for (int j = 0; j < 4; j++)
        bAddr[j] = (unsigned)__cvta_generic_to_shared(
            &Bs[lane & 15][nw + j * 16 + (lane >> 4) * 8]);

    const int ar = tid >> 1, ac = (tid & 1) * 8;
    const int br = tid >> 4, bc = (tid & 15) * 8;

    for (int k0 = 0; k0 < 256; k0 += 16) {
        if (tid < 128)
            *(uint4*)&As[ar][ac] = *(const uint4*)(Ah + (size_t)(brow + ar) * 256 + k0 + ac);
        *(uint4*)&Bs[br][bc] = *(const uint4*)(Bh + (size_t)(k0 + br) * 128 + bc);
        __syncthreads();

        unsigned a[4], b[4][4];
        asm volatile("ldmatrix.sync.aligned.m8n8.x4.shared.b16 {%0,%1,%2,%3}, [%4];"
                     : "=r"(a[0]), "=r"(a[1]), "=r"(a[2]), "=r"(a[3]) : "r"(aAddr));
#pragma unroll
        for (int j = 0; j < 4; j++)
            asm volatile("ldmatrix.sync.aligned.m8n8.x4.trans.shared.b16 {%0,%1,%2,%3}, [%4];"
                         : "=r"(b[j][0]), "=r"(b[j][1]), "=r"(b[j][2]), "=r"(b[j][3])
                         : "r"(bAddr[j]));
#pragma unroll
        for (int nj = 0; nj < 8; nj++) {
            const unsigned b0 = b[nj >> 1][(nj & 1) * 2];
            const unsigned b1 = b[nj >> 1][(nj & 1) * 2 + 1];
            asm volatile(
                "mma.sync.aligned.m16n8k16.row.col.f32.f16.f16.f32 "
                "{%0,%1,%2,%3}, {%4,%5,%6,%7}, {%8,%9}, {%0,%1,%2,%3};"
                : "+f"(c[nj][0]), "+f"(c[nj][1]), "+f"(c[nj][2]), "+f"(c[nj][3])
                : "r"(a[0]), "r"(a[1]), "r"(a[2]), "r"(a[3]), "r"(b0), "r"(b1));
        }
        __syncthreads();
    }

    const int g  = lane >> 2;
    const int tg = lane & 3;
#pragma unroll
    for (int nj = 0; nj < 8; nj++) {
        int r0 = mw + g;
        int cc = nw + nj * 8 + tg * 2;
        Cs[r0][cc]     = c[nj][0]; Cs[r0][cc + 1]     = c[nj][1];
        Cs[r0 + 8][cc] = c[nj][2]; Cs[r0 + 8][cc + 1] = c[nj][3];
    }
    __syncthreads();

    const int c0 = lane * 4;
    float4 bi4 = *(const float4*)(bias + c0);
    float4 g4  = *(const float4*)(gamma + c0);
    float4 be4 = *(const float4*)(beta + c0);
    for (int rr = warp; rr < 64; rr += 8) {
        float v0 = Cs[rr][c0]     + bi4.x;
        float v1 = Cs[rr][c0 + 1] + bi4.y;
        float v2 = Cs[rr][c0 + 2] + bi4.z;
        float v3 = Cs[rr][c0 + 3] + bi4.w;
        float s = v0 + v1 + v2 + v3;
#pragma unroll
        for (int o = 16; o > 0; o >>= 1) s += __shfl_xor_sync(0xffffffffu, s, o);
        float mu = s * (1.f / 128.f);
        float d0 = v0 - mu, d1 = v1 - mu, d2 = v2 - mu, d3 = v3 - mu;
        float sq = d0 * d0 + d1 * d1 + d2 * d2 + d3 * d3;
#pragma unroll
        for (int o = 16; o > 0; o >>= 1) sq += __shfl_xor_sync(0xffffffffu, sq, o);
        float inv = rsqrtf(sq * (1.f / 128.f) + LN_EPS);
        float4 y;
        y.x = fmaxf(d0 * inv * g4.x + be4.x, 0.f);
        y.y = fmaxf(d1 * inv * g4.y + be4.y, 0.f);
        y.z = fmaxf(d2 * inv * g4.z + be4.z, 0.f);
        y.w = fmaxf(d3 * inv * g4.w + be4.w, 0.f);
        *(float4*)(C + (size_t)(brow + rr) * 128 + c0) = y;
    }
}

// ---------------- attention logits from fp16 h ----------------
__global__ void attn_dots_kernel(const float* __restrict__ att_src,
                                 const float* __restrict__ att_dst) {
    int warp = threadIdx.x >> 5;
    int lane = threadIdx.x & 31;
    int n    = blockIdx.x * 2 + (warp >> 1);
    int head = warp & 1;
    uint2 hv = ((const uint2*)&g_hh[(size_t)n * FTOT + head * FOUT])[lane];
    float2 h01 = __half22float2(*(__half2*)&hv.x);
    float2 h23 = __half22float2(*(__half2*)&hv.y);
    float4 s4 = ((const float4*)att_src)[head * 32 + lane];
    float4 d4 = ((const float4*)att_dst)[head * 32 + lane];
    float ds = h01.x * s4.x + h01.y * s4.y + h23.x * s4.z + h23.y * s4.w;
    float dd = h01.x * d4.x + h01.y * d4.y + h23.x * d4.z + h23.y * d4.w;
#pragma unroll
    for (int o = 16; o > 0; o >>= 1) {
        ds += __shfl_xor_sync(0xffffffff, ds, o);
        dd += __shfl_xor_sync(0xffffffff, dd, o);
    }
    if (lane == 0) {
        g_as[n * 2 + head] = ds;
        g_ad[n * 2 + head] = dd;
    }
}

// ---------------- fused fp32 GEMM + bias + LN + ReLU [+ 32->3 proj] (small layers) ----------------
template <int BM, int N, int K, int TM, bool PROJ>
__global__ void fused_gemm_ln_kernel(
    const float* __restrict__ A, const float* __restrict__ W,
    const float* __restrict__ bias, const float* __restrict__ gamma,
    const float* __restrict__ beta, float* __restrict__ C,
    const float* __restrict__ w3, const float* __restrict__ b3,
    float* __restrict__ Z) {
    constexpr int LX = N / 4;
    constexpr int THREADS = (BM / TM) * LX;
    __shared__ float As[16][BM + 4];
    __shared__ float Ws[16][N];
    __shared__ float w3s[96];
    __shared__ float b3s[3];
    const int tid = threadIdx.x;
    const int tx  = tid % LX;
    const int ty  = tid / LX;
    const int brow = blockIdx.x * BM;

    if (PROJ) {
        for (int i = tid; i < 96; i += THREADS) w3s[i] = w3[i];
        if (tid < 3) b3s[tid] = b3[tid];
    }

    float2 acc2[TM][2];
#pragma unroll
    for (int m = 0; m < TM; m++) { acc2[m][0] = make_float2(0.f, 0.f); acc2[m][1] = make_float2(0.f, 0.f); }

    for (int k0 = 0; k0 < K; k0 += 16) {
#pragma unroll
        for (int i = tid; i < BM * 4; i += THREADS) {
            int r = i >> 2, c4 = (i & 3) * 4;
            float4 v = *(const float4*)(A + (size_t)(brow + r) * K + k0 + c4);
            As[c4 + 0][r] = v.x; As[c4 + 1][r] = v.y;
            As[c4 + 2][r] = v.z; As[c4 + 3][r] = v.w;
        }
#pragma unroll
        for (int i = tid; i < N * 4; i += THREADS) {
            int r = i / (N / 4), c4 = (i % (N / 4)) * 4;
            *(float4*)&Ws[r][c4] = *(const float4*)(W + (size_t)(k0 + r) * N + c4);
        }
        __syncthreads();
#pragma unroll
        for (int k = 0; k < 16; k++) {
            float ar[TM];
#pragma unroll
            for (int q = 0; q < TM / 4; q++)
                *(float4*)&ar[q * 4] = *(float4*)&As[k][ty * TM + q * 4];
            float4 b4 = *(float4*)&Ws[k][tx * 4];
            float2 br0 = make_float2(b4.x, b4.y);
            float2 br1 = make_float2(b4.z, b4.w);
#pragma unroll
            for (int m = 0; m < TM; m++) {
                ffma2(acc2[m][0], ar[m], br0);
                ffma2(acc2[m][1], ar[m], br1);
            }
        }
        __syncthreads();
    }

    const int c0 = tx * 4;
    float4 bi4 = *(const float4*)(bias + c0);
    float4 g4  = *(const float4*)(gamma + c0);
    float4 be4 = *(const float4*)(beta + c0);

#pragma unroll
    for (int m = 0; m < TM; m++) {
        float v0 = acc2[m][0].x + bi4.x;
        float v1 = acc2[m][0].y + bi4.y;
        float v2 = acc2[m][1].x + bi4.z;
        float v3 = acc2[m][1].y + bi4.w;
        float s = v0 + v1 + v2 + v3;
#pragma unroll
        for (int o = LX >> 1; o > 0; o >>= 1) s += __shfl_xor_sync(0xffffffffu, s, o);
        float mu = s * (1.f / N);
        float d0 = v0 - mu, d1 = v1 - mu, d2 = v2 - mu, d3 = v3 - mu;
        float sq = d0 * d0 + d1 * d1 + d2 * d2 + d3 * d3;
#pragma unroll
        for (int o = LX >> 1; o > 0; o >>= 1) sq += __shfl_xor_sync(0xffffffffu, sq, o);
        float inv = rsqrtf(sq * (1.f / N) + LN_EPS);
        float y0 = fmaxf(d0 * inv * g4.x + be4.x, 0.f);
        float y1 = fmaxf(d1 * inv * g4.y + be4.y, 0.f);
        float y2 = fmaxf(d2 * inv * g4.z + be4.z, 0.f);
        float y3 = fmaxf(d3 * inv * g4.w + be4.w, 0.f);
        int row = brow + ty * TM + m;
        if (!PROJ) {
            float4 v; v.x = y0; v.y = y1; v.z = y2; v.w = y3;
            *(float4*)(C + (size_t)row * N + c0) = v;
        } else {
            float p0 = y0 * w3s[(c0 + 0) * 3 + 0] + y1 * w3s[(c0 + 1) * 3 + 0] +
                       y2 * w3s[(c0 + 2) * 3 + 0] + y3 * w3s[(c0 + 3) * 3 + 0];
            float p1 = y0 * w3s[(c0 + 0) * 3 + 1] + y1 * w3s[(c0 + 1) * 3 + 1] +
                       y2 * w3s[(c0 + 2) * 3 + 1] + y3 * w3s[(c0 + 3) * 3 + 1];
            float p2 = y0 * w3s[(c0 + 0) * 3 + 2] + y1 * w3s[(c0 + 1) * 3 + 2] +
                       y2 * w3s[(c0 + 2) * 3 + 2] + y3 * w3s[(c0 + 3) * 3 + 2];
#pragma unroll
            for (int o = LX >> 1; o > 0; o >>= 1) {
                p0 += __shfl_xor_sync(0xffffffffu, p0, o);
                p1 += __shfl_xor_sync(0xffffffffu, p1, o);
                p2 += __shfl_xor_sync(0xffffffffu, p2, o);
            }
            if (tx == 0) {
                Z[row * 3 + 0] = p0 + b3s[0];
                Z[row * 3 + 1] = p1 + b3s[1];
                Z[row * 3 + 2] = p2 + b3s[2];
            }
        }
    }
}

// ---------------- bucket CSR ----------------
__global__ void bucket_init_kernel() {
    int i = blockIdx.x * blockDim.x + threadIdx.x;
    if (i < NN) {
        g_deg[i] = 1;
        g_srt[i * CAP] = i;
    }
}

__global__ void bucket_scatter_kernel(const int* __restrict__ ei) {
    int id = blockIdx.x * blockDim.x + threadIdx.x;
    if (id >= EE / 4) return;
    int4 s = *(const int4*)&ei[id * 4];
    int4 d = *(const int4*)&ei[EE + id * 4];
    int p;
    p = atomicAdd(&g_deg[d.x], 1); if (p < CAP) g_srt[d.x * CAP + p] = s.x;
    p = atomicAdd(&g_deg[d.y], 1); if (p < CAP) g_srt[d.y * CAP + p] = s.y;
    p = atomicAdd(&g_deg[d.z], 1); if (p < CAP) g_srt[d.z * CAP + p] = s.z;
    p = atomicAdd(&g_deg[d.w], 1); if (p < CAP) g_srt[d.w * CAP + p] = s.w;
}

// ---------------- GAT softmax + aggregation (fp16 h in, fp16 out) ----------------
__global__ __launch_bounds__(64) void gat_agg_kernel(const float* __restrict__ bias) {
    const int dst = blockIdx.x;
    const int tid = threadIdx.x;
    const int start = dst * CAP;
    const int deg   = min(g_deg[dst], CAP);
    const float ad0 = g_ad[dst * 2], ad1 = g_ad[dst * 2 + 1];

    __shared__ int   sh_s[CAP];
    __shared__ float sh_w0[CAP];
    __shared__ float sh_w1[CAP];
    __shared__ float rsum[4];

    float s0 = 0.f, s1 = 0.f;
    for (int i = tid; i < deg; i += 64) {
        int s = g_srt[start + i];
        float2 av = ((const float2*)g_as)[s];
        float e0 = av.x + ad0; e0 = e0 > 0.f ? e0 : NEG_SLOPE * e0;
        float e1 = av.y + ad1; e1 = e1 > 0.f ? e1 : NEG_SLOPE * e1;
        float w0 = __expf(e0);
        float w1 = __expf(e1);
        sh_s[i]  = s;
        sh_w0[i] = w0;
        sh_w1[i] = w1;
        s0 += w0; s1 += w1;
    }
    __syncthreads();

    const int c0 = 4 * tid;
    const float* shw = (tid >= 32) ? sh_w1 : sh_w0;
    float2 accA = make_float2(0.f, 0.f);
    float2 accB = make_float2(0.f, 0.f);
    const __half* hbase = &g_hh[c0];

#pragma unroll 8
    for (int i = 0; i < deg; i++) {
        float w = shw[i];
        uint2 v = *(const uint2*)(hbase + (size_t)sh_s[i] * FTOT);
        float2 f01 = __half22float2(*(__half2*)&v.x);
        float2 f23 = __half22float2(*(__half2*)&v.y);
        ffma2(accA, w, f01);
        ffma2(accB, w, f23);
    }

#pragma unroll
    for (int o = 16; o > 0; o >>= 1) {
        s0 += __shfl_xor_sync(0xffffffffu, s0, o);
        s1 += __shfl_xor_sync(0xffffffffu, s1, o);
    }
    if ((tid & 31) == 0) { rsum[(tid >> 5) * 2] = s0; rsum[(tid >> 5) * 2 + 1] = s1; }
    __syncthreads();
    float t0 = rsum[0] + rsum[2];
    float t1 = rsum[1] + rsum[3];
    float inv = (tid >= 32) ? (1.f / (t1 + 1e-16f)) : (1.f / (t0 + 1e-16f));

    float4 bi = *(const float4*)(bias + c0);
    float o0 = fmaxf(accA.x * inv + bi.x, 0.f);
    float o1 = fmaxf(accA.y * inv + bi.y, 0.f);
    float o2 = fmaxf(accB.x * inv + bi.z, 0.f);
    float o3 = fmaxf(accB.y * inv + bi.w, 0.f);
    __half2 h0 = __floats2half2_rn(o0, o1);
    __half2 h1 = __floats2half2_rn(o2, o3);
    uint2 u;
    u.x = *(unsigned*)&h0;
    u.y = *(unsigned*)&h1;
    *(uint2*)&g_gath[(size_t)dst * 256 + c0] = u;
}

// ---------------- pairwise distances, streaming stores, MUFU sqrt ----------------
#define CD_I 64
#define CD_J 1024
__global__ __launch_bounds__(256) void cdist_kernel(float* __restrict__ out) {
    __shared__ float zi[CD_I * 3];
    int ibase = blockIdx.y * CD_I;
    int jbase = blockIdx.x * CD_J;
    for (int t = threadIdx.x; t < CD_I * 3; t += 256) zi[t] = g_z[ibase * 3 + t];

    int j0 = jbase + threadIdx.x * 4;
    float4 p0 = *(const float4*)(g_z + (size_t)j0 * 3);
    float4 p1 = *(const float4*)(g_z + (size_t)j0 * 3 + 4);
    float4 p2 = *(const float4*)(g_z + (size_t)j0 * 3 + 8);
    float jx[4] = {p0.x, p0.w, p1.z, p2.y};
    float jy[4] = {p0.y, p1.x, p1.w, p2.z};
    float jz[4] = {p0.z, p1.y, p2.x, p2.w};
    __syncthreads();

#pragma unroll 4
    for (int ii = 0; ii < CD_I; ii++) {
        float zx = zi[ii * 3], zy = zi[ii * 3 + 1], zz = zi[ii * 3 + 2];
        float r[4];
#pragma unroll
        for (int t = 0; t < 4; t++) {
            float dx = zx - jx[t];
            float dy = zy - jy[t];
            float dz = zz - jz[t];
            float d2 = dx * dx + dy * dy + dz * dz;
            r[t] = d2 > 0.f ? d2 * rsqrtf(d2) : 0.f;
        }
        float* ptr = out + (size_t)(ibase + ii) * NN + j0;
        asm volatile("st.global.cs.v4.f32 [%0], {%1, %2, %3, %4};"
                     :: "l"(ptr), "f"(r[0]), "f"(r[1]), "f"(r[2]), "f"(r[3])
                     : "memory");
    }
}

// ---------------- host launcher ----------------
extern "C" void kernel_launch(void* const* d_in, const int* in_sizes, int n_in,
                              void* d_out, int out_size) {
    const float* x        = (const float*)d_in[0];
    const int*   ei       = (const int*)  d_in[1];
    const float* W_gat    = (const float*)d_in[2];
    const float* att_src  = (const float*)d_in[3];
    const float* att_dst  = (const float*)d_in[4];
    const float* bias_gat = (const float*)d_in[5];
    const float* w_a  = (const float*)d_in[6];
    const float* b_a  = (const float*)d_in[7];
    const float* g_a  = (const float*)d_in[8];
    const float* be_a = (const float*)d_in[9];
    const float* w1   = (const float*)d_in[10];
    const float* b1   = (const float*)d_in[11];
    const float* g1   = (const float*)d_in[12];
    const float* be1  = (const float*)d_in[13];
    const float* w2   = (const float*)d_in[14];
    const float* b2   = (const float*)d_in[15];
    const float* g2   = (const float*)d_in[16];
    const float* be2  = (const float*)d_in[17];
    const float* w3   = (const float*)d_in[18];
    const float* b3   = (const float*)d_in[19];
    float* out = (float*)d_out;

    void* p;
    cudaGetSymbolAddress(&p, g_xh);   __half* pxh  = (__half*)p;
    cudaGetSymbolAddress(&p, g_wh);   __half* pwh  = (__half*)p;
    cudaGetSymbolAddress(&p, g_w1h);  __half* pw1h = (__half*)p;
    cudaGetSymbolAddress(&p, g_hh);   __half* phh  = (__half*)p;
    cudaGetSymbolAddress(&p, g_gath); __half* pgath= (__half*)p;
    cudaGetSymbolAddress(&p, g_l1);   float* pl1   = (float*)p;
    cudaGetSymbolAddress(&p, g_l2);   float* pl2   = (float*)p;
    cudaGetSymbolAddress(&p, g_z);    float* pz    = (float*)p;

    static cudaStream_t s2 = nullptr;
    static cudaEvent_t evFork = nullptr, evJoin = nullptr;
    static bool tried = false;
    if (!tried) {
        tried = true;
        if (cudaStreamCreateWithFlags(&s2, cudaStreamNonBlocking) != cudaSuccess) s2 = nullptr;
        if (s2) {
            if (cudaEventCreateWithFlags(&evFork, cudaEventDisableTiming) != cudaSuccess ||
                cudaEventCreateWithFlags(&evJoin, cudaEventDisableTiming) != cudaSuccess) {
                s2 = nullptr;
            }
        }
    }

    const int CVT_TOT = X4 + W4 + WA4;
    if (s2) {
        cudaEventRecord(evFork, 0);
        cudaStreamWaitEvent(s2, evFork, 0);
        bucket_init_kernel<<<NN / 256, 256, 0, s2>>>();
        bucket_scatter_kernel<<<EE / 4 / 256, 256, 0, s2>>>(ei);
        cudaEventRecord(evJoin, s2);

        cvt_all_kernel<<<(CVT_TOT + 255) / 256, 256>>>(x, W_gat, w_a);
        hgemm1_kernel<<<dim3(FTOT / 128, NN / 128), 256>>>(pxh, pwh, phh);
        attn_dots_kernel<<<NN / 2, 128>>>(att_src, att_dst);

        cudaStreamWaitEvent(0, evJoin, 0);
    } else {
        cvt_all_kernel<<<(CVT_TOT + 255) / 256, 256>>>(x, W_gat, w_a);
        hgemm1_kernel<<<dim3(FTOT / 128, NN / 128), 256>>>(pxh, pwh, phh);
        attn_dots_kernel<<<NN / 2, 128>>>(att_src, att_dst);
        bucket_init_kernel<<<NN / 256, 256>>>();
        bucket_scatter_kernel<<<EE / 4 / 256, 256>>>(ei);
    }

    // segment softmax + aggregation + bias + relu -> fp16
    gat_agg_kernel<<<NN, 64>>>(bias_gat);

    // layer_a: HMMA gemm + bias + LN + ReLU
    hgemm_ln_kernel<<<NN / 64, 256>>>(pgath, pw1h, b_a, g_a, be_a, pl1);

    // remaining MLP (fp32 FFMA2) + final projection
    fused_gemm_ln_kernel<128, 64, 128, 8, false><<<NN / 128, 256>>>(
        pl1, w1, b1, g1, be1, pl2, nullptr, nullptr, nullptr);
    fused_gemm_ln_kernel<128, 32, 64, 8, true><<<NN / 128, 128>>>(
        pl2, w2, b2, g2, be2, nullptr, w3, b3, pz);

    // pairwise distance matrix
    cdist_kernel<<<dim3(NN / CD_J, NN / CD_I), 256>>>(out);
}

// round 12
// speedup vs baseline: 1.4980x; 1.0227x over previous
#include <cuda_runtime.h>
#include <cuda_fp16.h>
#include <math.h>

#define NN   8192
#define EE   524288
#define FIN  256
#define FTOT 256      // H * F_OUT
#define FOUT 128
#define CAP  256      // per-node bucket capacity (mean deg = 65, Poisson)
#define LN_EPS   1e-5f
#define NEG_SLOPE 0.2f

// ---------------- scratch (__device__ globals; no allocation allowed) ----------------
__device__ __align__(16) __half g_xh[NN * FIN];     // x in fp16
__device__ __align__(16) __half g_wh[FIN * FTOT];   // W_gat in fp16
__device__ __align__(16) __half g_w1h[256 * 128];   // w_a in fp16
__device__ __align__(16) __half g_hh[NN * FTOT];    // x @ W_gat, fp16
__device__ __align__(16) __half g_gath[NN * 256];   // GAT output (relu), fp16
__device__ __align__(16) float g_as[NN * 2];
__device__ __align__(16) float g_ad[NN * 2];
__device__ int   g_deg[NN];
__device__ int   g_srt[NN * CAP];
__device__ __align__(16) float g_l1[NN * 128];
__device__ __align__(16) float g_l2[NN * 64];
__device__ __align__(16) float g_z[NN * 3];

// ---------------- packed fp32x2 FMA ----------------
__device__ __forceinline__ void ffma2(float2& c, float a, const float2& b) {
    float2 av = make_float2(a, a);
    unsigned long long ua = *reinterpret_cast<unsigned long long*>(&av);
    unsigned long long ub = *reinterpret_cast<const unsigned long long*>(&b);
    unsigned long long uc = *reinterpret_cast<unsigned long long*>(&c);
    asm("fma.rn.f32x2 %0, %1, %2, %0;" : "+l"(uc) : "l"(ua), "l"(ub));
    c = *reinterpret_cast<float2*>(&uc);
}

__device__ __forceinline__ void cp_async16(unsigned smem_dst, const void* gmem_src) {
    asm volatile("cp.async.cg.shared.global [%0], [%1], 16;" :: "r"(smem_dst), "l"(gmem_src));
}

// ---------------- fused fp32 -> fp16 conversion of x, W_gat, w_a ----------------
#define X4  (NN * FIN / 4)          // 131072
#define W4  (FIN * FTOT / 4)        // 16384
#define WA4 (256 * 128 / 4)         // 8192
__global__ void cvt_all_kernel(const float* __restrict__ x,
                               const float* __restrict__ W,
                               const float* __restrict__ wa) {
    int i = blockIdx.x * blockDim.x + threadIdx.x;
    const float* src; __half* dst; int j;
    if (i < X4)            { src = x;  dst = g_xh;  j = i; }
    else if (i < X4 + W4)  { src = W;  dst = g_wh;  j = i - X4; }
    else if (i < X4 + W4 + WA4) { src = wa; dst = g_w1h; j = i - X4 - W4; }
    else return;
    float4 v = ((const float4*)src)[j];
    __half2 h0 = __floats2half2_rn(v.x, v.y);
    __half2 h1 = __floats2half2_rn(v.z, v.w);
    uint2 u;
    u.x = *(unsigned*)&h0;
    u.y = *(unsigned*)&h1;
    ((uint2*)dst)[j] = u;
}

#define A_LDS 40   // 32 + 8 pad halfs (80B rows, 16B-aligned)
#define B_LDS 136  // 128 + 8 pad halfs (272B rows)

// ---------------- gemm1: fp16 HMMA, 64x128 tile, BK=32 cp.async pipeline,
//                  fused attention dots from the fp16 epilogue staging buffer ----------------
__global__ __launch_bounds__(256) void hgemm1_kernel(
    const __half* __restrict__ Ah,
    const __half* __restrict__ Bh,
    __half* __restrict__ C,
    const float* __restrict__ att_src,
    const float* __restrict__ att_dst) {
    // pipeline buffers; epilogue Cs overlays them
    __shared__ __align__(16) char smem_raw[2 * 64 * A_LDS * 2 + 2 * 32 * B_LDS * 2];
    __half* As_base = (__half*)smem_raw;
    __half* Bs_base = As_base + 2 * 64 * A_LDS;
    __half (*Cs)[B_LDS] = (__half(*)[B_LDS])smem_raw;   // [64][136] = 17408B < 27648B

    const int tid  = threadIdx.x;
    const int warp = tid >> 5;
    const int lane = tid & 31;
    const int brow = blockIdx.y * 64;
    const int bcol = blockIdx.x * 128;   // head = blockIdx.x
    const int mw = (warp & 3) * 16;
    const int nw = (warp >> 2) * 64;

    float c[8][4];
#pragma unroll
    for (int nj = 0; nj < 8; nj++)
#pragma unroll
        for (int q = 0; q < 4; q++) c[nj][q] = 0.f;

    unsigned aAddr[2], bAddr[2][4];
#pragma unroll
    for (int st = 0; st < 2; st++) {
        if (st == 0 || true) {}
    }
#pragma unroll
    for (int st = 0; st < 2; st++) {
        aAddr[st] = (unsigned)__cvta_generic_to_shared(
            As_base + st * 64 * A_LDS + (mw + (lane & 15)) * A_LDS + (lane >> 4) * 8);
#pragma unroll
        for (int j = 0; j < 4; j++)
            bAddr[st][j] = (unsigned)__cvta_generic_to_shared(
                Bs_base + st * 32 * B_LDS + (lane & 15) * B_LDS + nw + j * 16 + (lane >> 4) * 8);
    }

    // staging: A tile 64x32 (4 chunks/row, 256 chunks = 1/thread);
    //          B tile 32x128 (16 chunks/row, 512 chunks = 2/thread)
    const int arA = tid >> 2, acA = (tid & 3) * 8;
    const int brB = tid >> 4, bcB = (tid & 15) * 8;

    auto stage = [&](int kt, int st) {
        __half* Ad = As_base + st * 64 * A_LDS;
        __half* Bd = Bs_base + st * 32 * B_LDS;
        int k0 = kt * 32;
        cp_async16((unsigned)__cvta_generic_to_shared(Ad + arA * A_LDS + acA),
                   Ah + (size_t)(brow + arA) * FIN + k0 + acA);
#pragma unroll
        for (int l = 0; l < 2; l++) {
            int r = brB + l * 16;
            cp_async16((unsigned)__cvta_generic_to_shared(Bd + r * B_LDS + bcB),
                       Bh + (size_t)(k0 + r) * FTOT + bcol + bcB);
        }
    };

    stage(0, 0);
    asm volatile("cp.async.commit_group;");

#pragma unroll
    for (int it = 0; it < 8; it++) {
        const int cur = it & 1;
        if (it < 7) {
            stage(it + 1, cur ^ 1);
            asm volatile("cp.async.commit_group;");
            asm volatile("cp.async.wait_group 1;");
        } else {
            asm volatile("cp.async.wait_group 0;");
        }
        __syncthreads();
#pragma unroll
        for (int ks = 0; ks < 2; ks++) {
            unsigned a[4], b[4][4];
            asm volatile("ldmatrix.sync.aligned.m8n8.x4.shared.b16 {%0,%1,%2,%3}, [%4];"
                         : "=r"(a[0]), "=r"(a[1]), "=r"(a[2]), "=r"(a[3])
                         : "r"(aAddr[cur] + ks * 32));
#pragma unroll
            for (int j = 0; j < 4; j++)
                asm volatile("ldmatrix.sync.aligned.m8n8.x4.trans.shared.b16 {%0,%1,%2,%3}, [%4];"
                             : "=r"(b[j][0]), "=r"(b[j][1]), "=r"(b[j][2]), "=r"(b[j][3])
                             : "r"(bAddr[cur][j] + ks * 16 * B_LDS * 2));
#pragma unroll
            for (int nj = 0; nj < 8; nj++) {
                const unsigned b0 = b[nj >> 1][(nj & 1) * 2];
                const unsigned b1 = b[nj >> 1][(nj & 1) * 2 + 1];
                asm volatile(
                    "mma.sync.aligned.m16n8k16.row.col.f32.f16.f16.f32 "
                    "{%0,%1,%2,%3}, {%4,%5,%6,%7}, {%8,%9}, {%0,%1,%2,%3};"
                    : "+f"(c[nj][0]), "+f"(c[nj][1]), "+f"(c[nj][2]), "+f"(c[nj][3])
                    : "r"(a[0]), "r"(a[1]), "r"(a[2]), "r"(a[3]), "r"(b0), "r"(b1));
            }
        }
        __syncthreads();
    }

    // epilogue: stage fp16 into Cs overlay
    const int g  = lane >> 2;
    const int tg = lane & 3;
#pragma unroll
    for (int nj = 0; nj < 8; nj++) {
        int r0 = mw + g;
        int cc = nw + nj * 8 + tg * 2;
        *(__half2*)&Cs[r0][cc]     = __floats2half2_rn(c[nj][0], c[nj][1]);
        *(__half2*)&Cs[r0 + 8][cc] = __floats2half2_rn(c[nj][2], c[nj][3]);
    }
    __syncthreads();

    // global stores: 64x128 halfs = 1024 uint4 chunks, 4/thread
#pragma unroll
    for (int l = 0; l < 4; l++) {
        int idx = tid + l * 256;
        int r = idx >> 4, c8 = (idx & 15) * 8;
        *(uint4*)(C + (size_t)(brow + r) * FTOT + bcol + c8) = *(uint4*)&Cs[r][c8];
    }

    // fused attention dots: this block's 128 cols == one head.
    // warp handles rows [warp*8, warp*8+8); lane owns cols lane*4..lane*4+3.
    {
        const int head = blockIdx.x;
        float4 s4 = ((const float4*)att_src)[head * 32 + lane];
        float4 d4 = ((const float4*)att_dst)[head * 32 + lane];
#pragma unroll
        for (int t = 0; t < 8; t++) {
            int rr = warp * 8 + t;
            uint2 hv = *(const uint2*)&Cs[rr][lane * 4];
            float2 h01 = __half22float2(*(__half2*)&hv.x);
            float2 h23 = __half22float2(*(__half2*)&hv.y);
            float ds = h01.x * s4.x + h01.y * s4.y + h23.x * s4.z + h23.y * s4.w;
            float dd = h01.x * d4.x + h01.y * d4.y + h23.x * d4.z + h23.y * d4.w;
#pragma unroll
            for (int o = 16; o > 0; o >>= 1) {
                ds += __shfl_xor_sync(0xffffffffu, ds, o);
                dd += __shfl_xor_sync(0xffffffffu, dd, o);
            }
            if (lane == 0) {
                int row = brow + rr;
                g_as[row * 2 + head] = ds;
                g_ad[row * 2 + head] = dd;
            }
        }
    }
}

// ---------------- layer_a: fp16 HMMA (64x128), BK=32 cp.async pipeline + bias + LN + ReLU ----------------
__global__ __launch_bounds__(256) void hgemm_ln_kernel(
    const __half* __restrict__ Ah,   // g_gath [NN][256]
    const __half* __restrict__ Bh,   // w_a fp16 [256][128]
    const float* __restrict__ bias, const float* __restrict__ gamma,
    const float* __restrict__ beta, float* __restrict__ C) {  // g_l1 [NN][128]
    // pipeline (27648B) and fp32 Cs overlay (64*132*4 = 33792B): take max
    __shared__ __align__(16) char smem_raw[64 * 132 * 4];
    __half* As_base = (__half*)smem_raw;
    __half* Bs_base = As_base + 2 * 64 * A_LDS;
    float (*Cs)[132] = (float(*)[132])smem_raw;

    const int tid  = threadIdx.x;
    const int warp = tid >> 5;
    const int lane = tid & 31;
    const int brow = blockIdx.x * 64;
    const int mw = (warp & 3) * 16;
    const int nw = (warp >> 2) * 64;

    float c[8][4];
#pragma unroll
    for (int nj = 0; nj < 8; nj++)
#pragma unroll
        for (int q = 0; q < 4; q++) c[nj][q] = 0.f;

    unsigned aAddr[2], bAddr[2][4];
#pragma unroll
    for (int st = 0; st < 2; st++) {
        aAddr[st] = (unsigned)__cvta_generic_to_shared(
            As_base + st * 64 * A_LDS + (mw + (lane & 15)) * A_LDS + (lane >> 4) * 8);
#pragma unroll
        for (int j = 0; j < 4; j++)
            bAddr[st][j] = (unsigned)__cvta_generic_to_shared(
                Bs_base + st * 32 * B_LDS + (lane & 15) * B_LDS + nw + j * 16 + (lane >> 4) * 8);
    }

    const int arA = tid >> 2, acA = (tid & 3) * 8;
    const int brB = tid >> 4, bcB = (tid & 15) * 8;

    auto stage = [&](int kt, int st) {
        __half* Ad = As_base + st * 64 * A_LDS;
        __half* Bd = Bs_base + st * 32 * B_LDS;
        int k0 = kt * 32;
        cp_async16((unsigned)__cvta_generic_to_shared(Ad + arA * A_LDS + acA),
                   Ah + (size_t)(brow + arA) * 256 + k0 + acA);
#pragma unroll
        for (int l = 0; l < 2; l++) {
            int r = brB + l * 16;
            cp_async16((unsigned)__cvta_generic_to_shared(Bd + r * B_LDS + bcB),
                       Bh + (size_t)(k0 + r) * 128 + bcB);
        }
    };

    stage(0, 0);
    asm volatile("cp.async.commit_group;");

#pragma unroll
    for (int it = 0; it < 8; it++) {
        const int cur = it & 1;
        if (it < 7) {
            stage(it + 1, cur ^ 1);
            asm volatile("cp.async.commit_group;");
            asm volatile("cp.async.wait_group 1;");
        } else {
            asm volatile("cp.async.wait_group 0;");
        }
        __syncthreads();
#pragma unroll
        for (int ks = 0; ks < 2; ks++) {
            unsigned a[4], b[4][4];
            asm volatile("ldmatrix.sync.aligned.m8n8.x4.shared.b16 {%0,%1,%2,%3}, [%4];"
                         : "=r"(a[0]), "=r"(a[1]), "=r"(a[2]), "=r"(a[3])
                         : "r"(aAddr[cur] + ks * 32));
#pragma unroll
            for (int j = 0; j < 4; j++)
                asm volatile("ldmatrix.sync.aligned.m8n8.x4.trans.shared.b16 {%0,%1,%2,%3}, [%4];"
                             : "=r"(b[j][0]), "=r"(b[j][1]), "=r"(b[j][2]), "=r"(b[j][3])
                             : "r"(bAddr[cur][j] + ks * 16 * B_LDS * 2));
#pragma unroll
            for (int nj = 0; nj < 8; nj++) {
                const unsigned b0 = b[nj >> 1][(nj & 1) * 2];
                const unsigned b1 = b[nj >> 1][(nj & 1) * 2 + 1];
                asm volatile(
                    "mma.sync.aligned.m16n8k16.row.col.f32.f16.f16.f32 "
                    "{%0,%1,%2,%3}, {%4,%5,%6,%7}, {%8,%9}, {%0,%1,%2,%3};"
                    : "+f"(c[nj][0]), "+f"(c[nj][1]), "+f"(c[nj][2]), "+f"(c[nj][3])
                    : "r"(a[0]), "r"(a[1]), "r"(a[2]), "r"(a[3]), "r"(b0), "r"(b1));
            }
        }
        __syncthreads();
    }

    // stage fp32 accumulators into Cs overlay
    const int g  = lane >> 2;
    const int tg = lane & 3;
#pragma unroll
    for (int nj = 0; nj < 8; nj++) {
        int r0 = mw + g;
        int cc = nw + nj * 8 + tg * 2;
        Cs[r0][cc]     = c[nj][0]; Cs[r0][cc + 1]     = c[nj][1];
        Cs[r0 + 8][cc] = c[nj][2]; Cs[r0 + 8][cc + 1] = c[nj][3];
    }
    __syncthreads();

    // LN + ReLU: warp per row
    const int c0 = lane * 4;
    float4 bi4 = *(const float4*)(bias + c0);
    float4 g4  = *(const float4*)(gamma + c0);
    float4 be4 = *(const float4*)(beta + c0);
    for (int rr = warp; rr < 64; rr += 8) {
        float v0 = Cs[rr][c0]     + bi4.x;
        float v1 = Cs[rr][c0 + 1] + bi4.y;
        float v2 = Cs[rr][c0 + 2] + bi4.z;
        float v3 = Cs[rr][c0 + 3] + bi4.w;
        float s = v0 + v1 + v2 + v3;
#pragma unroll
        for (int o = 16; o > 0; o >>= 1) s += __shfl_xor_sync(0xffffffffu, s, o);
        float mu = s * (1.f / 128.f);
        float d0 = v0 - mu, d1 = v1 - mu, d2 = v2 - mu, d3 = v3 - mu;
        float sq = d0 * d0 + d1 * d1 + d2 * d2 + d3 * d3;
#pragma unroll
        for (int o = 16; o > 0; o >>= 1) sq += __shfl_xor_sync(0xffffffffu, sq, o);
        float inv = rsqrtf(sq * (1.f / 128.f) + LN_EPS);
        float4 y;
        y.x = fmaxf(d0 * inv * g4.x + be4.x, 0.f);
        y.y = fmaxf(d1 * inv * g4.y + be4.y, 0.f);
        y.z = fmaxf(d2 * inv * g4.z + be4.z, 0.f);
        y.w = fmaxf(d3 * inv * g4.w + be4.w, 0.f);
        *(float4*)(C + (size_t)(brow + rr) * 128 + c0) = y;
    }
}

// ---------------- fused fp32 GEMM + bias + LN + ReLU [+ 32->3 proj] (small layers) ----------------
template <int BM, int N, int K, int TM, bool PROJ>
__global__ void fused_gemm_ln_kernel(
    const float* __restrict__ A, const float* __restrict__ W,
    const float* __restrict__ bias, const float* __restrict__ gamma,
    const float* __restrict__ beta, float* __restrict__ C,
    const float* __restrict__ w3, const float* __restrict__ b3,
    float* __restrict__ Z) {
    constexpr int LX = N / 4;
    constexpr int THREADS = (BM / TM) * LX;
    __shared__ float As[16][BM + 4];
    __shared__ float Ws[16][N];
    __shared__ float w3s[96];
    __shared__ float b3s[3];
    const int tid = threadIdx.x;
    const int tx  = tid % LX;
    const int ty  = tid / LX;
    const int brow = blockIdx.x * BM;

    if (PROJ) {
        for (int i = tid; i < 96; i += THREADS) w3s[i] = w3[i];
        if (tid < 3) b3s[tid] = b3[tid];
    }

    float2 acc2[TM][2];
#pragma unroll
    for (int m = 0; m < TM; m++) { acc2[m][0] = make_float2(0.f, 0.f); acc2[m][1] = make_float2(0.f, 0.f); }

    for (int k0 = 0; k0 < K; k0 += 16) {
#pragma unroll
        for (int i = tid; i < BM * 4; i += THREADS) {
            int r = i >> 2, c4 = (i & 3) * 4;
            float4 v = *(const float4*)(A + (size_t)(brow + r) * K + k0 + c4);
            As[c4 + 0][r] = v.x; As[c4 + 1][r] = v.y;
            As[c4 + 2][r] = v.z; As[c4 + 3][r] = v.w;
        }
#pragma unroll
        for (int i = tid; i < N * 4; i += THREADS) {
            int r = i / (N / 4), c4 = (i % (N / 4)) * 4;
            *(float4*)&Ws[r][c4] = *(const float4*)(W + (size_t)(k0 + r) * N + c4);
        }
        __syncthreads();
#pragma unroll
        for (int k = 0; k < 16; k++) {
            float ar[TM];
#pragma unroll
            for (int q = 0; q < TM / 4; q++)
                *(float4*)&ar[q * 4] = *(float4*)&As[k][ty * TM + q * 4];
            float4 b4 = *(float4*)&Ws[k][tx * 4];
            float2 br0 = make_float2(b4.x, b4.y);
            float2 br1 = make_float2(b4.z, b4.w);
#pragma unroll
            for (int m = 0; m < TM; m++) {
                ffma2(acc2[m][0], ar[m], br0);
                ffma2(acc2[m][1], ar[m], br1);
            }
        }
        __syncthreads();
    }

    const int c0 = tx * 4;
    float4 bi4 = *(const float4*)(bias + c0);
    float4 g4  = *(const float4*)(gamma + c0);
    float4 be4 = *(const float4*)(beta + c0);

#pragma unroll
    for (int m = 0; m < TM; m++) {
        float v0 = acc2[m][0].x + bi4.x;
        float v1 = acc2[m][0].y + bi4.y;
        float v2 = acc2[m][1].x + bi4.z;
        float v3 = acc2[m][1].y + bi4.w;
        float s = v0 + v1 + v2 + v3;
#pragma unroll
        for (int o = LX >> 1; o > 0; o >>= 1) s += __shfl_xor_sync(0xffffffffu, s, o);
        float mu = s * (1.f / N);
        float d0 = v0 - mu, d1 = v1 - mu, d2 = v2 - mu, d3 = v3 - mu;
        float sq = d0 * d0 + d1 * d1 + d2 * d2 + d3 * d3;
#pragma unroll
        for (int o = LX >> 1; o > 0; o >>= 1) sq += __shfl_xor_sync(0xffffffffu, sq, o);
        float inv = rsqrtf(sq * (1.f / N) + LN_EPS);
        float y0 = fmaxf(d0 * inv * g4.x + be4.x, 0.f);
        float y1 = fmaxf(d1 * inv * g4.y + be4.y, 0.f);
        float y2 = fmaxf(d2 * inv * g4.z + be4.z, 0.f);
        float y3 = fmaxf(d3 * inv * g4.w + be4.w, 0.f);
        int row = brow + ty * TM + m;
        if (!PROJ) {
            float4 v; v.x = y0; v.y = y1; v.z = y2; v.w = y3;
            *(float4*)(C + (size_t)row * N + c0) = v;
        } else {
            float p0 = y0 * w3s[(c0 + 0) * 3 + 0] + y1 * w3s[(c0 + 1) * 3 + 0] +
                       y2 * w3s[(c0 + 2) * 3 + 0] + y3 * w3s[(c0 + 3) * 3 + 0];
            float p1 = y0 * w3s[(c0 + 0) * 3 + 1] + y1 * w3s[(c0 + 1) * 3 + 1] +
                       y2 * w3s[(c0 + 2) * 3 + 1] + y3 * w3s[(c0 + 3) * 3 + 1];
            float p2 = y0 * w3s[(c0 + 0) * 3 + 2] + y1 * w3s[(c0 + 1) * 3 + 2] +
                       y2 * w3s[(c0 + 2) * 3 + 2] + y3 * w3s[(c0 + 3) * 3 + 2];
#pragma unroll
            for (int o = LX >> 1; o > 0; o >>= 1) {
                p0 += __shfl_xor_sync(0xffffffffu, p0, o);
                p1 += __shfl_xor_sync(0xffffffffu, p1, o);
                p2 += __shfl_xor_sync(0xffffffffu, p2, o);
            }
            if (tx == 0) {
                Z[row * 3 + 0] = p0 + b3s[0];
                Z[row * 3 + 1] = p1 + b3s[1];
                Z[row * 3 + 2] = p2 + b3s[2];
            }
        }
    }
}

// ---------------- bucket CSR ----------------
__global__ void bucket_init_kernel() {
    int i = blockIdx.x * blockDim.x + threadIdx.x;
    if (i < NN) {
        g_deg[i] = 1;
        g_srt[i * CAP] = i;
    }
}

__global__ void bucket_scatter_kernel(const int* __restrict__ ei) {
    int id = blockIdx.x * blockDim.x + threadIdx.x;
    if (id >= EE / 4) return;
    int4 s = *(const int4*)&ei[id * 4];
    int4 d = *(const int4*)&ei[EE + id * 4];
    int p;
    p = atomicAdd(&g_deg[d.x], 1); if (p < CAP) g_srt[d.x * CAP + p] = s.x;
    p = atomicAdd(&g_deg[d.y], 1); if (p < CAP) g_srt[d.y * CAP + p] = s.y;
    p = atomicAdd(&g_deg[d.z], 1); if (p < CAP) g_srt[d.z * CAP + p] = s.z;
    p = atomicAdd(&g_deg[d.w], 1); if (p < CAP) g_srt[d.w * CAP + p] = s.w;
}

// ---------------- GAT softmax + aggregation (fp16 h in, fp16 out) ----------------
__global__ __launch_bounds__(64) void gat_agg_kernel(const float* __restrict__ bias) {
    const int dst = blockIdx.x;
    const int tid = threadIdx.x;
    const int start = dst * CAP;
    const int deg   = min(g_deg[dst], CAP);
    const float ad0 = g_ad[dst * 2], ad1 = g_ad[dst * 2 + 1];

    __shared__ int   sh_s[CAP];
    __shared__ float sh_w0[CAP];
    __shared__ float sh_w1[CAP];
    __shared__ float rsum[4];

    float s0 = 0.f, s1 = 0.f;
    for (int i = tid; i < deg; i += 64) {
        int s = g_srt[start + i];
        float2 av = ((const float2*)g_as)[s];
        float e0 = av.x + ad0; e0 = e0 > 0.f ? e0 : NEG_SLOPE * e0;
        float e1 = av.y + ad1; e1 = e1 > 0.f ? e1 : NEG_SLOPE * e1;
        float w0 = __expf(e0);
        float w1 = __expf(e1);
        sh_s[i]  = s;
        sh_w0[i] = w0;
        sh_w1[i] = w1;
        s0 += w0; s1 += w1;
    }
    __syncthreads();

    const int c0 = 4 * tid;
    const float* shw = (tid >= 32) ? sh_w1 : sh_w0;
    float2 accA = make_float2(0.f, 0.f);
    float2 accB = make_float2(0.f, 0.f);
    const __half* hbase = &g_hh[c0];

#pragma unroll 8
    for (int i = 0; i < deg; i++) {
        float w = shw[i];
        uint2 v = *(const uint2*)(hbase + (size_t)sh_s[i] * FTOT);
        float2 f01 = __half22float2(*(__half2*)&v.x);
        float2 f23 = __half22float2(*(__half2*)&v.y);
        ffma2(accA, w, f01);
        ffma2(accB, w, f23);
    }

#pragma unroll
    for (int o = 16; o > 0; o >>= 1) {
        s0 += __shfl_xor_sync(0xffffffffu, s0, o);
        s1 += __shfl_xor_sync(0xffffffffu, s1, o);
    }
    if ((tid & 31) == 0) { rsum[(tid >> 5) * 2] = s0; rsum[(tid >> 5) * 2 + 1] = s1; }
    __syncthreads();
    float t0 = rsum[0] + rsum[2];
    float t1 = rsum[1] + rsum[3];
    float inv = (tid >= 32) ? (1.f / (t1 + 1e-16f)) : (1.f / (t0 + 1e-16f));

    float4 bi = *(const float4*)(bias + c0);
    float o0 = fmaxf(accA.x * inv + bi.x, 0.f);
    float o1 = fmaxf(accA.y * inv + bi.y, 0.f);
    float o2 = fmaxf(accB.x * inv + bi.z, 0.f);
    float o3 = fmaxf(accB.y * inv + bi.w, 0.f);
    __half2 h0 = __floats2half2_rn(o0, o1);
    __half2 h1 = __floats2half2_rn(o2, o3);
    uint2 u;
    u.x = *(unsigned*)&h0;
    u.y = *(unsigned*)&h1;
    *(uint2*)&g_gath[(size_t)dst * 256 + c0] = u;
}

// ---------------- pairwise distances, streaming stores, MUFU sqrt ----------------
#define CD_I 64
#define CD_J 1024
__global__ __launch_bounds__(256) void cdist_kernel(float* __restrict__ out) {
    __shared__ float zi[CD_I * 3];
    int ibase = blockIdx.y * CD_I;
    int jbase = blockIdx.x * CD_J;
    for (int t = threadIdx.x; t < CD_I * 3; t += 256) zi[t] = g_z[ibase * 3 + t];

    int j0 = jbase + threadIdx.x * 4;
    float4 p0 = *(const float4*)(g_z + (size_t)j0 * 3);
    float4 p1 = *(const float4*)(g_z + (size_t)j0 * 3 + 4);
    float4 p2 = *(const float4*)(g_z + (size_t)j0 * 3 + 8);
    float jx[4] = {p0.x, p0.w, p1.z, p2.y};
    float jy[4] = {p0.y, p1.x, p1.w, p2.z};
    float jz[4] = {p0.z, p1.y, p2.x, p2.w};
    __syncthreads();

#pragma unroll 4
    for (int ii = 0; ii < CD_I; ii++) {
        float zx = zi[ii * 3], zy = zi[ii * 3 + 1], zz = zi[ii * 3 + 2];
        float r[4];
#pragma unroll
        for (int t = 0; t < 4; t++) {
            float dx = zx - jx[t];
            float dy = zy - jy[t];
            float dz = zz - jz[t];
            float d2 = dx * dx + dy * dy + dz * dz;
            r[t] = d2 > 0.f ? d2 * rsqrtf(d2) : 0.f;
        }
        float* ptr = out + (size_t)(ibase + ii) * NN + j0;
        asm volatile("st.global.cs.v4.f32 [%0], {%1, %2, %3, %4};"
                     :: "l"(ptr), "f"(r[0]), "f"(r[1]), "f"(r[2]), "f"(r[3])
                     : "memory");
    }
}

// ---------------- host launcher ----------------
extern "C" void kernel_launch(void* const* d_in, const int* in_sizes, int n_in,
                              void* d_out, int out_size) {
    const float* x        = (const float*)d_in[0];
    const int*   ei       = (const int*)  d_in[1];
    const float* W_gat    = (const float*)d_in[2];
    const float* att_src  = (const float*)d_in[3];
    const float* att_dst  = (const float*)d_in[4];
    const float* bias_gat = (const float*)d_in[5];
    const float* w_a  = (const float*)d_in[6];
    const float* b_a  = (const float*)d_in[7];
    const float* g_a  = (const float*)d_in[8];
    const float* be_a = (const float*)d_in[9];
    const float* w1   = (const float*)d_in[10];
    const float* b1   = (const float*)d_in[11];
    const float* g1   = (const float*)d_in[12];
    const float* be1  = (const float*)d_in[13];
    const float* w2   = (const float*)d_in[14];
    const float* b2   = (const float*)d_in[15];
    const float* g2   = (const float*)d_in[16];
    const float* be2  = (const float*)d_in[17];
    const float* w3   = (const float*)d_in[18];
    const float* b3   = (const float*)d_in[19];
    float* out = (float*)d_out;

    void* p;
    cudaGetSymbolAddress(&p, g_xh);   __half* pxh  = (__half*)p;
    cudaGetSymbolAddress(&p, g_wh);   __half* pwh  = (__half*)p;
    cudaGetSymbolAddress(&p, g_w1h);  __half* pw1h = (__half*)p;
    cudaGetSymbolAddress(&p, g_hh);   __half* phh  = (__half*)p;
    cudaGetSymbolAddress(&p, g_gath); __half* pgath= (__half*)p;
    cudaGetSymbolAddress(&p, g_l1);   float* pl1   = (float*)p;
    cudaGetSymbolAddress(&p, g_l2);   float* pl2   = (float*)p;
    cudaGetSymbolAddress(&p, g_z);    float* pz    = (float*)p;

    static cudaStream_t s2 = nullptr;
    static cudaEvent_t evFork = nullptr, evJoin = nullptr;
    static bool tried = false;
    if (!tried) {
        tried = true;
        if (cudaStreamCreateWithFlags(&s2, cudaStreamNonBlocking) != cudaSuccess) s2 = nullptr;
        if (s2) {
            if (cudaEventCreateWithFlags(&evFork, cudaEventDisableTiming) != cudaSuccess ||
                cudaEventCreateWithFlags(&evJoin, cudaEventDisableTiming) != cudaSuccess) {
                s2 = nullptr;
            }
        }
    }

    const int CVT_TOT = X4 + W4 + WA4;
    if (s2) {
        cudaEventRecord(evFork, 0);
        cudaStreamWaitEvent(s2, evFork, 0);
        bucket_init_kernel<<<NN / 256, 256, 0, s2>>>();
        bucket_scatter_kernel<<<EE / 4 / 256, 256, 0, s2>>>(ei);
        cudaEventRecord(evJoin, s2);

        cvt_all_kernel<<<(CVT_TOT + 255) / 256, 256>>>(x, W_gat, w_a);
        hgemm1_kernel<<<dim3(2, NN / 64), 256>>>(pxh, pwh, phh, att_src, att_dst);

        cudaStreamWaitEvent(0, evJoin, 0);
    } else {
        cvt_all_kernel<<<(CVT_TOT + 255) / 256, 256>>>(x, W_gat, w_a);
        hgemm1_kernel<<<dim3(2, NN / 64), 256>>>(pxh, pwh, phh, att_src, att_dst);
        bucket_init_kernel<<<NN / 256, 256>>>();
        bucket_scatter_kernel<<<EE / 4 / 256, 256>>>(ei);
    }

    // segment softmax + aggregation + bias + relu -> fp16
    gat_agg_kernel<<<NN, 64>>>(bias_gat);

    // layer_a: HMMA gemm + bias + LN + ReLU (cp.async pipelined)
    hgemm_ln_kernel<<<NN / 64, 256>>>(pgath, pw1h, b_a, g_a, be_a, pl1);

    // remaining MLP (fp32 FFMA2) + final projection
    fused_gemm_ln_kernel<128, 64, 128, 8, false><<<NN / 128, 256>>>(
        pl1, w1, b1, g1, be1, pl2, nullptr, nullptr, nullptr);
    fused_gemm_ln_kernel<128, 32, 64, 8, true><<<NN / 128, 128>>>(
        pl2, w2, b2, g2, be2, nullptr, w3, b3, pz);

    // pairwise distance matrix
    cdist_kernel<<<dim3(NN / CD_J, NN / CD_I), 256>>>(out);
}

// round 13
// speedup vs baseline: 1.5692x; 1.0475x over previous
#include <cuda_runtime.h>
#include <cuda_fp16.h>
#include <math.h>

#define NN   8192
#define EE   524288
#define FIN  256
#define FTOT 256      // H * F_OUT
#define FOUT 128
#define CAP  256      // per-node bucket capacity (mean deg = 65, Poisson)
#define LN_EPS   1e-5f
#define NEG_SLOPE 0.2f

// ---------------- scratch (__device__ globals; no allocation allowed) ----------------
__device__ __align__(16) __half g_wh[FIN * FTOT];   // W_gat in fp16
__device__ __align__(16) __half g_w1h[256 * 128];   // w_a in fp16
__device__ __align__(16) __half g_hh[NN * FTOT];    // x @ W_gat, fp16
__device__ __align__(16) __half g_gath[NN * 256];   // GAT output (relu), fp16
__device__ __align__(16) float g_as[NN * 2];
__device__ __align__(16) float g_ad[NN * 2];
__device__ int   g_deg[NN];
__device__ int   g_srt[NN * CAP];
__device__ __align__(16) float g_l1[NN * 128];
__device__ __align__(16) float g_z[NN * 3];

// ---------------- packed fp32x2 FMA ----------------
__device__ __forceinline__ void ffma2(float2& c, float a, const float2& b) {
    float2 av = make_float2(a, a);
    unsigned long long ua = *reinterpret_cast<unsigned long long*>(&av);
    unsigned long long ub = *reinterpret_cast<const unsigned long long*>(&b);
    unsigned long long uc = *reinterpret_cast<unsigned long long*>(&c);
    asm("fma.rn.f32x2 %0, %1, %2, %0;" : "+l"(uc) : "l"(ua), "l"(ub));
    c = *reinterpret_cast<float2*>(&uc);
}

__device__ __forceinline__ void cp_async16(unsigned smem_dst, const void* gmem_src) {
    asm volatile("cp.async.cg.shared.global [%0], [%1], 16;" :: "r"(smem_dst), "l"(gmem_src));
}

// ---------------- fp32 -> fp16 conversion of W_gat, w_a (weights only) ----------------
#define W4  (FIN * FTOT / 4)        // 16384
#define WA4 (256 * 128 / 4)         // 8192
__global__ void cvt_w_kernel(const float* __restrict__ W,
                             const float* __restrict__ wa) {
    int i = blockIdx.x * blockDim.x + threadIdx.x;
    const float* src; __half* dst; int j;
    if (i < W4)            { src = W;  dst = g_wh;  j = i; }
    else if (i < W4 + WA4) { src = wa; dst = g_w1h; j = i - W4; }
    else return;
    float4 v = ((const float4*)src)[j];
    __half2 h0 = __floats2half2_rn(v.x, v.y);
    __half2 h1 = __floats2half2_rn(v.z, v.w);
    uint2 u;
    u.x = *(unsigned*)&h0;
    u.y = *(unsigned*)&h1;
    ((uint2*)dst)[j] = u;
}

#define A_LDS 40   // 32 + 8 pad halfs (80B rows, 16B-aligned)
#define B_LDS 136  // 128 + 8 pad halfs (272B rows)

// ---------------- gemm1: fp32 x read directly (convert in staging), fp16 HMMA,
//                  64x128 tile, BK=32, cp.async(B)/reg-staged(A) pipeline,
//                  fused attention dots from the fp16 epilogue staging buffer ----------------
__global__ __launch_bounds__(256) void hgemm1_kernel(
    const float* __restrict__ Ax,    // x fp32 [NN][256]
    const __half* __restrict__ Bh,   // W_gat fp16 [256][256]
    __half* __restrict__ C,          // h fp16 [NN][256]
    const float* __restrict__ att_src,
    const float* __restrict__ att_dst) {
    __shared__ __align__(16) char smem_raw[2 * 64 * A_LDS * 2 + 2 * 32 * B_LDS * 2];
    __half* As_base = (__half*)smem_raw;
    __half* Bs_base = As_base + 2 * 64 * A_LDS;
    __half (*Cs)[B_LDS] = (__half(*)[B_LDS])smem_raw;   // epilogue overlay [64][136]

    const int tid  = threadIdx.x;
    const int warp = tid >> 5;
    const int lane = tid & 31;
    const int brow = blockIdx.y * 64;
    const int bcol = blockIdx.x * 128;   // head = blockIdx.x
    const int mw = (warp & 3) * 16;
    const int nw = (warp >> 2) * 64;

    float c[8][4];
#pragma unroll
    for (int nj = 0; nj < 8; nj++)
#pragma unroll
        for (int q = 0; q < 4; q++) c[nj][q] = 0.f;

    unsigned aAddr[2], bAddr[2][4];
#pragma unroll
    for (int st = 0; st < 2; st++) {
        aAddr[st] = (unsigned)__cvta_generic_to_shared(
            As_base + st * 64 * A_LDS + (mw + (lane & 15)) * A_LDS + (lane >> 4) * 8);
#pragma unroll
        for (int j = 0; j < 4; j++)
            bAddr[st][j] = (unsigned)__cvta_generic_to_shared(
                Bs_base + st * 32 * B_LDS + (lane & 15) * B_LDS + nw + j * 16 + (lane >> 4) * 8);
    }

    // A staging: 64x32 fp32 tile, thread handles row tid>>2, cols (tid&3)*8 .. +8
    const int arA = tid >> 2, acA = (tid & 3) * 8;
    // B staging: 32x128 fp16 tile via cp.async, 2 chunks/thread
    const int brB = tid >> 4, bcB = (tid & 15) * 8;

    float4 va0, va1;   // fp32 A registers for the in-flight tile
    auto ldgA = [&](int kt) {
        const float* src = Ax + (size_t)(brow + arA) * FIN + kt * 32 + acA;
        va0 = *(const float4*)src;
        va1 = *(const float4*)(src + 4);
    };
    auto stsA = [&](int st) {
        __half2 h[4];
        h[0] = __floats2half2_rn(va0.x, va0.y);
        h[1] = __floats2half2_rn(va0.z, va0.w);
        h[2] = __floats2half2_rn(va1.x, va1.y);
        h[3] = __floats2half2_rn(va1.z, va1.w);
        *(uint4*)(As_base + st * 64 * A_LDS + arA * A_LDS + acA) = *(uint4*)h;
    };
    auto cpB = [&](int kt, int st) {
        __half* Bd = Bs_base + st * 32 * B_LDS;
        int k0 = kt * 32;
#pragma unroll
        for (int l = 0; l < 2; l++) {
            int r = brB + l * 16;
            cp_async16((unsigned)__cvta_generic_to_shared(Bd + r * B_LDS + bcB),
                       Bh + (size_t)(k0 + r) * FTOT + bcol + bcB);
        }
    };

    // prologue
    ldgA(0); cpB(0, 0);
    asm volatile("cp.async.commit_group;");
    stsA(0);
    asm volatile("cp.async.wait_group 0;");
    __syncthreads();

#pragma unroll
    for (int it = 0; it < 8; it++) {
        const int cur = it & 1;
        if (it < 7) {
            ldgA(it + 1);                 // LDG in flight during MMAs below
            cpB(it + 1, cur ^ 1);
            asm volatile("cp.async.commit_group;");
        }
#pragma unroll
        for (int ks = 0; ks < 2; ks++) {
            unsigned a[4], b[4][4];
            asm volatile("ldmatrix.sync.aligned.m8n8.x4.shared.b16 {%0,%1,%2,%3}, [%4];"
                         : "=r"(a[0]), "=r"(a[1]), "=r"(a[2]), "=r"(a[3])
                         : "r"(aAddr[cur] + ks * 32));
#pragma unroll
            for (int j = 0; j < 4; j++)
                asm volatile("ldmatrix.sync.aligned.m8n8.x4.trans.shared.b16 {%0,%1,%2,%3}, [%4];"
                             : "=r"(b[j][0]), "=r"(b[j][1]), "=r"(b[j][2]), "=r"(b[j][3])
                             : "r"(bAddr[cur][j] + ks * 16 * B_LDS * 2));
#pragma unroll
            for (int nj = 0; nj < 8; nj++) {
                const unsigned b0 = b[nj >> 1][(nj & 1) * 2];
                const unsigned b1 = b[nj >> 1][(nj & 1) * 2 + 1];
                asm volatile(
                    "mma.sync.aligned.m16n8k16.row.col.f32.f16.f16.f32 "
                    "{%0,%1,%2,%3}, {%4,%5,%6,%7}, {%8,%9}, {%0,%1,%2,%3};"
                    : "+f"(c[nj][0]), "+f"(c[nj][1]), "+f"(c[nj][2]), "+f"(c[nj][3])
                    : "r"(a[0]), "r"(a[1]), "r"(a[2]), "r"(a[3]), "r"(b0), "r"(b1));
            }
        }
        if (it < 7) {
            stsA(cur ^ 1);
            asm volatile("cp.async.wait_group 0;");
        }
        __syncthreads();
    }

    // epilogue: stage fp16 into Cs overlay
    const int g  = lane >> 2;
    const int tg = lane & 3;
#pragma unroll
    for (int nj = 0; nj < 8; nj++) {
        int r0 = mw + g;
        int cc = nw + nj * 8 + tg * 2;
        *(__half2*)&Cs[r0][cc]     = __floats2half2_rn(c[nj][0], c[nj][1]);
        *(__half2*)&Cs[r0 + 8][cc] = __floats2half2_rn(c[nj][2], c[nj][3]);
    }
    __syncthreads();

#pragma unroll
    for (int l = 0; l < 4; l++) {
        int idx = tid + l * 256;
        int r = idx >> 4, c8 = (idx & 15) * 8;
        *(uint4*)(C + (size_t)(brow + r) * FTOT + bcol + c8) = *(uint4*)&Cs[r][c8];
    }

    // fused attention dots (this block's 128 cols == one head)
    {
        const int head = blockIdx.x;
        float4 s4 = ((const float4*)att_src)[head * 32 + lane];
        float4 d4 = ((const float4*)att_dst)[head * 32 + lane];
#pragma unroll
        for (int t = 0; t < 8; t++) {
            int rr = warp * 8 + t;
            uint2 hv = *(const uint2*)&Cs[rr][lane * 4];
            float2 h01 = __half22float2(*(__half2*)&hv.x);
            float2 h23 = __half22float2(*(__half2*)&hv.y);
            float ds = h01.x * s4.x + h01.y * s4.y + h23.x * s4.z + h23.y * s4.w;
            float dd = h01.x * d4.x + h01.y * d4.y + h23.x * d4.z + h23.y * d4.w;
#pragma unroll
            for (int o = 16; o > 0; o >>= 1) {
                ds += __shfl_xor_sync(0xffffffffu, ds, o);
                dd += __shfl_xor_sync(0xffffffffu, dd, o);
            }
            if (lane == 0) {
                int row = brow + rr;
                g_as[row * 2 + head] = ds;
                g_ad[row * 2 + head] = dd;
            }
        }
    }
}

// ---------------- layer_a: fp16 HMMA (64x128), BK=32 cp.async pipeline + bias + LN + ReLU ----------------
__global__ __launch_bounds__(256) void hgemm_ln_kernel(
    const __half* __restrict__ Ah,   // g_gath [NN][256]
    const __half* __restrict__ Bh,   // w_a fp16 [256][128]
    const float* __restrict__ bias, const float* __restrict__ gamma,
    const float* __restrict__ beta, float* __restrict__ C) {  // g_l1 [NN][128]
    __shared__ __align__(16) char smem_raw[64 * 132 * 4];
    __half* As_base = (__half*)smem_raw;
    __half* Bs_base = As_base + 2 * 64 * A_LDS;
    float (*Cs)[132] = (float(*)[132])smem_raw;

    const int tid  = threadIdx.x;
    const int warp = tid >> 5;
    const int lane = tid & 31;
    const int brow = blockIdx.x * 64;
    const int mw = (warp & 3) * 16;
    const int nw = (warp >> 2) * 64;

    float c[8][4];
#pragma unroll
    for (int nj = 0; nj < 8; nj++)
#pragma unroll
        for (int q = 0; q < 4; q++) c[nj][q] = 0.f;

    unsigned aAddr[2], bAddr[2][4];
#pragma unroll
    for (int st = 0; st < 2; st++) {
        aAddr[st] = (unsigned)__cvta_generic_to_shared(
            As_base + st * 64 * A_LDS + (mw + (lane & 15)) * A_LDS + (lane >> 4) * 8);
#pragma unroll
        for (int j = 0; j < 4; j++)
            bAddr[st][j] = (unsigned)__cvta_generic_to_shared(
                Bs_base + st * 32 * B_LDS + (lane & 15) * B_LDS + nw + j * 16 + (lane >> 4) * 8);
    }

    const int arA = tid >> 2, acA = (tid & 3) * 8;
    const int brB = tid >> 4, bcB = (tid & 15) * 8;

    auto stage = [&](int kt, int st) {
        __half* Ad = As_base + st * 64 * A_LDS;
        __half* Bd = Bs_base + st * 32 * B_LDS;
        int k0 = kt * 32;
        cp_async16((unsigned)__cvta_generic_to_shared(Ad + arA * A_LDS + acA),
                   Ah + (size_t)(brow + arA) * 256 + k0 + acA);
#pragma unroll
        for (int l = 0; l < 2; l++) {
            int r = brB + l * 16;
            cp_async16((unsigned)__cvta_generic_to_shared(Bd + r * B_LDS + bcB),
                       Bh + (size_t)(k0 + r) * 128 + bcB);
        }
    };

    stage(0, 0);
    asm volatile("cp.async.commit_group;");

#pragma unroll
    for (int it = 0; it < 8; it++) {
        const int cur = it & 1;
        if (it < 7) {
            stage(it + 1, cur ^ 1);
            asm volatile("cp.async.commit_group;");
            asm volatile("cp.async.wait_group 1;");
        } else {
            asm volatile("cp.async.wait_group 0;");
        }
        __syncthreads();
#pragma unroll
        for (int ks = 0; ks < 2; ks++) {
            unsigned a[4], b[4][4];
            asm volatile("ldmatrix.sync.aligned.m8n8.x4.shared.b16 {%0,%1,%2,%3}, [%4];"
                         : "=r"(a[0]), "=r"(a[1]), "=r"(a[2]), "=r"(a[3])
                         : "r"(aAddr[cur] + ks * 32));
#pragma unroll
            for (int j = 0; j < 4; j++)
                asm volatile("ldmatrix.sync.aligned.m8n8.x4.trans.shared.b16 {%0,%1,%2,%3}, [%4];"
                             : "=r"(b[j][0]), "=r"(b[j][1]), "=r"(b[j][2]), "=r"(b[j][3])
                             : "r"(bAddr[cur][j] + ks * 16 * B_LDS * 2));
#pragma unroll
            for (int nj = 0; nj < 8; nj++) {
                const unsigned b0 = b[nj >> 1][(nj & 1) * 2];
                const unsigned b1 = b[nj >> 1][(nj & 1) * 2 + 1];
                asm volatile(
                    "mma.sync.aligned.m16n8k16.row.col.f32.f16.f16.f32 "
                    "{%0,%1,%2,%3}, {%4,%5,%6,%7}, {%8,%9}, {%0,%1,%2,%3};"
                    : "+f"(c[nj][0]), "+f"(c[nj][1]), "+f"(c[nj][2]), "+f"(c[nj][3])
                    : "r"(a[0]), "r"(a[1]), "r"(a[2]), "r"(a[3]), "r"(b0), "r"(b1));
            }
        }
        __syncthreads();
    }

    const int g  = lane >> 2;
    const int tg = lane & 3;
#pragma unroll
    for (int nj = 0; nj < 8; nj++) {
        int r0 = mw + g;
        int cc = nw + nj * 8 + tg * 2;
        Cs[r0][cc]     = c[nj][0]; Cs[r0][cc + 1]     = c[nj][1];
        Cs[r0 + 8][cc] = c[nj][2]; Cs[r0 + 8][cc + 1] = c[nj][3];
    }
    __syncthreads();

    const int c0 = lane * 4;
    float4 bi4 = *(const float4*)(bias + c0);
    float4 g4  = *(const float4*)(gamma + c0);
    float4 be4 = *(const float4*)(beta + c0);
    for (int rr = warp; rr < 64; rr += 8) {
        float v0 = Cs[rr][c0]     + bi4.x;
        float v1 = Cs[rr][c0 + 1] + bi4.y;
        float v2 = Cs[rr][c0 + 2] + bi4.z;
        float v3 = Cs[rr][c0 + 3] + bi4.w;
        float s = v0 + v1 + v2 + v3;
#pragma unroll
        for (int o = 16; o > 0; o >>= 1) s += __shfl_xor_sync(0xffffffffu, s, o);
        float mu = s * (1.f / 128.f);
        float d0 = v0 - mu, d1 = v1 - mu, d2 = v2 - mu, d3 = v3 - mu;
        float sq = d0 * d0 + d1 * d1 + d2 * d2 + d3 * d3;
#pragma unroll
        for (int o = 16; o > 0; o >>= 1) sq += __shfl_xor_sync(0xffffffffu, sq, o);
        float inv = rsqrtf(sq * (1.f / 128.f) + LN_EPS);
        float4 y;
        y.x = fmaxf(d0 * inv * g4.x + be4.x, 0.f);
        y.y = fmaxf(d1 * inv * g4.y + be4.y, 0.f);
        y.z = fmaxf(d2 * inv * g4.z + be4.z, 0.f);
        y.w = fmaxf(d3 * inv * g4.w + be4.w, 0.f);
        *(float4*)(C + (size_t)(brow + rr) * 128 + c0) = y;
    }
}

// ---------------- fused tail: (128->64)+LN+ReLU, (64->32)+LN+ReLU, (32->3)+bias -> z ----------------
__global__ __launch_bounds__(256) void fused_tail_kernel(
    const float* __restrict__ A,     // g_l1 [NN][128]
    const float* __restrict__ w1, const float* __restrict__ b1,
    const float* __restrict__ g1, const float* __restrict__ be1,
    const float* __restrict__ w2, const float* __restrict__ b2,
    const float* __restrict__ g2, const float* __restrict__ be2,
    const float* __restrict__ w3, const float* __restrict__ b3,
    float* __restrict__ Z) {
    __shared__ float As[16][68];
    __shared__ float Ws[16][64];
    __shared__ float Ys[64][68];
    __shared__ float w2s[64][32];
    __shared__ float w3s[96];
    __shared__ float b3s[3];
    const int tid = threadIdx.x;
    const int tx  = tid & 15;        // 16 col-groups x 4 = 64 cols
    const int ty  = tid >> 4;        // 16 row-groups x TM=4 = 64 rows
    const int brow = blockIdx.x * 64;

    // preload small weights
    for (int i = tid; i < 64 * 32; i += 256) w2s[i >> 5][i & 31] = w2[i];
    if (tid < 96) w3s[tid] = w3[tid];
    if (tid < 3)  b3s[tid] = b3[tid];

    // ---- layer2: 128 -> 64 (streamed K) ----
    float2 acc2[4][2];
#pragma unroll
    for (int m = 0; m < 4; m++) { acc2[m][0] = make_float2(0.f, 0.f); acc2[m][1] = make_float2(0.f, 0.f); }

    for (int k0 = 0; k0 < 128; k0 += 16) {
        {
            int i = tid;                       // 256 chunks, 1 per thread
            int r = i >> 2, c4 = (i & 3) * 4;
            float4 v = *(const float4*)(A + (size_t)(brow + r) * 128 + k0 + c4);
            As[c4 + 0][r] = v.x; As[c4 + 1][r] = v.y;
            As[c4 + 2][r] = v.z; As[c4 + 3][r] = v.w;
        }
        {
            int i = tid;                       // 256 chunks, 1 per thread
            int r = i >> 4, c4 = (i & 15) * 4;
            *(float4*)&Ws[r][c4] = *(const float4*)(w1 + (size_t)(k0 + r) * 64 + c4);
        }
        __syncthreads();
#pragma unroll
        for (int k = 0; k < 16; k++) {
            float ar[4];
            *(float4*)&ar[0] = *(float4*)&As[k][ty * 4];
            float4 b4 = *(float4*)&Ws[k][tx * 4];
            float2 br0 = make_float2(b4.x, b4.y);
            float2 br1 = make_float2(b4.z, b4.w);
#pragma unroll
            for (int m = 0; m < 4; m++) {
                ffma2(acc2[m][0], ar[m], br0);
                ffma2(acc2[m][1], ar[m], br1);
            }
        }
        __syncthreads();
    }

    // bias + LN(64) + ReLU -> Ys
    {
        const int c0 = tx * 4;
        float4 bi4 = *(const float4*)(b1 + c0);
        float4 g4  = *(const float4*)(g1 + c0);
        float4 be4 = *(const float4*)(be1 + c0);
#pragma unroll
        for (int m = 0; m < 4; m++) {
            float v0 = acc2[m][0].x + bi4.x;
            float v1 = acc2[m][0].y + bi4.y;
            float v2 = acc2[m][1].x + bi4.z;
            float v3 = acc2[m][1].y + bi4.w;
            float s = v0 + v1 + v2 + v3;
#pragma unroll
            for (int o = 8; o > 0; o >>= 1) s += __shfl_xor_sync(0xffffffffu, s, o);
            float mu = s * (1.f / 64.f);
            float d0 = v0 - mu, d1 = v1 - mu, d2 = v2 - mu, d3 = v3 - mu;
            float sq = d0 * d0 + d1 * d1 + d2 * d2 + d3 * d3;
#pragma unroll
            for (int o = 8; o > 0; o >>= 1) sq += __shfl_xor_sync(0xffffffffu, sq, o);
            float inv = rsqrtf(sq * (1.f / 64.f) + LN_EPS);
            float4 y;
            y.x = fmaxf(d0 * inv * g4.x + be4.x, 0.f);
            y.y = fmaxf(d1 * inv * g4.y + be4.y, 0.f);
            y.z = fmaxf(d2 * inv * g4.z + be4.z, 0.f);
            y.w = fmaxf(d3 * inv * g4.w + be4.w, 0.f);
            *(float4*)&Ys[ty * 4 + m][c0] = y;
        }
    }
    __syncthreads();

    // ---- layer3: 64 -> 32, LN(32), ReLU, proj 32 -> 3 ----
    {
        const int tx3 = tid & 7;       // 8 col-groups x 4 = 32 cols
        const int ty3 = tid >> 3;      // 32 row-groups x 2 = 64 rows
        const int c3  = tx3 * 4;
        float4 bi = *(const float4*)(b2 + c3);
        float4 gg = *(const float4*)(g2 + c3);
        float4 bb = *(const float4*)(be2 + c3);
#pragma unroll
        for (int m = 0; m < 2; m++) {
            int r = ty3 * 2 + m;
            float2 a0 = make_float2(0.f, 0.f), a1 = make_float2(0.f, 0.f);
#pragma unroll 8
            for (int k = 0; k < 64; k++) {
                float yv = Ys[r][k];
                ffma2(a0, yv, *(const float2*)&w2s[k][c3]);
                ffma2(a1, yv, *(const float2*)&w2s[k][c3 + 2]);
            }
            float v0 = a0.x + bi.x, v1 = a0.y + bi.y;
            float v2 = a1.x + bi.z, v3 = a1.y + bi.w;
            float s = v0 + v1 + v2 + v3;
#pragma unroll
            for (int o = 4; o > 0; o >>= 1) s += __shfl_xor_sync(0xffffffffu, s, o);
            float mu = s * (1.f / 32.f);
            float d0 = v0 - mu, d1 = v1 - mu, d2 = v2 - mu, d3 = v3 - mu;
            float sq = d0 * d0 + d1 * d1 + d2 * d2 + d3 * d3;
#pragma unroll
            for (int o = 4; o > 0; o >>= 1) sq += __shfl_xor_sync(0xffffffffu, sq, o);
            float inv = rsqrtf(sq * (1.f / 32.f) + LN_EPS);
            float y0 = fmaxf(d0 * inv * gg.x + bb.x, 0.f);
            float y1 = fmaxf(d1 * inv * gg.y + bb.y, 0.f);
            float y2 = fmaxf(d2 * inv * gg.z + bb.z, 0.f);
            float y3 = fmaxf(d3 * inv * gg.w + bb.w, 0.f);
            float p0 = y0 * w3s[(c3 + 0) * 3 + 0] + y1 * w3s[(c3 + 1) * 3 + 0] +
                       y2 * w3s[(c3 + 2) * 3 + 0] + y3 * w3s[(c3 + 3) * 3 + 0];
            float p1 = y0 * w3s[(c3 + 0) * 3 + 1] + y1 * w3s[(c3 + 1) * 3 + 1] +
                       y2 * w3s[(c3 + 2) * 3 + 1] + y3 * w3s[(c3 + 3) * 3 + 1];
            float p2 = y0 * w3s[(c3 + 0) * 3 + 2] + y1 * w3s[(c3 + 1) * 3 + 2] +
                       y2 * w3s[(c3 + 2) * 3 + 2] + y3 * w3s[(c3 + 3) * 3 + 2];
#pragma unroll
            for (int o = 4; o > 0; o >>= 1) {
                p0 += __shfl_xor_sync(0xffffffffu, p0, o);
                p1 += __shfl_xor_sync(0xffffffffu, p1, o);
                p2 += __shfl_xor_sync(0xffffffffu, p2, o);
            }
            if (tx3 == 0) {
                int row = brow + r;
                Z[row * 3 + 0] = p0 + b3s[0];
                Z[row * 3 + 1] = p1 + b3s[1];
                Z[row * 3 + 2] = p2 + b3s[2];
            }
        }
    }
}

// ---------------- bucket CSR ----------------
__global__ void bucket_init_kernel() {
    int i = blockIdx.x * blockDim.x + threadIdx.x;
    if (i < NN) {
        g_deg[i] = 1;
        g_srt[i * CAP] = i;
    }
}

__global__ void bucket_scatter_kernel(const int* __restrict__ ei) {
    int id = blockIdx.x * blockDim.x + threadIdx.x;
    if (id >= EE / 4) return;
    int4 s = *(const int4*)&ei[id * 4];
    int4 d = *(const int4*)&ei[EE + id * 4];
    int p;
    p = atomicAdd(&g_deg[d.x], 1); if (p < CAP) g_srt[d.x * CAP + p] = s.x;
    p = atomicAdd(&g_deg[d.y], 1); if (p < CAP) g_srt[d.y * CAP + p] = s.y;
    p = atomicAdd(&g_deg[d.z], 1); if (p < CAP) g_srt[d.z * CAP + p] = s.z;
    p = atomicAdd(&g_deg[d.w], 1); if (p < CAP) g_srt[d.w * CAP + p] = s.w;
}

// ---------------- GAT softmax + aggregation (fp16 h in, fp16 out) ----------------
__global__ __launch_bounds__(64) void gat_agg_kernel(const float* __restrict__ bias) {
    const int dst = blockIdx.x;
    const int tid = threadIdx.x;
    const int start = dst * CAP;
    const int deg   = min(g_deg[dst], CAP);
    const float ad0 = g_ad[dst * 2], ad1 = g_ad[dst * 2 + 1];

    __shared__ int   sh_s[CAP];
    __shared__ float sh_w0[CAP];
    __shared__ float sh_w1[CAP];
    __shared__ float rsum[4];

    float s0 = 0.f, s1 = 0.f;
    for (int i = tid; i < deg; i += 64) {
        int s = g_srt[start + i];
        float2 av = ((const float2*)g_as)[s];
        float e0 = av.x + ad0; e0 = e0 > 0.f ? e0 : NEG_SLOPE * e0;
        float e1 = av.y + ad1; e1 = e1 > 0.f ? e1 : NEG_SLOPE * e1;
        float w0 = __expf(e0);
        float w1 = __expf(e1);
        sh_s[i]  = s;
        sh_w0[i] = w0;
        sh_w1[i] = w1;
        s0 += w0; s1 += w1;
    }
    __syncthreads();

    const int c0 = 4 * tid;
    const float* shw = (tid >= 32) ? sh_w1 : sh_w0;
    float2 accA = make_float2(0.f, 0.f);
    float2 accB = make_float2(0.f, 0.f);
    const __half* hbase = &g_hh[c0];

#pragma unroll 8
    for (int i = 0; i < deg; i++) {
        float w = shw[i];
        uint2 v = *(const uint2*)(hbase + (size_t)sh_s[i] * FTOT);
        float2 f01 = __half22float2(*(__half2*)&v.x);
        float2 f23 = __half22float2(*(__half2*)&v.y);
        ffma2(accA, w, f01);
        ffma2(accB, w, f23);
    }

#pragma unroll
    for (int o = 16; o > 0; o >>= 1) {
        s0 += __shfl_xor_sync(0xffffffffu, s0, o);
        s1 += __shfl_xor_sync(0xffffffffu, s1, o);
    }
    if ((tid & 31) == 0) { rsum[(tid >> 5) * 2] = s0; rsum[(tid >> 5) * 2 + 1] = s1; }
    __syncthreads();
    float t0 = rsum[0] + rsum[2];
    float t1 = rsum[1] + rsum[3];
    float inv = (tid >= 32) ? (1.f / (t1 + 1e-16f)) : (1.f / (t0 + 1e-16f));

    float4 bi = *(const float4*)(bias + c0);
    float o0 = fmaxf(accA.x * inv + bi.x, 0.f);
    float o1 = fmaxf(accA.y * inv + bi.y, 0.f);
    float o2 = fmaxf(accB.x * inv + bi.z, 0.f);
    float o3 = fmaxf(accB.y * inv + bi.w, 0.f);
    __half2 h0 = __floats2half2_rn(o0, o1);
    __half2 h1 = __floats2half2_rn(o2, o3);
    uint2 u;
    u.x = *(unsigned*)&h0;
    u.y = *(unsigned*)&h1;
    *(uint2*)&g_gath[(size_t)dst * 256 + c0] = u;
}

// ---------------- pairwise distances, streaming stores, MUFU sqrt ----------------
#define CD_I 64
#define CD_J 1024
__global__ __launch_bounds__(256) void cdist_kernel(float* __restrict__ out) {
    __shared__ float zi[CD_I * 3];
    int ibase = blockIdx.y * CD_I;
    int jbase = blockIdx.x * CD_J;
    for (int t = threadIdx.x; t < CD_I * 3; t += 256) zi[t] = g_z[ibase * 3 + t];

    int j0 = jbase + threadIdx.x * 4;
    float4 p0 = *(const float4*)(g_z + (size_t)j0 * 3);
    float4 p1 = *(const float4*)(g_z + (size_t)j0 * 3 + 4);
    float4 p2 = *(const float4*)(g_z + (size_t)j0 * 3 + 8);
    float jx[4] = {p0.x, p0.w, p1.z, p2.y};
    float jy[4] = {p0.y, p1.x, p1.w, p2.z};
    float jz[4] = {p0.z, p1.y, p2.x, p2.w};
    __syncthreads();

#pragma unroll 4
    for (int ii = 0; ii < CD_I; ii++) {
        float zx = zi[ii * 3], zy = zi[ii * 3 + 1], zz = zi[ii * 3 + 2];
        float r[4];
#pragma unroll
        for (int t = 0; t < 4; t++) {
            float dx = zx - jx[t];
            float dy = zy - jy[t];
            float dz = zz - jz[t];
            float d2 = dx * dx + dy * dy + dz * dz;
            r[t] = d2 > 0.f ? d2 * rsqrtf(d2) : 0.f;
        }
        float* ptr = out + (size_t)(ibase + ii) * NN + j0;
        asm volatile("st.global.cs.v4.f32 [%0], {%1, %2, %3, %4};"
                     :: "l"(ptr), "f"(r[0]), "f"(r[1]), "f"(r[2]), "f"(r[3])
                     : "memory");
    }
}

// ---------------- host launcher ----------------
extern "C" void kernel_launch(void* const* d_in, const int* in_sizes, int n_in,
                              void* d_out, int out_size) {
    const float* x        = (const float*)d_in[0];
    const int*   ei       = (const int*)  d_in[1];
    const float* W_gat    = (const float*)d_in[2];
    const float* att_src  = (const float*)d_in[3];
    const float* att_dst  = (const float*)d_in[4];
    const float* bias_gat = (const float*)d_in[5];
    const float* w_a  = (const float*)d_in[6];
    const float* b_a  = (const float*)d_in[7];
    const float* g_a  = (const float*)d_in[8];
    const float* be_a = (const float*)d_in[9];
    const float* w1   = (const float*)d_in[10];
    const float* b1   = (const float*)d_in[11];
    const float* g1   = (const float*)d_in[12];
    const float* be1  = (const float*)d_in[13];
    const float* w2   = (const float*)d_in[14];
    const float* b2   = (const float*)d_in[15];
    const float* g2   = (const float*)d_in[16];
    const float* be2  = (const float*)d_in[17];
    const float* w3   = (const float*)d_in[18];
    const float* b3   = (const float*)d_in[19];
    float* out = (float*)d_out;

    void* p;
    cudaGetSymbolAddress(&p, g_wh);   __half* pwh  = (__half*)p;
    cudaGetSymbolAddress(&p, g_w1h);  __half* pw1h = (__half*)p;
    cudaGetSymbolAddress(&p, g_hh);   __half* phh  = (__half*)p;
    cudaGetSymbolAddress(&p, g_gath); __half* pgath= (__half*)p;
    cudaGetSymbolAddress(&p, g_l1);   float* pl1   = (float*)p;
    cudaGetSymbolAddress(&p, g_z);    float* pz    = (float*)p;

    static cudaStream_t s2 = nullptr;
    static cudaEvent_t evFork = nullptr, evJoin = nullptr;
    static bool tried = false;
    if (!tried) {
        tried = true;
        if (cudaStreamCreateWithFlags(&s2, cudaStreamNonBlocking) != cudaSuccess) s2 = nullptr;
        if (s2) {
            if (cudaEventCreateWithFlags(&evFork, cudaEventDisableTiming) != cudaSuccess ||
                cudaEventCreateWithFlags(&evJoin, cudaEventDisableTiming) != cudaSuccess) {
                s2 = nullptr;
            }
        }
    }

    const int CVT_TOT = W4 + WA4;
    if (s2) {
        cudaEventRecord(evFork, 0);
        cudaStreamWaitEvent(s2, evFork, 0);
        bucket_init_kernel<<<NN / 256, 256, 0, s2>>>();
        bucket_scatter_kernel<<<EE / 4 / 256, 256, 0, s2>>>(ei);
        cudaEventRecord(evJoin, s2);

        cvt_w_kernel<<<(CVT_TOT + 255) / 256, 256>>>(W_gat, w_a);
        hgemm1_kernel<<<dim3(2, NN / 64), 256>>>(x, pwh, phh, att_src, att_dst);

        cudaStreamWaitEvent(0, evJoin, 0);
    } else {
        cvt_w_kernel<<<(CVT_TOT + 255) / 256, 256>>>(W_gat, w_a);
        hgemm1_kernel<<<dim3(2, NN / 64), 256>>>(x, pwh, phh, att_src, att_dst);
        bucket_init_kernel<<<NN / 256, 256>>>();
        bucket_scatter_kernel<<<EE / 4 / 256, 256>>>(ei);
    }

    // segment softmax + aggregation + bias + relu -> fp16
    gat_agg_kernel<<<NN, 64>>>(bias_gat);

    // layer_a: HMMA gemm + bias + LN + ReLU
    hgemm_ln_kernel<<<NN / 64, 256>>>(pgath, pw1h, b_a, g_a, be_a, pl1);

    // fused MLP tail: layer2 + LN + layer3 + LN + final projection
    fused_tail_kernel<<<NN / 64, 256>>>(pl1, w1, b1, g1, be1,
                                        w2, b2, g2, be2, w3, b3, pz);

    // pairwise distance matrix
    cdist_kernel<<<dim3(NN / CD_J, NN / CD_I), 256>>>(out);
}

// round 14
// speedup vs baseline: 1.6207x; 1.0328x over previous
#include <cuda_runtime.h>
#include <cuda_fp16.h>
#include <math.h>

#define NN   8192
#define EE   524288
#define FIN  256
#define FTOT 256      // H * F_OUT
#define FOUT 128
#define CAP  256      // per-node bucket capacity (mean deg = 65, Poisson)
#define LN_EPS   1e-5f
#define NEG_SLOPE 0.2f

// ---------------- scratch (__device__ globals; no allocation allowed) ----------------
__device__ __align__(16) __half g_xh[NN * FIN];     // x in fp16
__device__ __align__(16) __half g_wh[FIN * FTOT];   // W_gat in fp16
__device__ __align__(16) __half g_w1h[256 * 128];   // w_a in fp16
__device__ __align__(16) __half g_hh[NN * FTOT];    // x @ W_gat, fp16
__device__ __align__(16) __half g_gath[NN * 256];   // GAT output (relu), fp16
__device__ __align__(16) float g_as[NN * 2];
__device__ __align__(16) float g_ad[NN * 2];
__device__ int   g_deg[NN];
__device__ int   g_srt[NN * CAP];
__device__ __align__(16) float g_l1[NN * 128];
__device__ __align__(16) float g_z[NN * 3];

// ---------------- packed fp32x2 FMA ----------------
__device__ __forceinline__ void ffma2(float2& c, float a, const float2& b) {
    float2 av = make_float2(a, a);
    unsigned long long ua = *reinterpret_cast<unsigned long long*>(&av);
    unsigned long long ub = *reinterpret_cast<const unsigned long long*>(&b);
    unsigned long long uc = *reinterpret_cast<unsigned long long*>(&c);
    asm("fma.rn.f32x2 %0, %1, %2, %0;" : "+l"(uc) : "l"(ua), "l"(ub));
    c = *reinterpret_cast<float2*>(&uc);
}

__device__ __forceinline__ void cp_async16(unsigned smem_dst, const void* gmem_src) {
    asm volatile("cp.async.cg.shared.global [%0], [%1], 16;" :: "r"(smem_dst), "l"(gmem_src));
}

// ---------------- fused fp32 -> fp16 conversion of x, W_gat, w_a (2 chunks/thread) ----------------
#define X4  (NN * FIN / 4)          // 131072
#define W4  (FIN * FTOT / 4)        // 16384
#define WA4 (256 * 128 / 4)         // 8192
#define CVT_TOT (X4 + W4 + WA4)     // 155648
__global__ void cvt_all_kernel(const float* __restrict__ x,
                               const float* __restrict__ W,
                               const float* __restrict__ wa) {
    int base = blockIdx.x * blockDim.x + threadIdx.x;
#pragma unroll
    for (int l = 0; l < 2; l++) {
        int i = base + l * (CVT_TOT / 2);
        const float* src; __half* dst; int j;
        if (i < X4)            { src = x;  dst = g_xh;  j = i; }
        else if (i < X4 + W4)  { src = W;  dst = g_wh;  j = i - X4; }
        else if (i < CVT_TOT)  { src = wa; dst = g_w1h; j = i - X4 - W4; }
        else continue;
        float4 v = ((const float4*)src)[j];
        __half2 h0 = __floats2half2_rn(v.x, v.y);
        __half2 h1 = __floats2half2_rn(v.z, v.w);
        uint2 u;
        u.x = *(unsigned*)&h0;
        u.y = *(unsigned*)&h1;
        ((uint2*)dst)[j] = u;
    }
}

#define A_LDS 40   // 32 + 8 pad halfs (80B rows, 16B-aligned)
#define B_LDS 136  // 128 + 8 pad halfs (272B rows)
#define STG_A (64 * A_LDS)   // halfs per A stage
#define STG_B (32 * B_LDS)   // halfs per B stage

// ---------------- gemm1: fp16 HMMA, 64x128 tile, BK=32, 3-stage cp.async pipeline
//                  (ONE barrier per K-tile), fused attention dots from fp16 staging ----------------
__global__ __launch_bounds__(256) void hgemm1_kernel(
    const __half* __restrict__ Ah,   // x fp16 [NN][256]
    const __half* __restrict__ Bh,   // W_gat fp16 [256][256]
    __half* __restrict__ C,          // h fp16 [NN][256]
    const float* __restrict__ att_src,
    const float* __restrict__ att_dst) {
    __shared__ __align__(16) char smem_raw[3 * (STG_A + STG_B) * 2];
    __half* As_base = (__half*)smem_raw;                       // stage s at As_base + s*(STG_A+STG_B)
    __half (*Cs)[B_LDS] = (__half(*)[B_LDS])smem_raw;          // epilogue overlay [64][136]

    const int tid  = threadIdx.x;
    const int warp = tid >> 5;
    const int lane = tid & 31;
    const int brow = blockIdx.y * 64;
    const int bcol = blockIdx.x * 128;   // head = blockIdx.x
    const int mw = (warp & 3) * 16;
    const int nw = (warp >> 2) * 64;

    float c[8][4];
#pragma unroll
    for (int nj = 0; nj < 8; nj++)
#pragma unroll
        for (int q = 0; q < 4; q++) c[nj][q] = 0.f;

    unsigned aAddr[3], bAddr[3][4];
#pragma unroll
    for (int st = 0; st < 3; st++) {
        __half* Abuf = As_base + st * (STG_A + STG_B);
        __half* Bbuf = Abuf + STG_A;
        aAddr[st] = (unsigned)__cvta_generic_to_shared(
            Abuf + (mw + (lane & 15)) * A_LDS + (lane >> 4) * 8);
#pragma unroll
        for (int j = 0; j < 4; j++)
            bAddr[st][j] = (unsigned)__cvta_generic_to_shared(
                Bbuf + (lane & 15) * B_LDS + nw + j * 16 + (lane >> 4) * 8);
    }

    const int arA = tid >> 2, acA = (tid & 3) * 8;   // A: 1 chunk/thread
    const int brB = tid >> 4, bcB = (tid & 15) * 8;  // B: 2 chunks/thread

    auto stage = [&](int kt, int st) {
        __half* Abuf = As_base + st * (STG_A + STG_B);
        __half* Bbuf = Abuf + STG_A;
        int k0 = kt * 32;
        cp_async16((unsigned)__cvta_generic_to_shared(Abuf + arA * A_LDS + acA),
                   Ah + (size_t)(brow + arA) * FIN + k0 + acA);
#pragma unroll
        for (int l = 0; l < 2; l++) {
            int r = brB + l * 16;
            cp_async16((unsigned)__cvta_generic_to_shared(Bbuf + r * B_LDS + bcB),
                       Bh + (size_t)(k0 + r) * FTOT + bcol + bcB);
        }
    };

    stage(0, 0);
    asm volatile("cp.async.commit_group;");
    stage(1, 1);
    asm volatile("cp.async.commit_group;");

#pragma unroll
    for (int it = 0; it < 8; it++) {
        const int cur = it % 3;
        if (it < 7) asm volatile("cp.async.wait_group 1;");
        else        asm volatile("cp.async.wait_group 0;");
        __syncthreads();                 // data of tile `it` visible; consumers of it-1 done
        if (it + 2 < 8) {
            stage(it + 2, (it + 2) % 3); // buffer consumed at it-1; barrier passed since
            asm volatile("cp.async.commit_group;");
        }
#pragma unroll
        for (int ks = 0; ks < 2; ks++) {
            unsigned a[4], b[4][4];
            asm volatile("ldmatrix.sync.aligned.m8n8.x4.shared.b16 {%0,%1,%2,%3}, [%4];"
                         : "=r"(a[0]), "=r"(a[1]), "=r"(a[2]), "=r"(a[3])
                         : "r"(aAddr[cur] + ks * 32));
#pragma unroll
            for (int j = 0; j < 4; j++)
                asm volatile("ldmatrix.sync.aligned.m8n8.x4.trans.shared.b16 {%0,%1,%2,%3}, [%4];"
                             : "=r"(b[j][0]), "=r"(b[j][1]), "=r"(b[j][2]), "=r"(b[j][3])
                             : "r"(bAddr[cur][j] + ks * 16 * B_LDS * 2));
#pragma unroll
            for (int nj = 0; nj < 8; nj++) {
                const unsigned b0 = b[nj >> 1][(nj & 1) * 2];
                const unsigned b1 = b[nj >> 1][(nj & 1) * 2 + 1];
                asm volatile(
                    "mma.sync.aligned.m16n8k16.row.col.f32.f16.f16.f32 "
                    "{%0,%1,%2,%3}, {%4,%5,%6,%7}, {%8,%9}, {%0,%1,%2,%3};"
                    : "+f"(c[nj][0]), "+f"(c[nj][1]), "+f"(c[nj][2]), "+f"(c[nj][3])
                    : "r"(a[0]), "r"(a[1]), "r"(a[2]), "r"(a[3]), "r"(b0), "r"(b1));
            }
        }
    }
    __syncthreads();   // all warps done with stage buffers before Cs overlay

    // epilogue: stage fp16 into Cs overlay
    const int g  = lane >> 2;
    const int tg = lane & 3;
#pragma unroll
    for (int nj = 0; nj < 8; nj++) {
        int r0 = mw + g;
        int cc = nw + nj * 8 + tg * 2;
        *(__half2*)&Cs[r0][cc]     = __floats2half2_rn(c[nj][0], c[nj][1]);
        *(__half2*)&Cs[r0 + 8][cc] = __floats2half2_rn(c[nj][2], c[nj][3]);
    }
    __syncthreads();

#pragma unroll
    for (int l = 0; l < 4; l++) {
        int idx = tid + l * 256;
        int r = idx >> 4, c8 = (idx & 15) * 8;
        *(uint4*)(C + (size_t)(brow + r) * FTOT + bcol + c8) = *(uint4*)&Cs[r][c8];
    }

    // fused attention dots (this block's 128 cols == one head)
    {
        const int head = blockIdx.x;
        float4 s4 = ((const float4*)att_src)[head * 32 + lane];
        float4 d4 = ((const float4*)att_dst)[head * 32 + lane];
#pragma unroll
        for (int t = 0; t < 8; t++) {
            int rr = warp * 8 + t;
            uint2 hv = *(const uint2*)&Cs[rr][lane * 4];
            float2 h01 = __half22float2(*(__half2*)&hv.x);
            float2 h23 = __half22float2(*(__half2*)&hv.y);
            float ds = h01.x * s4.x + h01.y * s4.y + h23.x * s4.z + h23.y * s4.w;
            float dd = h01.x * d4.x + h01.y * d4.y + h23.x * d4.z + h23.y * d4.w;
#pragma unroll
            for (int o = 16; o > 0; o >>= 1) {
                ds += __shfl_xor_sync(0xffffffffu, ds, o);
                dd += __shfl_xor_sync(0xffffffffu, dd, o);
            }
            if (lane == 0) {
                int row = brow + rr;
                g_as[row * 2 + head] = ds;
                g_ad[row * 2 + head] = dd;
            }
        }
    }
}

// ---------------- layer_a: fp16 HMMA (64x128), 3-stage pipeline + bias + LN + ReLU ----------------
__global__ __launch_bounds__(256) void hgemm_ln_kernel(
    const __half* __restrict__ Ah,   // g_gath [NN][256]
    const __half* __restrict__ Bh,   // w_a fp16 [256][128]
    const float* __restrict__ bias, const float* __restrict__ gamma,
    const float* __restrict__ beta, float* __restrict__ C) {  // g_l1 [NN][128]
    // pipeline 41472B vs fp32 Cs overlay 33792B -> size to pipeline
    __shared__ __align__(16) char smem_raw[3 * (STG_A + STG_B) * 2];
    __half* As_base = (__half*)smem_raw;
    float (*Cs)[132] = (float(*)[132])smem_raw;

    const int tid  = threadIdx.x;
    const int warp = tid >> 5;
    const int lane = tid & 31;
    const int brow = blockIdx.x * 64;
    const int mw = (warp & 3) * 16;
    const int nw = (warp >> 2) * 64;

    float c[8][4];
#pragma unroll
    for (int nj = 0; nj < 8; nj++)
#pragma unroll
        for (int q = 0; q < 4; q++) c[nj][q] = 0.f;

    unsigned aAddr[3], bAddr[3][4];
#pragma unroll
    for (int st = 0; st < 3; st++) {
        __half* Abuf = As_base + st * (STG_A + STG_B);
        __half* Bbuf = Abuf + STG_A;
        aAddr[st] = (unsigned)__cvta_generic_to_shared(
            Abuf + (mw + (lane & 15)) * A_LDS + (lane >> 4) * 8);
#pragma unroll
        for (int j = 0; j < 4; j++)
            bAddr[st][j] = (unsigned)__cvta_generic_to_shared(
                Bbuf + (lane & 15) * B_LDS + nw + j * 16 + (lane >> 4) * 8);
    }

    const int arA = tid >> 2, acA = (tid & 3) * 8;
    const int brB = tid >> 4, bcB = (tid & 15) * 8;

    auto stage = [&](int kt, int st) {
        __half* Abuf = As_base + st * (STG_A + STG_B);
        __half* Bbuf = Abuf + STG_A;
        int k0 = kt * 32;
        cp_async16((unsigned)__cvta_generic_to_shared(Abuf + arA * A_LDS + acA),
                   Ah + (size_t)(brow + arA) * 256 + k0 + acA);
#pragma unroll
        for (int l = 0; l < 2; l++) {
            int r = brB + l * 16;
            cp_async16((unsigned)__cvta_generic_to_shared(Bbuf + r * B_LDS + bcB),
                       Bh + (size_t)(k0 + r) * 128 + bcB);
        }
    };

    stage(0, 0);
    asm volatile("cp.async.commit_group;");
    stage(1, 1);
    asm volatile("cp.async.commit_group;");

#pragma unroll
    for (int it = 0; it < 8; it++) {
        const int cur = it % 3;
        if (it < 7) asm volatile("cp.async.wait_group 1;");
        else        asm volatile("cp.async.wait_group 0;");
        __syncthreads();
        if (it + 2 < 8) {
            stage(it + 2, (it + 2) % 3);
            asm volatile("cp.async.commit_group;");
        }
#pragma unroll
        for (int ks = 0; ks < 2; ks++) {
            unsigned a[4], b[4][4];
            asm volatile("ldmatrix.sync.aligned.m8n8.x4.shared.b16 {%0,%1,%2,%3}, [%4];"
                         : "=r"(a[0]), "=r"(a[1]), "=r"(a[2]), "=r"(a[3])
                         : "r"(aAddr[cur] + ks * 32));
#pragma unroll
            for (int j = 0; j < 4; j++)
                asm volatile("ldmatrix.sync.aligned.m8n8.x4.trans.shared.b16 {%0,%1,%2,%3}, [%4];"
                             : "=r"(b[j][0]), "=r"(b[j][1]), "=r"(b[j][2]), "=r"(b[j][3])
                             : "r"(bAddr[cur][j] + ks * 16 * B_LDS * 2));
#pragma unroll
            for (int nj = 0; nj < 8; nj++) {
                const unsigned b0 = b[nj >> 1][(nj & 1) * 2];
                const unsigned b1 = b[nj >> 1][(nj & 1) * 2 + 1];
                asm volatile(
                    "mma.sync.aligned.m16n8k16.row.col.f32.f16.f16.f32 "
                    "{%0,%1,%2,%3}, {%4,%5,%6,%7}, {%8,%9}, {%0,%1,%2,%3};"
                    : "+f"(c[nj][0]), "+f"(c[nj][1]), "+f"(c[nj][2]), "+f"(c[nj][3])
                    : "r"(a[0]), "r"(a[1]), "r"(a[2]), "r"(a[3]), "r"(b0), "r"(b1));
            }
        }
    }
    __syncthreads();

    // stage fp32 accumulators into Cs overlay
    const int g  = lane >> 2;
    const int tg = lane & 3;
#pragma unroll
    for (int nj = 0; nj < 8; nj++) {
        int r0 = mw + g;
        int cc = nw + nj * 8 + tg * 2;
        Cs[r0][cc]     = c[nj][0]; Cs[r0][cc + 1]     = c[nj][1];
        Cs[r0 + 8][cc] = c[nj][2]; Cs[r0 + 8][cc + 1] = c[nj][3];
    }
    __syncthreads();

    const int c0 = lane * 4;
    float4 bi4 = *(const float4*)(bias + c0);
    float4 g4  = *(const float4*)(gamma + c0);
    float4 be4 = *(const float4*)(beta + c0);
    for (int rr = warp; rr < 64; rr += 8) {
        float v0 = Cs[rr][c0]     + bi4.x;
        float v1 = Cs[rr][c0 + 1] + bi4.y;
        float v2 = Cs[rr][c0 + 2] + bi4.z;
        float v3 = Cs[rr][c0 + 3] + bi4.w;
        float s = v0 + v1 + v2 + v3;
#pragma unroll
        for (int o = 16; o > 0; o >>= 1) s += __shfl_xor_sync(0xffffffffu, s, o);
        float mu = s * (1.f / 128.f);
        float d0 = v0 - mu, d1 = v1 - mu, d2 = v2 - mu, d3 = v3 - mu;
        float sq = d0 * d0 + d1 * d1 + d2 * d2 + d3 * d3;
#pragma unroll
        for (int o = 16; o > 0; o >>= 1) sq += __shfl_xor_sync(0xffffffffu, sq, o);
        float inv = rsqrtf(sq * (1.f / 128.f) + LN_EPS);
        float4 y;
        y.x = fmaxf(d0 * inv * g4.x + be4.x, 0.f);
        y.y = fmaxf(d1 * inv * g4.y + be4.y, 0.f);
        y.z = fmaxf(d2 * inv * g4.z + be4.z, 0.f);
        y.w = fmaxf(d3 * inv * g4.w + be4.w, 0.f);
        *(float4*)(C + (size_t)(brow + rr) * 128 + c0) = y;
    }
}

// ---------------- fused tail: (128->64)+LN+ReLU, (64->32)+LN+ReLU, (32->3)+bias -> z ----------------
__global__ __launch_bounds__(256) void fused_tail_kernel(
    const float* __restrict__ A,     // g_l1 [NN][128]
    const float* __restrict__ w1, const float* __restrict__ b1,
    const float* __restrict__ g1, const float* __restrict__ be1,
    const float* __restrict__ w2, const float* __restrict__ b2,
    const float* __restrict__ g2, const float* __restrict__ be2,
    const float* __restrict__ w3, const float* __restrict__ b3,
    float* __restrict__ Z) {
    __shared__ float As[16][68];
    __shared__ float Ws[16][64];
    __shared__ float Ys[64][68];
    __shared__ float w2s[64][32];
    __shared__ float w3s[96];
    __shared__ float b3s[3];
    const int tid = threadIdx.x;
    const int tx  = tid & 15;
    const int ty  = tid >> 4;
    const int brow = blockIdx.x * 64;

    for (int i = tid; i < 64 * 32; i += 256) w2s[i >> 5][i & 31] = w2[i];
    if (tid < 96) w3s[tid] = w3[tid];
    if (tid < 3)  b3s[tid] = b3[tid];

    float2 acc2[4][2];
#pragma unroll
    for (int m = 0; m < 4; m++) { acc2[m][0] = make_float2(0.f, 0.f); acc2[m][1] = make_float2(0.f, 0.f); }

    for (int k0 = 0; k0 < 128; k0 += 16) {
        {
            int i = tid;
            int r = i >> 2, c4 = (i & 3) * 4;
            float4 v = *(const float4*)(A + (size_t)(brow + r) * 128 + k0 + c4);
            As[c4 + 0][r] = v.x; As[c4 + 1][r] = v.y;
            As[c4 + 2][r] = v.z; As[c4 + 3][r] = v.w;
        }
        {
            int i = tid;
            int r = i >> 4, c4 = (i & 15) * 4;
            *(float4*)&Ws[r][c4] = *(const float4*)(w1 + (size_t)(k0 + r) * 64 + c4);
        }
        __syncthreads();
#pragma unroll
        for (int k = 0; k < 16; k++) {
            float ar[4];
            *(float4*)&ar[0] = *(float4*)&As[k][ty * 4];
            float4 b4 = *(float4*)&Ws[k][tx * 4];
            float2 br0 = make_float2(b4.x, b4.y);
            float2 br1 = make_float2(b4.z, b4.w);
#pragma unroll
            for (int m = 0; m < 4; m++) {
                ffma2(acc2[m][0], ar[m], br0);
                ffma2(acc2[m][1], ar[m], br1);
            }
        }
        __syncthreads();
    }

    {
        const int c0 = tx * 4;
        float4 bi4 = *(const float4*)(b1 + c0);
        float4 g4  = *(const float4*)(g1 + c0);
        float4 be4 = *(const float4*)(be1 + c0);
#pragma unroll
        for (int m = 0; m < 4; m++) {
            float v0 = acc2[m][0].x + bi4.x;
            float v1 = acc2[m][0].y + bi4.y;
            float v2 = acc2[m][1].x + bi4.z;
            float v3 = acc2[m][1].y + bi4.w;
            float s = v0 + v1 + v2 + v3;
#pragma unroll
            for (int o = 8; o > 0; o >>= 1) s += __shfl_xor_sync(0xffffffffu, s, o);
            float mu = s * (1.f / 64.f);
            float d0 = v0 - mu, d1 = v1 - mu, d2 = v2 - mu, d3 = v3 - mu;
            float sq = d0 * d0 + d1 * d1 + d2 * d2 + d3 * d3;
#pragma unroll
            for (int o = 8; o > 0; o >>= 1) sq += __shfl_xor_sync(0xffffffffu, sq, o);
            float inv = rsqrtf(sq * (1.f / 64.f) + LN_EPS);
            float4 y;
            y.x = fmaxf(d0 * inv * g4.x + be4.x, 0.f);
            y.y = fmaxf(d1 * inv * g4.y + be4.y, 0.f);
            y.z = fmaxf(d2 * inv * g4.z + be4.z, 0.f);
            y.w = fmaxf(d3 * inv * g4.w + be4.w, 0.f);
            *(float4*)&Ys[ty * 4 + m][c0] = y;
        }
    }
    __syncthreads();

    {
        const int tx3 = tid & 7;
        const int ty3 = tid >> 3;
        const int c3  = tx3 * 4;
        float4 bi = *(const float4*)(b2 + c3);
        float4 gg = *(const float4*)(g2 + c3);
        float4 bb = *(const float4*)(be2 + c3);
#pragma unroll
        for (int m = 0; m < 2; m++) {
            int r = ty3 * 2 + m;
            float2 a0 = make_float2(0.f, 0.f), a1 = make_float2(0.f, 0.f);
#pragma unroll 8
            for (int k = 0; k < 64; k++) {
                float yv = Ys[r][k];
                ffma2(a0, yv, *(const float2*)&w2s[k][c3]);
                ffma2(a1, yv, *(const float2*)&w2s[k][c3 + 2]);
            }
            float v0 = a0.x + bi.x, v1 = a0.y + bi.y;
            float v2 = a1.x + bi.z, v3 = a1.y + bi.w;
            float s = v0 + v1 + v2 + v3;
#pragma unroll
            for (int o = 4; o > 0; o >>= 1) s += __shfl_xor_sync(0xffffffffu, s, o);
            float mu = s * (1.f / 32.f);
            float d0 = v0 - mu, d1 = v1 - mu, d2 = v2 - mu, d3 = v3 - mu;
            float sq = d0 * d0 + d1 * d1 + d2 * d2 + d3 * d3;
#pragma unroll
            for (int o = 4; o > 0; o >>= 1) sq += __shfl_xor_sync(0xffffffffu, sq, o);
            float inv = rsqrtf(sq * (1.f / 32.f) + LN_EPS);
            float y0 = fmaxf(d0 * inv * gg.x + bb.x, 0.f);
            float y1 = fmaxf(d1 * inv * gg.y + bb.y, 0.f);
            float y2 = fmaxf(d2 * inv * gg.z + bb.z, 0.f);
            float y3 = fmaxf(d3 * inv * gg.w + bb.w, 0.f);
            float p0 = y0 * w3s[(c3 + 0) * 3 + 0] + y1 * w3s[(c3 + 1) * 3 + 0] +
                       y2 * w3s[(c3 + 2) * 3 + 0] + y3 * w3s[(c3 + 3) * 3 + 0];
            float p1 = y0 * w3s[(c3 + 0) * 3 + 1] + y1 * w3s[(c3 + 1) * 3 + 1] +
                       y2 * w3s[(c3 + 2) * 3 + 1] + y3 * w3s[(c3 + 3) * 3 + 1];
            float p2 = y0 * w3s[(c3 + 0) * 3 + 2] + y1 * w3s[(c3 + 1) * 3 + 2] +
                       y2 * w3s[(c3 + 2) * 3 + 2] + y3 * w3s[(c3 + 3) * 3 + 2];
#pragma unroll
            for (int o = 4; o > 0; o >>= 1) {
                p0 += __shfl_xor_sync(0xffffffffu, p0, o);
                p1 += __shfl_xor_sync(0xffffffffu, p1, o);
                p2 += __shfl_xor_sync(0xffffffffu, p2, o);
            }
            if (tx3 == 0) {
                int row = brow + r;
                Z[row * 3 + 0] = p0 + b3s[0];
                Z[row * 3 + 1] = p1 + b3s[1];
                Z[row * 3 + 2] = p2 + b3s[2];
            }
        }
    }
}

// ---------------- bucket CSR ----------------
__global__ void bucket_init_kernel() {
    int i = blockIdx.x * blockDim.x + threadIdx.x;
    if (i < NN) {
        g_deg[i] = 1;
        g_srt[i * CAP] = i;
    }
}

__global__ void bucket_scatter_kernel(const int* __restrict__ ei) {
    int id = blockIdx.x * blockDim.x + threadIdx.x;
    if (id >= EE / 4) return;
    int4 s = *(const int4*)&ei[id * 4];
    int4 d = *(const int4*)&ei[EE + id * 4];
    int p;
    p = atomicAdd(&g_deg[d.x], 1); if (p < CAP) g_srt[d.x * CAP + p] = s.x;
    p = atomicAdd(&g_deg[d.y], 1); if (p < CAP) g_srt[d.y * CAP + p] = s.y;
    p = atomicAdd(&g_deg[d.z], 1); if (p < CAP) g_srt[d.z * CAP + p] = s.z;
    p = atomicAdd(&g_deg[d.w], 1); if (p < CAP) g_srt[d.w * CAP + p] = s.w;
}

// ---------------- GAT softmax + aggregation (fp16 h in, fp16 out) ----------------
__global__ __launch_bounds__(64) void gat_agg_kernel(const float* __restrict__ bias) {
    const int dst = blockIdx.x;
    const int tid = threadIdx.x;
    const int start = dst * CAP;
    const int deg   = min(g_deg[dst], CAP);
    const float ad0 = g_ad[dst * 2], ad1 = g_ad[dst * 2 + 1];

    __shared__ int   sh_s[CAP];
    __shared__ float sh_w0[CAP];
    __shared__ float sh_w1[CAP];
    __shared__ float rsum[4];

    float s0 = 0.f, s1 = 0.f;
    for (int i = tid; i < deg; i += 64) {
        int s = g_srt[start + i];
        float2 av = ((const float2*)g_as)[s];
        float e0 = av.x + ad0; e0 = e0 > 0.f ? e0 : NEG_SLOPE * e0;
        float e1 = av.y + ad1; e1 = e1 > 0.f ? e1 : NEG_SLOPE * e1;
        float w0 = __expf(e0);
        float w1 = __expf(e1);
        sh_s[i]  = s;
        sh_w0[i] = w0;
        sh_w1[i] = w1;
        s0 += w0; s1 += w1;
    }
    __syncthreads();

    const int c0 = 4 * tid;
    const float* shw = (tid >= 32) ? sh_w1 : sh_w0;
    float2 accA = make_float2(0.f, 0.f);
    float2 accB = make_float2(0.f, 0.f);
    const __half* hbase = &g_hh[c0];

#pragma unroll 8
    for (int i = 0; i < deg; i++) {
        float w = shw[i];
        uint2 v = *(const uint2*)(hbase + (size_t)sh_s[i] * FTOT);
        float2 f01 = __half22float2(*(__half2*)&v.x);
        float2 f23 = __half22float2(*(__half2*)&v.y);
        ffma2(accA, w, f01);
        ffma2(accB, w, f23);
    }

#pragma unroll
    for (int o = 16; o > 0; o >>= 1) {
        s0 += __shfl_xor_sync(0xffffffffu, s0, o);
        s1 += __shfl_xor_sync(0xffffffffu, s1, o);
    }
    if ((tid & 31) == 0) { rsum[(tid >> 5) * 2] = s0; rsum[(tid >> 5) * 2 + 1] = s1; }
    __syncthreads();
    float t0 = rsum[0] + rsum[2];
    float t1 = rsum[1] + rsum[3];
    float inv = (tid >= 32) ? (1.f / (t1 + 1e-16f)) : (1.f / (t0 + 1e-16f));

    float4 bi = *(const float4*)(bias + c0);
    float o0 = fmaxf(accA.x * inv + bi.x, 0.f);
    float o1 = fmaxf(accA.y * inv + bi.y, 0.f);
    float o2 = fmaxf(accB.x * inv + bi.z, 0.f);
    float o3 = fmaxf(accB.y * inv + bi.w, 0.f);
    __half2 h0 = __floats2half2_rn(o0, o1);
    __half2 h1 = __floats2half2_rn(o2, o3);
    uint2 u;
    u.x = *(unsigned*)&h0;
    u.y = *(unsigned*)&h1;
    *(uint2*)&g_gath[(size_t)dst * 256 + c0] = u;
}

// ---------------- pairwise distances, streaming stores, MUFU sqrt ----------------
#define CD_I 64
#define CD_J 1024
__global__ __launch_bounds__(256) void cdist_kernel(float* __restrict__ out) {
    __shared__ float zi[CD_I * 3];
    int ibase = blockIdx.y * CD_I;
    int jbase = blockIdx.x * CD_J;
    for (int t = threadIdx.x; t < CD_I * 3; t += 256) zi[t] = g_z[ibase * 3 + t];

    int j0 = jbase + threadIdx.x * 4;
    float4 p0 = *(const float4*)(g_z + (size_t)j0 * 3);
    float4 p1 = *(const float4*)(g_z + (size_t)j0 * 3 + 4);
    float4 p2 = *(const float4*)(g_z + (size_t)j0 * 3 + 8);
    float jx[4] = {p0.x, p0.w, p1.z, p2.y};
    float jy[4] = {p0.y, p1.x, p1.w, p2.z};
    float jz[4] = {p0.z, p1.y, p2.x, p2.w};
    __syncthreads();

#pragma unroll 4
    for (int ii = 0; ii < CD_I; ii++) {
        float zx = zi[ii * 3], zy = zi[ii * 3 + 1], zz = zi[ii * 3 + 2];
        float r[4];
#pragma unroll
        for (int t = 0; t < 4; t++) {
            float dx = zx - jx[t];
            float dy = zy - jy[t];
            float dz = zz - jz[t];
            float d2 = dx * dx + dy * dy + dz * dz;
            r[t] = d2 > 0.f ? d2 * rsqrtf(d2) : 0.f;
        }
        float* ptr = out + (size_t)(ibase + ii) * NN + j0;
        asm volatile("st.global.cs.v4.f32 [%0], {%1, %2, %3, %4};"
                     :: "l"(ptr), "f"(r[0]), "f"(r[1]), "f"(r[2]), "f"(r[3])
                     : "memory");
    }
}

// ---------------- host launcher ----------------
extern "C" void kernel_launch(void* const* d_in, const int* in_sizes, int n_in,
                              void* d_out, int out_size) {
    const float* x        = (const float*)d_in[0];
    const int*   ei       = (const int*)  d_in[1];
    const float* W_gat    = (const float*)d_in[2];
    const float* att_src  = (const float*)d_in[3];
    const float* att_dst  = (const float*)d_in[4];
    const float* bias_gat = (const float*)d_in[5];
    const float* w_a  = (const float*)d_in[6];
    const float* b_a  = (const float*)d_in[7];
    const float* g_a  = (const float*)d_in[8];
    const float* be_a = (const float*)d_in[9];
    const float* w1   = (const float*)d_in[10];
    const float* b1   = (const float*)d_in[11];
    const float* g1   = (const float*)d_in[12];
    const float* be1  = (const float*)d_in[13];
    const float* w2   = (const float*)d_in[14];
    const float* b2   = (const float*)d_in[15];
    const float* g2   = (const float*)d_in[16];
    const float* be2  = (const float*)d_in[17];
    const float* w3   = (const float*)d_in[18];
    const float* b3   = (const float*)d_in[19];
    float* out = (float*)d_out;

    void* p;
    cudaGetSymbolAddress(&p, g_xh);   __half* pxh  = (__half*)p;
    cudaGetSymbolAddress(&p, g_wh);   __half* pwh  = (__half*)p;
    cudaGetSymbolAddress(&p, g_w1h);  __half* pw1h = (__half*)p;
    cudaGetSymbolAddress(&p, g_hh);   __half* phh  = (__half*)p;
    cudaGetSymbolAddress(&p, g_gath); __half* pgath= (__half*)p;
    cudaGetSymbolAddress(&p, g_l1);   float* pl1   = (float*)p;
    cudaGetSymbolAddress(&p, g_z);    float* pz    = (float*)p;

    static cudaStream_t s2 = nullptr;
    static cudaEvent_t evFork = nullptr, evJoin = nullptr;
    static bool tried = false;
    if (!tried) {
        tried = true;
        if (cudaStreamCreateWithFlags(&s2, cudaStreamNonBlocking) != cudaSuccess) s2 = nullptr;
        if (s2) {
            if (cudaEventCreateWithFlags(&evFork, cudaEventDisableTiming) != cudaSuccess ||
                cudaEventCreateWithFlags(&evJoin, cudaEventDisableTiming) != cudaSuccess) {
                s2 = nullptr;
            }
        }
    }

    if (s2) {
        cudaEventRecord(evFork, 0);
        cudaStreamWaitEvent(s2, evFork, 0);
        bucket_init_kernel<<<NN / 256, 256, 0, s2>>>();
        bucket_scatter_kernel<<<EE / 4 / 256, 256, 0, s2>>>(ei);
        cudaEventRecord(evJoin, s2);

        cvt_all_kernel<<<(CVT_TOT / 2 + 255) / 256, 256>>>(x, W_gat, w_a);
        hgemm1_kernel<<<dim3(2, NN / 64), 256>>>(pxh, pwh, phh, att_src, att_dst);

        cudaStreamWaitEvent(0, evJoin, 0);
    } else {
        cvt_all_kernel<<<(CVT_TOT / 2 + 255) / 256, 256>>>(x, W_gat, w_a);
        hgemm1_kernel<<<dim3(2, NN / 64), 256>>>(pxh, pwh, phh, att_src, att_dst);
        bucket_init_kernel<<<NN / 256, 256>>>();
        bucket_scatter_kernel<<<EE / 4 / 256, 256>>>(ei);
    }

    // segment softmax + aggregation + bias + relu -> fp16
    gat_agg_kernel<<<NN, 64>>>(bias_gat);

    // layer_a: HMMA gemm + bias + LN + ReLU (3-stage pipeline)
    hgemm_ln_kernel<<<NN / 64, 256>>>(pgath, pw1h, b_a, g_a, be_a, pl1);

    // fused MLP tail: layer2 + LN + layer3 + LN + final projection
    fused_tail_kernel<<<NN / 64, 256>>>(pl1, w1, b1, g1, be1,
                                        w2, b2, g2, be2, w3, b3, pz);

    // pairwise distance matrix
    cdist_kernel<<<dim3(NN / CD_J, NN / CD_I), 256>>>(out);
}

// round 15
// speedup vs baseline: 1.6452x; 1.0151x over previous
#include <cuda_runtime.h>
#include <cuda_fp16.h>
#include <math.h>

#define NN   8192
#define EE   524288
#define FIN  256
#define FTOT 256      // H * F_OUT
#define FOUT 128
#define CAP  256      // per-node bucket capacity (mean deg = 65, Poisson)
#define LN_EPS   1e-5f
#define NEG_SLOPE 0.2f

// ---------------- scratch (__device__ globals; no allocation allowed) ----------------
__device__ __align__(16) __half g_xh[NN * FIN];     // x in fp16
__device__ __align__(16) __half g_wh[FIN * FTOT];   // W_gat in fp16
__device__ __align__(16) __half g_w1h[256 * 128];   // w_a in fp16
__device__ __align__(16) __half g_hh[NN * FTOT];    // x @ W_gat, fp16
__device__ __align__(16) __half g_gath[NN * 256];   // GAT output (relu), fp16
__device__ __align__(16) float g_as[NN * 2];
__device__ __align__(16) float g_ad[NN * 2];
__device__ int   g_deg[NN];
__device__ int   g_srt[NN * CAP];
__device__ __align__(16) float g_l1[NN * 128];
__device__ __align__(16) float g_z[NN * 3];

// ---------------- packed fp32x2 FMA ----------------
__device__ __forceinline__ void ffma2(float2& c, float a, const float2& b) {
    float2 av = make_float2(a, a);
    unsigned long long ua = *reinterpret_cast<unsigned long long*>(&av);
    unsigned long long ub = *reinterpret_cast<const unsigned long long*>(&b);
    unsigned long long uc = *reinterpret_cast<unsigned long long*>(&c);
    asm("fma.rn.f32x2 %0, %1, %2, %0;" : "+l"(uc) : "l"(ua), "l"(ub));
    c = *reinterpret_cast<float2*>(&uc);
}

__device__ __forceinline__ void cp_async16(unsigned smem_dst, const void* gmem_src) {
    asm volatile("cp.async.cg.shared.global [%0], [%1], 16;" :: "r"(smem_dst), "l"(gmem_src));
}

// ---------------- fused fp32 -> fp16 conversion of x, W_gat, w_a (2 chunks/thread) ----------------
#define X4  (NN * FIN / 4)          // 131072
#define W4  (FIN * FTOT / 4)        // 16384
#define WA4 (256 * 128 / 4)         // 8192
#define CVT_TOT (X4 + W4 + WA4)     // 155648
__global__ void cvt_all_kernel(const float* __restrict__ x,
                               const float* __restrict__ W,
                               const float* __restrict__ wa) {
    int base = blockIdx.x * blockDim.x + threadIdx.x;
#pragma unroll
    for (int l = 0; l < 2; l++) {
        int i = base + l * (CVT_TOT / 2);
        const float* src; __half* dst; int j;
        if (i < X4)            { src = x;  dst = g_xh;  j = i; }
        else if (i < X4 + W4)  { src = W;  dst = g_wh;  j = i - X4; }
        else if (i < CVT_TOT)  { src = wa; dst = g_w1h; j = i - X4 - W4; }
        else continue;
        float4 v = ((const float4*)src)[j];
        __half2 h0 = __floats2half2_rn(v.x, v.y);
        __half2 h1 = __floats2half2_rn(v.z, v.w);
        uint2 u;
        u.x = *(unsigned*)&h0;
        u.y = *(unsigned*)&h1;
        ((uint2*)dst)[j] = u;
    }
}

// BK=64 tiling constants
#define A2_LDS 72                    // 64 + 8 pad halfs (144B rows)
#define B_LDS  136                   // 128 + 8 pad halfs (272B rows)
#define STG2_A (64 * A2_LDS)         // 4608 halfs per A stage
#define STG2_B (64 * B_LDS)          // 8704 halfs per B stage
#define STG2   (STG2_A + STG2_B)     // 13312 halfs
#define SMEM_DYN (3 * STG2 * 2)      // 79872 bytes (3 stages)

// ---------------- gemm1: fp16 HMMA, 64x128 tile, BK=64, 3-stage pipeline,
//                  ONE barrier per K-tile, fused attention dots ----------------
__global__ __launch_bounds__(256) void hgemm1_kernel(
    const __half* __restrict__ Ah,   // x fp16 [NN][256]
    const __half* __restrict__ Bh,   // W_gat fp16 [256][256]
    __half* __restrict__ C,          // h fp16 [NN][256]
    const float* __restrict__ att_src,
    const float* __restrict__ att_dst) {
    extern __shared__ __align__(16) char smem_raw[];
    __half* As_base = (__half*)smem_raw;                 // stage s at As_base + s*STG2
    __half (*Cs)[B_LDS] = (__half(*)[B_LDS])smem_raw;    // epilogue overlay [64][136]

    const int tid  = threadIdx.x;
    const int warp = tid >> 5;
    const int lane = tid & 31;
    const int brow = blockIdx.y * 64;
    const int bcol = blockIdx.x * 128;   // head = blockIdx.x
    const int mw = (warp & 3) * 16;
    const int nw = (warp >> 2) * 64;

    float c[8][4];
#pragma unroll
    for (int nj = 0; nj < 8; nj++)
#pragma unroll
        for (int q = 0; q < 4; q++) c[nj][q] = 0.f;

    unsigned aAddr[3], bAddr[3][4];
#pragma unroll
    for (int st = 0; st < 3; st++) {
        __half* Abuf = As_base + st * STG2;
        __half* Bbuf = Abuf + STG2_A;
        aAddr[st] = (unsigned)__cvta_generic_to_shared(
            Abuf + (mw + (lane & 15)) * A2_LDS + (lane >> 4) * 8);
#pragma unroll
        for (int j = 0; j < 4; j++)
            bAddr[st][j] = (unsigned)__cvta_generic_to_shared(
                Bbuf + (lane & 15) * B_LDS + nw + j * 16 + (lane >> 4) * 8);
    }

    // A tile 64x64 halfs: 512 chunks -> 2/thread; B tile 64x128: 1024 chunks -> 4/thread
    auto stage = [&](int kt, int st) {
        __half* Abuf = As_base + st * STG2;
        __half* Bbuf = Abuf + STG2_A;
        int k0 = kt * 64;
#pragma unroll
        for (int l = 0; l < 2; l++) {
            int idx = tid + l * 256;
            int r = idx >> 3, cc = (idx & 7) * 8;
            cp_async16((unsigned)__cvta_generic_to_shared(Abuf + r * A2_LDS + cc),
                       Ah + (size_t)(brow + r) * FIN + k0 + cc);
        }
#pragma unroll
        for (int l = 0; l < 4; l++) {
            int idx = tid + l * 256;
            int r = idx >> 4, cc = (idx & 15) * 8;
            cp_async16((unsigned)__cvta_generic_to_shared(Bbuf + r * B_LDS + cc),
                       Bh + (size_t)(k0 + r) * FTOT + bcol + cc);
        }
    };

    stage(0, 0);
    asm volatile("cp.async.commit_group;");
    stage(1, 1);
    asm volatile("cp.async.commit_group;");

#pragma unroll
    for (int it = 0; it < 4; it++) {
        const int cur = it % 3;
        if (it < 3) asm volatile("cp.async.wait_group 1;");
        else        asm volatile("cp.async.wait_group 0;");
        __syncthreads();
        if (it + 2 < 4) {
            stage(it + 2, (it + 2) % 3);
            asm volatile("cp.async.commit_group;");
        }
#pragma unroll
        for (int ks = 0; ks < 4; ks++) {
            unsigned a[4], b[4][4];
            asm volatile("ldmatrix.sync.aligned.m8n8.x4.shared.b16 {%0,%1,%2,%3}, [%4];"
                         : "=r"(a[0]), "=r"(a[1]), "=r"(a[2]), "=r"(a[3])
                         : "r"(aAddr[cur] + ks * 32));
#pragma unroll
            for (int j = 0; j < 4; j++)
                asm volatile("ldmatrix.sync.aligned.m8n8.x4.trans.shared.b16 {%0,%1,%2,%3}, [%4];"
                             : "=r"(b[j][0]), "=r"(b[j][1]), "=r"(b[j][2]), "=r"(b[j][3])
                             : "r"(bAddr[cur][j] + ks * 16 * B_LDS * 2));
#pragma unroll
            for (int nj = 0; nj < 8; nj++) {
                const unsigned b0 = b[nj >> 1][(nj & 1) * 2];
                const unsigned b1 = b[nj >> 1][(nj & 1) * 2 + 1];
                asm volatile(
                    "mma.sync.aligned.m16n8k16.row.col.f32.f16.f16.f32 "
                    "{%0,%1,%2,%3}, {%4,%5,%6,%7}, {%8,%9}, {%0,%1,%2,%3};"
                    : "+f"(c[nj][0]), "+f"(c[nj][1]), "+f"(c[nj][2]), "+f"(c[nj][3])
                    : "r"(a[0]), "r"(a[1]), "r"(a[2]), "r"(a[3]), "r"(b0), "r"(b1));
            }
        }
    }
    __syncthreads();

    // epilogue: stage fp16 into Cs overlay
    const int g  = lane >> 2;
    const int tg = lane & 3;
#pragma unroll
    for (int nj = 0; nj < 8; nj++) {
        int r0 = mw + g;
        int cc = nw + nj * 8 + tg * 2;
        *(__half2*)&Cs[r0][cc]     = __floats2half2_rn(c[nj][0], c[nj][1]);
        *(__half2*)&Cs[r0 + 8][cc] = __floats2half2_rn(c[nj][2], c[nj][3]);
    }
    __syncthreads();

#pragma unroll
    for (int l = 0; l < 4; l++) {
        int idx = tid + l * 256;
        int r = idx >> 4, c8 = (idx & 15) * 8;
        *(uint4*)(C + (size_t)(brow + r) * FTOT + bcol + c8) = *(uint4*)&Cs[r][c8];
    }

    // fused attention dots (this block's 128 cols == one head)
    {
        const int head = blockIdx.x;
        float4 s4 = ((const float4*)att_src)[head * 32 + lane];
        float4 d4 = ((const float4*)att_dst)[head * 32 + lane];
#pragma unroll
        for (int t = 0; t < 8; t++) {
            int rr = warp * 8 + t;
            uint2 hv = *(const uint2*)&Cs[rr][lane * 4];
            float2 h01 = __half22float2(*(__half2*)&hv.x);
            float2 h23 = __half22float2(*(__half2*)&hv.y);
            float ds = h01.x * s4.x + h01.y * s4.y + h23.x * s4.z + h23.y * s4.w;
            float dd = h01.x * d4.x + h01.y * d4.y + h23.x * d4.z + h23.y * d4.w;
#pragma unroll
            for (int o = 16; o > 0; o >>= 1) {
                ds += __shfl_xor_sync(0xffffffffu, ds, o);
                dd += __shfl_xor_sync(0xffffffffu, dd, o);
            }
            if (lane == 0) {
                int row = brow + rr;
                g_as[row * 2 + head] = ds;
                g_ad[row * 2 + head] = dd;
            }
        }
    }
}

// ---------------- layer_a: fp16 HMMA (64x128), BK=64 3-stage pipeline + bias + LN + ReLU ----------------
__global__ __launch_bounds__(256) void hgemm_ln_kernel(
    const __half* __restrict__ Ah,   // g_gath [NN][256]
    const __half* __restrict__ Bh,   // w_a fp16 [256][128]
    const float* __restrict__ bias, const float* __restrict__ gamma,
    const float* __restrict__ beta, float* __restrict__ C) {  // g_l1 [NN][128]
    extern __shared__ __align__(16) char smem_raw[];
    __half* As_base = (__half*)smem_raw;
    float (*Cs)[132] = (float(*)[132])smem_raw;   // fp32 overlay 33792B < SMEM_DYN

    const int tid  = threadIdx.x;
    const int warp = tid >> 5;
    const int lane = tid & 31;
    const int brow = blockIdx.x * 64;
    const int mw = (warp & 3) * 16;
    const int nw = (warp >> 2) * 64;

    float c[8][4];
#pragma unroll
    for (int nj = 0; nj < 8; nj++)
#pragma unroll
        for (int q = 0; q < 4; q++) c[nj][q] = 0.f;

    unsigned aAddr[3], bAddr[3][4];
#pragma unroll
    for (int st = 0; st < 3; st++) {
        __half* Abuf = As_base + st * STG2;
        __half* Bbuf = Abuf + STG2_A;
        aAddr[st] = (unsigned)__cvta_generic_to_shared(
            Abuf + (mw + (lane & 15)) * A2_LDS + (lane >> 4) * 8);
#pragma unroll
        for (int j = 0; j < 4; j++)
            bAddr[st][j] = (unsigned)__cvta_generic_to_shared(
                Bbuf + (lane & 15) * B_LDS + nw + j * 16 + (lane >> 4) * 8);
    }

    auto stage = [&](int kt, int st) {
        __half* Abuf = As_base + st * STG2;
        __half* Bbuf = Abuf + STG2_A;
        int k0 = kt * 64;
#pragma unroll
        for (int l = 0; l < 2; l++) {
            int idx = tid + l * 256;
            int r = idx >> 3, cc = (idx & 7) * 8;
            cp_async16((unsigned)__cvta_generic_to_shared(Abuf + r * A2_LDS + cc),
                       Ah + (size_t)(brow + r) * 256 + k0 + cc);
        }
#pragma unroll
        for (int l = 0; l < 4; l++) {
            int idx = tid + l * 256;
            int r = idx >> 4, cc = (idx & 15) * 8;
            cp_async16((unsigned)__cvta_generic_to_shared(Bbuf + r * B_LDS + cc),
                       Bh + (size_t)(k0 + r) * 128 + cc);
        }
    };

    stage(0, 0);
    asm volatile("cp.async.commit_group;");
    stage(1, 1);
    asm volatile("cp.async.commit_group;");

#pragma unroll
    for (int it = 0; it < 4; it++) {
        const int cur = it % 3;
        if (it < 3) asm volatile("cp.async.wait_group 1;");
        else        asm volatile("cp.async.wait_group 0;");
        __syncthreads();
        if (it + 2 < 4) {
            stage(it + 2, (it + 2) % 3);
            asm volatile("cp.async.commit_group;");
        }
#pragma unroll
        for (int ks = 0; ks < 4; ks++) {
            unsigned a[4], b[4][4];
            asm volatile("ldmatrix.sync.aligned.m8n8.x4.shared.b16 {%0,%1,%2,%3}, [%4];"
                         : "=r"(a[0]), "=r"(a[1]), "=r"(a[2]), "=r"(a[3])
                         : "r"(aAddr[cur] + ks * 32));
#pragma unroll
            for (int j = 0; j < 4; j++)
                asm volatile("ldmatrix.sync.aligned.m8n8.x4.trans.shared.b16 {%0,%1,%2,%3}, [%4];"
                             : "=r"(b[j][0]), "=r"(b[j][1]), "=r"(b[j][2]), "=r"(b[j][3])
                             : "r"(bAddr[cur][j] + ks * 16 * B_LDS * 2));
#pragma unroll
            for (int nj = 0; nj < 8; nj++) {
                const unsigned b0 = b[nj >> 1][(nj & 1) * 2];
                const unsigned b1 = b[nj >> 1][(nj & 1) * 2 + 1];
                asm volatile(
                    "mma.sync.aligned.m16n8k16.row.col.f32.f16.f16.f32 "
                    "{%0,%1,%2,%3}, {%4,%5,%6,%7}, {%8,%9}, {%0,%1,%2,%3};"
                    : "+f"(c[nj][0]), "+f"(c[nj][1]), "+f"(c[nj][2]), "+f"(c[nj][3])
                    : "r"(a[0]), "r"(a[1]), "r"(a[2]), "r"(a[3]), "r"(b0), "r"(b1));
            }
        }
    }
    __syncthreads();

    // stage fp32 accumulators into Cs overlay
    const int g  = lane >> 2;
    const int tg = lane & 3;
#pragma unroll
    for (int nj = 0; nj < 8; nj++) {
        int r0 = mw + g;
        int cc = nw + nj * 8 + tg * 2;
        Cs[r0][cc]     = c[nj][0]; Cs[r0][cc + 1]     = c[nj][1];
        Cs[r0 + 8][cc] = c[nj][2]; Cs[r0 + 8][cc + 1] = c[nj][3];
    }
    __syncthreads();

    const int c0 = lane * 4;
    float4 bi4 = *(const float4*)(bias + c0);
    float4 g4  = *(const float4*)(gamma + c0);
    float4 be4 = *(const float4*)(beta + c0);
    for (int rr = warp; rr < 64; rr += 8) {
        float v0 = Cs[rr][c0]     + bi4.x;
        float v1 = Cs[rr][c0 + 1] + bi4.y;
        float v2 = Cs[rr][c0 + 2] + bi4.z;
        float v3 = Cs[rr][c0 + 3] + bi4.w;
        float s = v0 + v1 + v2 + v3;
#pragma unroll
        for (int o = 16; o > 0; o >>= 1) s += __shfl_xor_sync(0xffffffffu, s, o);
        float mu = s * (1.f / 128.f);
        float d0 = v0 - mu, d1 = v1 - mu, d2 = v2 - mu, d3 = v3 - mu;
        float sq = d0 * d0 + d1 * d1 + d2 * d2 + d3 * d3;
#pragma unroll
        for (int o = 16; o > 0; o >>= 1) sq += __shfl_xor_sync(0xffffffffu, sq, o);
        float inv = rsqrtf(sq * (1.f / 128.f) + LN_EPS);
        float4 y;
        y.x = fmaxf(d0 * inv * g4.x + be4.x, 0.f);
        y.y = fmaxf(d1 * inv * g4.y + be4.y, 0.f);
        y.z = fmaxf(d2 * inv * g4.z + be4.z, 0.f);
        y.w = fmaxf(d3 * inv * g4.w + be4.w, 0.f);
        *(float4*)(C + (size_t)(brow + rr) * 128 + c0) = y;
    }
}

// ---------------- fused tail: (128->64)+LN+ReLU, (64->32)+LN+ReLU, (32->3)+bias -> z ----------------
__global__ __launch_bounds__(256) void fused_tail_kernel(
    const float* __restrict__ A,     // g_l1 [NN][128]
    const float* __restrict__ w1, const float* __restrict__ b1,
    const float* __restrict__ g1, const float* __restrict__ be1,
    const float* __restrict__ w2, const float* __restrict__ b2,
    const float* __restrict__ g2, const float* __restrict__ be2,
    const float* __restrict__ w3, const float* __restrict__ b3,
    float* __restrict__ Z) {
    __shared__ float As[16][68];
    __shared__ float Ws[16][64];
    __shared__ float Ys[64][68];
    __shared__ float w2s[64][32];
    __shared__ float w3s[96];
    __shared__ float b3s[3];
    const int tid = threadIdx.x;
    const int tx  = tid & 15;
    const int ty  = tid >> 4;
    const int brow = blockIdx.x * 64;

    for (int i = tid; i < 64 * 32; i += 256) w2s[i >> 5][i & 31] = w2[i];
    if (tid < 96) w3s[tid] = w3[tid];
    if (tid < 3)  b3s[tid] = b3[tid];

    float2 acc2[4][2];
#pragma unroll
    for (int m = 0; m < 4; m++) { acc2[m][0] = make_float2(0.f, 0.f); acc2[m][1] = make_float2(0.f, 0.f); }

    for (int k0 = 0; k0 < 128; k0 += 16) {
        {
            int i = tid;
            int r = i >> 2, c4 = (i & 3) * 4;
            float4 v = *(const float4*)(A + (size_t)(brow + r) * 128 + k0 + c4);
            As[c4 + 0][r] = v.x; As[c4 + 1][r] = v.y;
            As[c4 + 2][r] = v.z; As[c4 + 3][r] = v.w;
        }
        {
            int i = tid;
            int r = i >> 4, c4 = (i & 15) * 4;
            *(float4*)&Ws[r][c4] = *(const float4*)(w1 + (size_t)(k0 + r) * 64 + c4);
        }
        __syncthreads();
#pragma unroll
        for (int k = 0; k < 16; k++) {
            float ar[4];
            *(float4*)&ar[0] = *(float4*)&As[k][ty * 4];
            float4 b4 = *(float4*)&Ws[k][tx * 4];
            float2 br0 = make_float2(b4.x, b4.y);
            float2 br1 = make_float2(b4.z, b4.w);
#pragma unroll
            for (int m = 0; m < 4; m++) {
                ffma2(acc2[m][0], ar[m], br0);
                ffma2(acc2[m][1], ar[m], br1);
            }
        }
        __syncthreads();
    }

    {
        const int c0 = tx * 4;
        float4 bi4 = *(const float4*)(b1 + c0);
        float4 g4  = *(const float4*)(g1 + c0);
        float4 be4 = *(const float4*)(be1 + c0);
#pragma unroll
        for (int m = 0; m < 4; m++) {
            float v0 = acc2[m][0].x + bi4.x;
            float v1 = acc2[m][0].y + bi4.y;
            float v2 = acc2[m][1].x + bi4.z;
            float v3 = acc2[m][1].y + bi4.w;
            float s = v0 + v1 + v2 + v3;
#pragma unroll
            for (int o = 8; o > 0; o >>= 1) s += __shfl_xor_sync(0xffffffffu, s, o);
            float mu = s * (1.f / 64.f);
            float d0 = v0 - mu, d1 = v1 - mu, d2 = v2 - mu, d3 = v3 - mu;
            float sq = d0 * d0 + d1 * d1 + d2 * d2 + d3 * d3;
#pragma unroll
            for (int o = 8; o > 0; o >>= 1) sq += __shfl_xor_sync(0xffffffffu, sq, o);
            float inv = rsqrtf(sq * (1.f / 64.f) + LN_EPS);
            float4 y;
            y.x = fmaxf(d0 * inv * g4.x + be4.x, 0.f);
            y.y = fmaxf(d1 * inv * g4.y + be4.y, 0.f);
            y.z = fmaxf(d2 * inv * g4.z + be4.z, 0.f);
            y.w = fmaxf(d3 * inv * g4.w + be4.w, 0.f);
            *(float4*)&Ys[ty * 4 + m][c0] = y;
        }
    }
    __syncthreads();

    {
        const int tx3 = tid & 7;
        const int ty3 = tid >> 3;
        const int c3  = tx3 * 4;
        float4 bi = *(const float4*)(b2 + c3);
        float4 gg = *(const float4*)(g2 + c3);
        float4 bb = *(const float4*)(be2 + c3);
#pragma unroll
        for (int m = 0; m < 2; m++) {
            int r = ty3 * 2 + m;
            float2 a0 = make_float2(0.f, 0.f), a1 = make_float2(0.f, 0.f);
#pragma unroll 8
            for (int k = 0; k < 64; k++) {
                float yv = Ys[r][k];
                ffma2(a0, yv, *(const float2*)&w2s[k][c3]);
                ffma2(a1, yv, *(const float2*)&w2s[k][c3 + 2]);
            }
            float v0 = a0.x + bi.x, v1 = a0.y + bi.y;
            float v2 = a1.x + bi.z, v3 = a1.y + bi.w;
            float s = v0 + v1 + v2 + v3;
#pragma unroll
            for (int o = 4; o > 0; o >>= 1) s += __shfl_xor_sync(0xffffffffu, s, o);
            float mu = s * (1.f / 32.f);
            float d0 = v0 - mu, d1 = v1 - mu, d2 = v2 - mu, d3 = v3 - mu;
            float sq = d0 * d0 + d1 * d1 + d2 * d2 + d3 * d3;
#pragma unroll
            for (int o = 4; o > 0; o >>= 1) sq += __shfl_xor_sync(0xffffffffu, sq, o);
            float inv = rsqrtf(sq * (1.f / 32.f) + LN_EPS);
            float y0 = fmaxf(d0 * inv * gg.x + bb.x, 0.f);
            float y1 = fmaxf(d1 * inv * gg.y + bb.y, 0.f);
            float y2 = fmaxf(d2 * inv * gg.z + bb.z, 0.f);
            float y3 = fmaxf(d3 * inv * gg.w + bb.w, 0.f);
            float p0 = y0 * w3s[(c3 + 0) * 3 + 0] + y1 * w3s[(c3 + 1) * 3 + 0] +
                       y2 * w3s[(c3 + 2) * 3 + 0] + y3 * w3s[(c3 + 3) * 3 + 0];
            float p1 = y0 * w3s[(c3 + 0) * 3 + 1] + y1 * w3s[(c3 + 1) * 3 + 1] +
                       y2 * w3s[(c3 + 2) * 3 + 1] + y3 * w3s[(c3 + 3) * 3 + 1];
            float p2 = y0 * w3s[(c3 + 0) * 3 + 2] + y1 * w3s[(c3 + 1) * 3 + 2] +
                       y2 * w3s[(c3 + 2) * 3 + 2] + y3 * w3s[(c3 + 3) * 3 + 2];
#pragma unroll
            for (int o = 4; o > 0; o >>= 1) {
                p0 += __shfl_xor_sync(0xffffffffu, p0, o);
                p1 += __shfl_xor_sync(0xffffffffu, p1, o);
                p2 += __shfl_xor_sync(0xffffffffu, p2, o);
            }
            if (tx3 == 0) {
                int row = brow + r;
                Z[row * 3 + 0] = p0 + b3s[0];
                Z[row * 3 + 1] = p1 + b3s[1];
                Z[row * 3 + 2] = p2 + b3s[2];
            }
        }
    }
}

// ---------------- bucket CSR ----------------
__global__ void bucket_init_kernel() {
    int i = blockIdx.x * blockDim.x + threadIdx.x;
    if (i < NN) {
        g_deg[i] = 1;
        g_srt[i * CAP] = i;
    }
}

__global__ void bucket_scatter_kernel(const int* __restrict__ ei) {
    int id = blockIdx.x * blockDim.x + threadIdx.x;
    if (id >= EE / 4) return;
    int4 s = *(const int4*)&ei[id * 4];
    int4 d = *(const int4*)&ei[EE + id * 4];
    int p;
    p = atomicAdd(&g_deg[d.x], 1); if (p < CAP) g_srt[d.x * CAP + p] = s.x;
    p = atomicAdd(&g_deg[d.y], 1); if (p < CAP) g_srt[d.y * CAP + p] = s.y;
    p = atomicAdd(&g_deg[d.z], 1); if (p < CAP) g_srt[d.z * CAP + p] = s.z;
    p = atomicAdd(&g_deg[d.w], 1); if (p < CAP) g_srt[d.w * CAP + p] = s.w;
}

// ---------------- GAT softmax + aggregation (fp16 h in, fp16 out) ----------------
__global__ __launch_bounds__(64) void gat_agg_kernel(const float* __restrict__ bias) {
    const int dst = blockIdx.x;
    const int tid = threadIdx.x;
    const int start = dst * CAP;
    const int deg   = min(g_deg[dst], CAP);
    const float ad0 = g_ad[dst * 2], ad1 = g_ad[dst * 2 + 1];

    __shared__ int   sh_s[CAP];
    __shared__ float sh_w0[CAP];
    __shared__ float sh_w1[CAP];
    __shared__ float rsum[4];

    float s0 = 0.f, s1 = 0.f;
    for (int i = tid; i < deg; i += 64) {
        int s = g_srt[start + i];
        float2 av = ((const float2*)g_as)[s];
        float e0 = av.x + ad0; e0 = e0 > 0.f ? e0 : NEG_SLOPE * e0;
        float e1 = av.y + ad1; e1 = e1 > 0.f ? e1 : NEG_SLOPE * e1;
        float w0 = __expf(e0);
        float w1 = __expf(e1);
        sh_s[i]  = s;
        sh_w0[i] = w0;
        sh_w1[i] = w1;
        s0 += w0; s1 += w1;
    }
    __syncthreads();

    const int c0 = 4 * tid;
    const float* shw = (tid >= 32) ? sh_w1 : sh_w0;
    float2 accA = make_float2(0.f, 0.f);
    float2 accB = make_float2(0.f, 0.f);
    const __half* hbase = &g_hh[c0];

#pragma unroll 8
    for (int i = 0; i < deg; i++) {
        float w = shw[i];
        uint2 v = *(const uint2*)(hbase + (size_t)sh_s[i] * FTOT);
        float2 f01 = __half22float2(*(__half2*)&v.x);
        float2 f23 = __half22float2(*(__half2*)&v.y);
        ffma2(accA, w, f01);
        ffma2(accB, w, f23);
    }

#pragma unroll
    for (int o = 16; o > 0; o >>= 1) {
        s0 += __shfl_xor_sync(0xffffffffu, s0, o);
        s1 += __shfl_xor_sync(0xffffffffu, s1, o);
    }
    if ((tid & 31) == 0) { rsum[(tid >> 5) * 2] = s0; rsum[(tid >> 5) * 2 + 1] = s1; }
    __syncthreads();
    float t0 = rsum[0] + rsum[2];
    float t1 = rsum[1] + rsum[3];
    float inv = (tid >= 32) ? (1.f / (t1 + 1e-16f)) : (1.f / (t0 + 1e-16f));

    float4 bi = *(const float4*)(bias + c0);
    float o0 = fmaxf(accA.x * inv + bi.x, 0.f);
    float o1 = fmaxf(accA.y * inv + bi.y, 0.f);
    float o2 = fmaxf(accB.x * inv + bi.z, 0.f);
    float o3 = fmaxf(accB.y * inv + bi.w, 0.f);
    __half2 h0 = __floats2half2_rn(o0, o1);
    __half2 h1 = __floats2half2_rn(o2, o3);
    uint2 u;
    u.x = *(unsigned*)&h0;
    u.y = *(unsigned*)&h1;
    *(uint2*)&g_gath[(size_t)dst * 256 + c0] = u;
}

// ---------------- pairwise distances, streaming stores, MUFU sqrt ----------------
#define CD_I 64
#define CD_J 1024
__global__ __launch_bounds__(256) void cdist_kernel(float* __restrict__ out) {
    __shared__ float zi[CD_I * 3];
    int ibase = blockIdx.y * CD_I;
    int jbase = blockIdx.x * CD_J;
    for (int t = threadIdx.x; t < CD_I * 3; t += 256) zi[t] = g_z[ibase * 3 + t];

    int j0 = jbase + threadIdx.x * 4;
    float4 p0 = *(const float4*)(g_z + (size_t)j0 * 3);
    float4 p1 = *(const float4*)(g_z + (size_t)j0 * 3 + 4);
    float4 p2 = *(const float4*)(g_z + (size_t)j0 * 3 + 8);
    float jx[4] = {p0.x, p0.w, p1.z, p2.y};
    float jy[4] = {p0.y, p1.x, p1.w, p2.z};
    float jz[4] = {p0.z, p1.y, p2.x, p2.w};
    __syncthreads();

#pragma unroll 4
    for (int ii = 0; ii < CD_I; ii++) {
        float zx = zi[ii * 3], zy = zi[ii * 3 + 1], zz = zi[ii * 3 + 2];
        float r[4];
#pragma unroll
        for (int t = 0; t < 4; t++) {
            float dx = zx - jx[t];
            float dy = zy - jy[t];
            float dz = zz - jz[t];
            float d2 = dx * dx + dy * dy + dz * dz;
            r[t] = d2 > 0.f ? d2 * rsqrtf(d2) : 0.f;
        }
        float* ptr = out + (size_t)(ibase + ii) * NN + j0;
        asm volatile("st.global.cs.v4.f32 [%0], {%1, %2, %3, %4};"
                     :: "l"(ptr), "f"(r[0]), "f"(r[1]), "f"(r[2]), "f"(r[3])
                     : "memory");
    }
}

// ---------------- host launcher ----------------
extern "C" void kernel_launch(void* const* d_in, const int* in_sizes, int n_in,
                              void* d_out, int out_size) {
    const float* x        = (const float*)d_in[0];
    const int*   ei       = (const int*)  d_in[1];
    const float* W_gat    = (const float*)d_in[2];
    const float* att_src  = (const float*)d_in[3];
    const float* att_dst  = (const float*)d_in[4];
    const float* bias_gat = (const float*)d_in[5];
    const float* w_a  = (const float*)d_in[6];
    const float* b_a  = (const float*)d_in[7];
    const float* g_a  = (const float*)d_in[8];
    const float* be_a = (const float*)d_in[9];
    const float* w1   = (const float*)d_in[10];
    const float* b1   = (const float*)d_in[11];
    const float* g1   = (const float*)d_in[12];
    const float* be1  = (const float*)d_in[13];
    const float* w2   = (const float*)d_in[14];
    const float* b2   = (const float*)d_in[15];
    const float* g2   = (const float*)d_in[16];
    const float* be2  = (const float*)d_in[17];
    const float* w3   = (const float*)d_in[18];
    const float* b3   = (const float*)d_in[19];
    float* out = (float*)d_out;

    void* p;
    cudaGetSymbolAddress(&p, g_xh);   __half* pxh  = (__half*)p;
    cudaGetSymbolAddress(&p, g_wh);   __half* pwh  = (__half*)p;
    cudaGetSymbolAddress(&p, g_w1h);  __half* pw1h = (__half*)p;
    cudaGetSymbolAddress(&p, g_hh);   __half* phh  = (__half*)p;
    cudaGetSymbolAddress(&p, g_gath); __half* pgath= (__half*)p;
    cudaGetSymbolAddress(&p, g_l1);   float* pl1   = (float*)p;
    cudaGetSymbolAddress(&p, g_z);    float* pz    = (float*)p;

    static cudaStream_t s2 = nullptr;
    static cudaEvent_t evFork = nullptr, evJoin = nullptr;
    static bool tried = false;
    if (!tried) {
        tried = true;
        cudaFuncSetAttribute(hgemm1_kernel,
                             cudaFuncAttributeMaxDynamicSharedMemorySize, SMEM_DYN);
        cudaFuncSetAttribute(hgemm_ln_kernel,
                             cudaFuncAttributeMaxDynamicSharedMemorySize, SMEM_DYN);
        if (cudaStreamCreateWithFlags(&s2, cudaStreamNonBlocking) != cudaSuccess) s2 = nullptr;
        if (s2) {
            if (cudaEventCreateWithFlags(&evFork, cudaEventDisableTiming) != cudaSuccess ||
                cudaEventCreateWithFlags(&evJoin, cudaEventDisableTiming) != cudaSuccess) {
                s2 = nullptr;
            }
        }
    }

    if (s2) {
        cudaEventRecord(evFork, 0);
        cudaStreamWaitEvent(s2, evFork, 0);
        bucket_init_kernel<<<NN / 256, 256, 0, s2>>>();
        bucket_scatter_kernel<<<EE / 4 / 256, 256, 0, s2>>>(ei);
        cudaEventRecord(evJoin, s2);

        cvt_all_kernel<<<(CVT_TOT / 2 + 255) / 256, 256>>>(x, W_gat, w_a);
        hgemm1_kernel<<<dim3(2, NN / 64), 256, SMEM_DYN>>>(pxh, pwh, phh, att_src, att_dst);

        cudaStreamWaitEvent(0, evJoin, 0);
    } else {
        cvt_all_kernel<<<(CVT_TOT / 2 + 255) / 256, 256>>>(x, W_gat, w_a);
        hgemm1_kernel<<<dim3(2, NN / 64), 256, SMEM_DYN>>>(pxh, pwh, phh, att_src, att_dst);
        bucket_init_kernel<<<NN / 256, 256>>>();
        bucket_scatter_kernel<<<EE / 4 / 256, 256>>>(ei);
    }

    // segment softmax + aggregation + bias + relu -> fp16
    gat_agg_kernel<<<NN, 64>>>(bias_gat);

    // layer_a: HMMA gemm + bias + LN + ReLU (BK=64 pipeline)
    hgemm_ln_kernel<<<NN / 64, 256, SMEM_DYN>>>(pgath, pw1h, b_a, g_a, be_a, pl1);

    // fused MLP tail: layer2 + LN + layer3 + LN + final projection
    fused_tail_kernel<<<NN / 64, 256>>>(pl1, w1, b1, g1, be1,
                                        w2, b2, g2, be2, w3, b3, pz);

    // pairwise distance matrix
    cdist_kernel<<<dim3(NN / CD_J, NN / CD_I), 256>>>(out);
}